// round 1
// baseline (speedup 1.0000x reference)
#include <cuda_runtime.h>
#include <math.h>

#define B_   32
#define S_   512
#define H_   512
#define NH_  8
#define HD_  64
#define F_   2048
#define L_   6
#define OUT_ 80
#define FD_  256
#define M_   (B_*S_)   // 16384 tokens

// ---------------- scratch (static device globals; no allocation) ----------------
__device__ float g_h   [M_*H_];
__device__ float g_q   [M_*H_];
__device__ float g_k   [M_*H_];
__device__ float g_v   [M_*H_];
__device__ float g_attn[M_*H_];
__device__ float g_x1  [M_*H_];
__device__ float g_mid [M_*F_];
__device__ float g_w1t [L_*F_*3*H_];
__device__ float g_w2t [L_*H_*3*F_];
__device__ float g_dpw1t[FD_*3*H_];
__device__ float g_dpw2t[FD_*3*FD_];

#define FLAG_RELU  1
#define FLAG_MASK  2
#define FLAG_TRANS 4

// ---------------- generic GEMM / conv3 GEMM ----------------
// C[m,n] = sum_kk A_virt[m,kk] * W[n,kk]  (+bias, relu, mask, transposed store)
// A_virt: for nseg>1, row m=(b,s), kk=(seg,ci): reads A[(b, s+seg-pad), ci], 0 outside.
#define GTM 128
#define GTN 64
#define GTK 16

__global__ __launch_bounds__(256) void gemm_kernel(
    const float* __restrict__ A, const float* __restrict__ W,
    const float* __restrict__ bias, float* __restrict__ C,
    int N, int cinLog2, int nseg, int pad, int flags,
    const int* __restrict__ lengths)
{
    __shared__ __align__(16) float As[GTK][GTM+4];
    __shared__ __align__(16) float Ws[GTK][GTN+4];
    int t  = threadIdx.x;
    int tx = t & 15, ty = t >> 4;
    int m0 = blockIdx.y * GTM;
    int n0 = blockIdx.x * GTN;
    int cin  = 1 << cinLog2;
    int Kdim = nseg << cinLog2;

    float acc[8][4];
#pragma unroll
    for (int i = 0; i < 8; i++)
#pragma unroll
        for (int j = 0; j < 4; j++) acc[i][j] = 0.f;

    int kl   = t & 15;
    int lrow = t >> 4;

    for (int kk0 = 0; kk0 < Kdim; kk0 += GTK) {
        int kk  = kk0 + kl;
        int seg = kk >> cinLog2;
        int ci  = kk & (cin - 1);
#pragma unroll
        for (int i = 0; i < 8; i++) {
            int lm = lrow + i * 16;
            int m  = m0 + lm;
            float vv;
            if (nseg == 1) {
                vv = A[(size_t)m * cin + kk];
            } else {
                int s    = m & (S_ - 1);
                int srow = s + seg - pad;
                vv = (srow >= 0 && srow < S_) ? A[(size_t)(m + srow - s) * cin + ci] : 0.f;
            }
            As[kl][lm] = vv;
        }
#pragma unroll
        for (int i = 0; i < 4; i++) {
            int ln2 = lrow + i * 16;
            int n   = n0 + ln2;
            Ws[kl][ln2] = (n < N) ? W[(size_t)n * Kdim + kk] : 0.f;
        }
        __syncthreads();
#pragma unroll
        for (int k = 0; k < GTK; k++) {
            float4 b4 = *(const float4*)&Ws[k][tx * 4];
            float4 a0 = *(const float4*)&As[k][ty * 8];
            float4 a1 = *(const float4*)&As[k][ty * 8 + 4];
            float av[8] = {a0.x, a0.y, a0.z, a0.w, a1.x, a1.y, a1.z, a1.w};
            float bv[4] = {b4.x, b4.y, b4.z, b4.w};
#pragma unroll
            for (int i = 0; i < 8; i++)
#pragma unroll
                for (int j = 0; j < 4; j++)
                    acc[i][j] += av[i] * bv[j];
        }
        __syncthreads();
    }

#pragma unroll
    for (int i = 0; i < 8; i++) {
        int m = m0 + ty * 8 + i;
        int s = m & (S_ - 1);
        int b = m >> 9;
        float mv = 1.f;
        if (flags & FLAG_MASK) mv = (s >= lengths[b]) ? 1.f : 0.f;
#pragma unroll
        for (int j = 0; j < 4; j++) {
            int n = n0 + tx * 4 + j;
            if (n < N) {
                float c = acc[i][j] + bias[n];
                if (flags & FLAG_RELU) c = fmaxf(c, 0.f);
                c *= mv;
                if (flags & FLAG_TRANS)
                    C[((size_t)b * N + n) * S_ + s] = c;   // (B, N, S)
                else
                    C[(size_t)m * N + n] = c;              // (B*S, N)
            }
        }
    }
}

// ---------------- flash attention (fp32, HD=64, S=512) ----------------
// NOTE reference quirk: scores KEPT where kpos >= len, -1e9 where kpos < len.
__global__ __launch_bounds__(256) void attn_kernel(
    const float* __restrict__ q, const float* __restrict__ k,
    const float* __restrict__ v, float* __restrict__ o,
    const int* __restrict__ lengths)
{
    extern __shared__ float sm[];
    float* Qs = sm;              // [d][r]  64x68
    float* Ks = sm + 64 * 68;    // [d][c]
    float* Vs = sm + 2 * 64 * 68; // [kk][d]
    float* Ps = sm + 3 * 64 * 68; // [kk][r]

    int t  = threadIdx.x;
    int tx = t & 15, ty = t >> 4;
    int qt = blockIdx.x, hh = blockIdx.y, b = blockIdx.z;
    int len = lengths[b];
    const int rowstride = H_;  // NH*HD

    const float* qbase = q + (((size_t)b * S_ + qt * 64) * NH_ + hh) * HD_;
    int lr = t >> 4;
    int d4 = (t & 15) * 4;
#pragma unroll
    for (int i = 0; i < 4; i++) {
        int r = lr + i * 16;
        float4 qv = *(const float4*)(qbase + (size_t)r * rowstride + d4);
        Qs[(d4 + 0) * 68 + r] = qv.x;
        Qs[(d4 + 1) * 68 + r] = qv.y;
        Qs[(d4 + 2) * 68 + r] = qv.z;
        Qs[(d4 + 3) * 68 + r] = qv.w;
    }

    float acc[4][4];
    float mI[4], lI[4];
#pragma unroll
    for (int i = 0; i < 4; i++) {
        mI[i] = -INFINITY; lI[i] = 0.f;
#pragma unroll
        for (int j = 0; j < 4; j++) acc[i][j] = 0.f;
    }

    for (int kt0 = 0; kt0 < S_; kt0 += 64) {
        const float* kbase = k + (((size_t)b * S_ + kt0) * NH_ + hh) * HD_;
        const float* vbase = v + (((size_t)b * S_ + kt0) * NH_ + hh) * HD_;
#pragma unroll
        for (int i = 0; i < 4; i++) {
            int r = lr + i * 16;
            float4 kv = *(const float4*)(kbase + (size_t)r * rowstride + d4);
            Ks[(d4 + 0) * 68 + r] = kv.x;
            Ks[(d4 + 1) * 68 + r] = kv.y;
            Ks[(d4 + 2) * 68 + r] = kv.z;
            Ks[(d4 + 3) * 68 + r] = kv.w;
            float4 vv = *(const float4*)(vbase + (size_t)r * rowstride + d4);
            *(float4*)&Vs[r * 68 + d4] = vv;
        }
        __syncthreads();

        float sv[4][4];
#pragma unroll
        for (int i = 0; i < 4; i++)
#pragma unroll
            for (int j = 0; j < 4; j++) sv[i][j] = 0.f;

        for (int d = 0; d < 64; d++) {
            float4 aa = *(const float4*)&Qs[d * 68 + ty * 4];
            float4 bb = *(const float4*)&Ks[d * 68 + tx * 4];
            float av[4] = {aa.x, aa.y, aa.z, aa.w};
            float bv[4] = {bb.x, bb.y, bb.z, bb.w};
#pragma unroll
            for (int i = 0; i < 4; i++)
#pragma unroll
                for (int j = 0; j < 4; j++)
                    sv[i][j] += av[i] * bv[j];
        }
#pragma unroll
        for (int i = 0; i < 4; i++)
#pragma unroll
            for (int j = 0; j < 4; j++) {
                int kp = kt0 + tx * 4 + j;
                float x = sv[i][j] * 0.125f;
                sv[i][j] = (kp >= len) ? x : -1e9f;   // reference's inverted mask
            }

#pragma unroll
        for (int i = 0; i < 4; i++) {
            float rmax = fmaxf(fmaxf(sv[i][0], sv[i][1]), fmaxf(sv[i][2], sv[i][3]));
#pragma unroll
            for (int off = 1; off < 16; off <<= 1)
                rmax = fmaxf(rmax, __shfl_xor_sync(0xffffffffu, rmax, off));
            float mn    = fmaxf(mI[i], rmax);
            float alpha = __expf(mI[i] - mn);
            mI[i] = mn;
            float ssum = 0.f;
#pragma unroll
            for (int j = 0; j < 4; j++) {
                float p = __expf(sv[i][j] - mn);
                Ps[(tx * 4 + j) * 68 + ty * 4 + i] = p;
                ssum += p;
            }
#pragma unroll
            for (int off = 1; off < 16; off <<= 1)
                ssum += __shfl_xor_sync(0xffffffffu, ssum, off);
            lI[i] = lI[i] * alpha + ssum;
#pragma unroll
            for (int j = 0; j < 4; j++) acc[i][j] *= alpha;
        }
        __syncthreads();

        for (int kk = 0; kk < 64; kk++) {
            float4 pv = *(const float4*)&Ps[kk * 68 + ty * 4];
            float4 vv = *(const float4*)&Vs[kk * 68 + tx * 4];
            float pa[4] = {pv.x, pv.y, pv.z, pv.w};
            float va[4] = {vv.x, vv.y, vv.z, vv.w};
#pragma unroll
            for (int i = 0; i < 4; i++)
#pragma unroll
                for (int j = 0; j < 4; j++)
                    acc[i][j] += pa[i] * va[j];
        }
        __syncthreads();
    }

    float* obase = o + (((size_t)b * S_ + qt * 64) * NH_ + hh) * HD_;
#pragma unroll
    for (int i = 0; i < 4; i++) {
        int r = ty * 4 + i;
        float inv = 1.f / lI[i];
        float4 ov = make_float4(acc[i][0] * inv, acc[i][1] * inv,
                                acc[i][2] * inv, acc[i][3] * inv);
        *(float4*)(obase + (size_t)r * rowstride + tx * 4) = ov;
    }
}

// ---------------- LayerNorm (optionally fused residual add) ----------------
__global__ __launch_bounds__(128) void ln_kernel(
    const float* __restrict__ x, const float* __restrict__ res,
    const float* __restrict__ g, const float* __restrict__ be,
    float* __restrict__ out, int C)
{
    int m = blockIdx.x, t = threadIdx.x;
    int nv = C >> 2;
    float4 v = make_float4(0.f, 0.f, 0.f, 0.f);
    if (t < nv) {
        v = ((const float4*)(x + (size_t)m * C))[t];
        if (res) {
            float4 w = ((const float4*)(res + (size_t)m * C))[t];
            v.x += w.x; v.y += w.y; v.z += w.z; v.w += w.w;
        }
    }
    float sum = v.x + v.y + v.z + v.w;
    float sq  = v.x * v.x + v.y * v.y + v.z * v.z + v.w * v.w;
#pragma unroll
    for (int off = 16; off; off >>= 1) {
        sum += __shfl_xor_sync(0xffffffffu, sum, off);
        sq  += __shfl_xor_sync(0xffffffffu, sq,  off);
    }
    __shared__ float s1[4], s2[4];
    if ((t & 31) == 0) { s1[t >> 5] = sum; s2[t >> 5] = sq; }
    __syncthreads();
    sum = s1[0] + s1[1] + s1[2] + s1[3];
    sq  = s2[0] + s2[1] + s2[2] + s2[3];
    float mean = sum / C;
    float var  = sq / C - mean * mean;
    float inv  = rsqrtf(var + 1e-5f);
    if (t < nv) {
        float4 gv = ((const float4*)g)[t];
        float4 bv = ((const float4*)be)[t];
        float4 o4;
        o4.x = (v.x - mean) * inv * gv.x + bv.x;
        o4.y = (v.y - mean) * inv * gv.y + bv.y;
        o4.z = (v.z - mean) * inv * gv.z + bv.z;
        o4.w = (v.w - mean) * inv * gv.w + bv.w;
        ((float4*)(out + (size_t)m * C))[t] = o4;
    }
}

// ---------------- small helpers ----------------
__global__ __launch_bounds__(256) void embed_kernel(
    const int* __restrict__ x, const float* __restrict__ emb, float* __restrict__ h)
{
    int idx = blockIdx.x * blockDim.x + threadIdx.x;
    if (idx >= M_ * (H_ / 4)) return;
    int m = idx >> 7, c4 = idx & 127;
    int tok = x[m];
    float4 e = ((const float4*)(emb + (size_t)tok * H_))[c4];
    const float sc = 22.62741699796952f;  // sqrt(512)
    e.x *= sc; e.y *= sc; e.z *= sc; e.w *= sc;
    ((float4*)(h + (size_t)m * H_))[c4] = e;
}

__global__ __launch_bounds__(256) void rope_kernel(float* __restrict__ p)
{
    int idx = blockIdx.x * blockDim.x + threadIdx.x;
    if (idx >= M_ * NH_ * 32) return;
    int j   = idx & 31;
    int row = idx >> 5;                 // (b*S+s)*NH + h
    int s   = (row >> 3) & (S_ - 1);
    float theta = expf(-(float)j * 0.28782313662425574f);  // ln(10000)/32
    float ang = (float)s * theta;
    float sn, cs;
    sincosf(ang, &sn, &cs);
    float* pr = p + (size_t)row * HD_;
    float x0 = pr[j], x1 = pr[j + 32];
    pr[j]      = x0 * cs - x1 * sn;
    pr[j + 32] = x1 * cs + x0 * sn;
}

__global__ __launch_bounds__(256) void maskmul_kernel(
    const float* __restrict__ in, float* __restrict__ out,
    const int* __restrict__ lengths)
{
    int idx = blockIdx.x * blockDim.x + threadIdx.x;
    if (idx >= M_ * H_) return;
    int m = idx >> 9;
    int s = m & (S_ - 1), b = m >> 9;
    out[idx] = in[idx] * ((s >= lengths[b]) ? 1.f : 0.f);  // reference's inverted mask
}

__global__ __launch_bounds__(256) void transpose_w_kernel(
    const float* __restrict__ in, float* __restrict__ out,
    int CO, int CI, int KK)
{
    int idx = blockIdx.x * blockDim.x + threadIdx.x;
    if (idx >= CO * CI * KK) return;
    int kk = idx % KK;
    int rest = idx / KK;
    int ci = rest % CI;
    int co = rest / CI;
    out[((size_t)co * KK + kk) * CI + ci] = in[idx];
}

__global__ __launch_bounds__(256) void dp_final_kernel(
    const float* __restrict__ x, const float* __restrict__ w,
    const float* __restrict__ pb, const int* __restrict__ lengths,
    float* __restrict__ out)
{
    int warp = threadIdx.x >> 5, lane = threadIdx.x & 31;
    int m = blockIdx.x * 8 + warp;
    if (m >= M_) return;
    const float* xr = x + (size_t)m * FD_;
    float s = 0.f;
    for (int c = lane; c < FD_; c += 32) s += xr[c] * w[c];
#pragma unroll
    for (int off = 16; off; off >>= 1) s += __shfl_xor_sync(0xffffffffu, s, off);
    if (lane == 0) {
        int b = m >> 9, sp = m & (S_ - 1);
        float mv = (sp >= lengths[b]) ? 1.f : 0.f;
        float val = (s + pb[0]) * mv;
        out[(size_t)b * S_ + sp] = ceilf(expf(val));
    }
}

// ---------------- orchestration ----------------
extern "C" void kernel_launch(void* const* d_in, const int* in_sizes, int n_in,
                              void* d_out, int out_size)
{
    const int*   x      = (const int*)  d_in[0];
    const int*   xlen   = (const int*)  d_in[1];
    const float* emb    = (const float*)d_in[2];
    const float* Wq     = (const float*)d_in[3];
    const float* bq     = (const float*)d_in[4];
    const float* Wk     = (const float*)d_in[5];
    const float* bk     = (const float*)d_in[6];
    const float* Wv     = (const float*)d_in[7];
    const float* bv     = (const float*)d_in[8];
    const float* Wo     = (const float*)d_in[9];
    const float* bo     = (const float*)d_in[10];
    const float* c1w    = (const float*)d_in[11];
    const float* c1b    = (const float*)d_in[12];
    const float* c2w    = (const float*)d_in[13];
    const float* c2b    = (const float*)d_in[14];
    const float* ln1g   = (const float*)d_in[15];
    const float* ln1b   = (const float*)d_in[16];
    const float* ln2g   = (const float*)d_in[17];
    const float* ln2b   = (const float*)d_in[18];
    const float* projw  = (const float*)d_in[19];
    const float* projb  = (const float*)d_in[20];
    const float* dpc1w  = (const float*)d_in[21];
    const float* dpc1b  = (const float*)d_in[22];
    const float* dpln1g = (const float*)d_in[23];
    const float* dpln1b = (const float*)d_in[24];
    const float* dpc2w  = (const float*)d_in[25];
    const float* dpc2b  = (const float*)d_in[26];
    const float* dpln2g = (const float*)d_in[27];
    const float* dpln2b = (const float*)d_in[28];
    const float* dppw   = (const float*)d_in[29];
    const float* dppb   = (const float*)d_in[30];
    float* out = (float*)d_out;

    float *h, *qb, *kb, *vb, *ab, *x1, *mid, *w1t, *w2t, *dpw1t, *dpw2t;
    cudaGetSymbolAddress((void**)&h,    g_h);
    cudaGetSymbolAddress((void**)&qb,   g_q);
    cudaGetSymbolAddress((void**)&kb,   g_k);
    cudaGetSymbolAddress((void**)&vb,   g_v);
    cudaGetSymbolAddress((void**)&ab,   g_attn);
    cudaGetSymbolAddress((void**)&x1,   g_x1);
    cudaGetSymbolAddress((void**)&mid,  g_mid);
    cudaGetSymbolAddress((void**)&w1t,  g_w1t);
    cudaGetSymbolAddress((void**)&w2t,  g_w2t);
    cudaGetSymbolAddress((void**)&dpw1t, g_dpw1t);
    cudaGetSymbolAddress((void**)&dpw2t, g_dpw2t);

    cudaFuncSetAttribute((const void*)attn_kernel,
                         cudaFuncAttributeMaxDynamicSharedMemorySize, 4 * 64 * 68 * 4);

    // weight re-layout (CO,CI,K) -> (CO,K,CI)
    {
        int tot;
        tot = L_ * F_ * H_ * 3;
        transpose_w_kernel<<<(tot + 255) / 256, 256>>>(c1w, w1t, L_ * F_, H_, 3);
        tot = L_ * H_ * F_ * 3;
        transpose_w_kernel<<<(tot + 255) / 256, 256>>>(c2w, w2t, L_ * H_, F_, 3);
        tot = FD_ * H_ * 3;
        transpose_w_kernel<<<(tot + 255) / 256, 256>>>(dpc1w, dpw1t, FD_, H_, 3);
        tot = FD_ * FD_ * 3;
        transpose_w_kernel<<<(tot + 255) / 256, 256>>>(dpc2w, dpw2t, FD_, FD_, 3);
    }

    embed_kernel<<<M_ * (H_ / 4) / 256, 256>>>(x, emb, h);

    dim3 g8(H_ / GTN, M_ / GTM);        // (8,128)
    dim3 gc1(F_ / GTN, M_ / GTM);       // (32,128)
    dim3 gmu((OUT_ + GTN - 1) / GTN, M_ / GTM);
    dim3 gdp(FD_ / GTN, M_ / GTM);
    dim3 ga(S_ / 64, NH_, B_);

    for (int l = 0; l < L_; l++) {
        size_t wOff = (size_t)l * H_ * H_;
        gemm_kernel<<<g8, 256>>>(h, Wq + wOff, bq + l * H_, qb, H_, 9, 1, 0, 0, xlen);
        gemm_kernel<<<g8, 256>>>(h, Wk + wOff, bk + l * H_, kb, H_, 9, 1, 0, 0, xlen);
        gemm_kernel<<<g8, 256>>>(h, Wv + wOff, bv + l * H_, vb, H_, 9, 1, 0, 0, xlen);
        rope_kernel<<<M_ * NH_ * 32 / 256, 256>>>(qb);
        rope_kernel<<<M_ * NH_ * 32 / 256, 256>>>(kb);
        attn_kernel<<<ga, 256, 4 * 64 * 68 * 4>>>(qb, kb, vb, ab, xlen);
        gemm_kernel<<<g8, 256>>>(ab, Wo + wOff, bo + l * H_, qb, H_, 9, 1, 0, 0, xlen);
        ln_kernel<<<M_, 128>>>(qb, h, ln1g + l * H_, ln1b + l * H_, x1, H_);
        gemm_kernel<<<gc1, 256>>>(x1, w1t + (size_t)l * F_ * 3 * H_, c1b + l * F_,
                                  mid, F_, 9, 3, 1, FLAG_RELU, xlen);
        gemm_kernel<<<g8, 256>>>(mid, w2t + (size_t)l * H_ * 3 * F_, c2b + l * H_,
                                 vb, H_, 11, 3, 1, 0, xlen);
        ln_kernel<<<M_, 128>>>(vb, x1, ln2g + l * H_, ln2b + l * H_, h, H_);
    }

    // mu = pointwise conv (GEMM, transposed store to (B,OUT,S))
    gemm_kernel<<<gmu, 256>>>(h, projw, projb, out, OUT_, 9, 1, 0, FLAG_TRANS, xlen);

    // duration predictor
    maskmul_kernel<<<M_ * H_ / 256, 256>>>(h, qb, xlen);
    gemm_kernel<<<gdp, 256>>>(qb, dpw1t, dpc1b, kb, FD_, 9, 3, 1,
                              FLAG_RELU | FLAG_MASK, xlen);
    ln_kernel<<<M_, 128>>>(kb, nullptr, dpln1g, dpln1b, vb, FD_);
    gemm_kernel<<<gdp, 256>>>(vb, dpw2t, dpc2b, kb, FD_, 8, 3, 1,
                              FLAG_RELU | FLAG_MASK, xlen);
    ln_kernel<<<M_, 128>>>(kb, nullptr, dpln2g, dpln2b, vb, FD_);
    dp_final_kernel<<<M_ / 8, 256>>>(vb, dppw, dppb, xlen,
                                     out + ((size_t)out_size - (size_t)B_ * S_));
}

// round 3
// speedup vs baseline: 2.1164x; 2.1164x over previous
#include <cuda_runtime.h>
#include <cuda_bf16.h>
#include <math.h>
#include <stdint.h>

#define B_   32
#define S_   512
#define H_   512
#define NH_  8
#define HD_  64
#define F_   2048
#define L_   6
#define OUT_ 80
#define FD_  256
#define M_   (B_*S_)   // 16384 tokens

// ---------------- scratch (static device globals; no allocation) ----------------
__device__ float    g_h   [M_*H_];
__device__ float    g_q   [M_*H_];
__device__ float    g_k   [M_*H_];
__device__ float    g_v   [M_*H_];
__device__ float    g_attn[M_*H_];
__device__ float    g_x1  [M_*H_];
__device__ unsigned g_mid [M_*F_];          // packed hi/lo bf16
__device__ unsigned g_pa  [M_*H_];          // packed activations
__device__ unsigned g_pw1t[L_*F_*3*H_];
__device__ unsigned g_pw2t[L_*H_*3*F_];
__device__ unsigned g_pwq [L_*H_*H_];
__device__ unsigned g_pwk [L_*H_*H_];
__device__ unsigned g_pwv [L_*H_*H_];
__device__ unsigned g_pwo [L_*H_*H_];
__device__ unsigned g_pproj[OUT_*H_];
__device__ unsigned g_pdp1[FD_*3*H_];
__device__ unsigned g_pdp2[FD_*3*FD_];

#define FLAG_RELU    1
#define FLAG_MASK    2
#define FLAG_TRANS   4
#define FLAG_PACKOUT 8

// ---------------- helpers ----------------
__device__ __forceinline__ unsigned pack_hl(float x) {
    __nv_bfloat16 h = __float2bfloat16_rn(x);
    float r = x - __bfloat162float(h);
    __nv_bfloat16 l = __float2bfloat16_rn(r);
    return ((unsigned)__bfloat16_as_ushort(h) << 16) | (unsigned)__bfloat16_as_ushort(l);
}

__device__ __forceinline__ uint32_t smem_u32(const void* p) {
    uint32_t a;
    asm("{ .reg .u64 t; cvta.to.shared.u64 t, %1; cvt.u32.u64 %0, t; }" : "=r"(a) : "l"(p));
    return a;
}

__device__ __forceinline__ void ldsm4(uint32_t* r, uint32_t addr) {
    asm volatile("ldmatrix.sync.aligned.m8n8.x4.shared.b16 {%0,%1,%2,%3}, [%4];"
                 : "=r"(r[0]), "=r"(r[1]), "=r"(r[2]), "=r"(r[3]) : "r"(addr));
}

__device__ __forceinline__ void mma16816(float* c, const uint32_t* a,
                                         uint32_t b0, uint32_t b1) {
    asm volatile(
        "mma.sync.aligned.m16n8k16.row.col.f32.bf16.bf16.f32 "
        "{%0,%1,%2,%3}, {%4,%5,%6,%7}, {%8,%9}, {%0,%1,%2,%3};"
        : "+f"(c[0]), "+f"(c[1]), "+f"(c[2]), "+f"(c[3])
        : "r"(a[0]), "r"(a[1]), "r"(a[2]), "r"(a[3]), "r"(b0), "r"(b1));
}

// ---------------- split-bf16 HMMA GEMM ----------------
// C[m,n] = sum_kk A_virt[m,kk] * W[n,kk]  (+bias, relu, mask, trans/packout)
// Ap/Wp: fp32 packed per element as (bf16_hi<<16)|bf16_lo.
// Tile 128x128, K-chunk 64, 256 threads (8 warps, 2x4 grid, 64x32 warp tile).
#define PITCH 144          // bytes per smem row (72 halves)
#define PLANE (128*PITCH)  // 18432 B

__global__ __launch_bounds__(256) void hgemm_kernel(
    const unsigned* __restrict__ Ap, const unsigned* __restrict__ Wp,
    const float* __restrict__ bias, void* __restrict__ Cout,
    int N, int cinLog2, int nseg, int pad, int flags,
    const int* __restrict__ lengths)
{
    extern __shared__ __align__(16) char smem[];
    const int OFF_AHI = 0, OFF_ALO = PLANE, OFF_BHI = 2 * PLANE, OFF_BLO = 3 * PLANE;
    uint32_t sb = smem_u32(smem);

    int t = threadIdx.x, wid = t >> 5, lane = t & 31;
    int m0 = blockIdx.y * 128, n0 = blockIdx.x * 128;
    int cin = 1 << cinLog2;
    int Kdim = nseg << cinLog2;
    int nch = Kdim >> 6;
    int wm = (wid >> 2) * 64, wn = (wid & 3) * 32;

    float acc[4][4][4];
#pragma unroll
    for (int i = 0; i < 4; i++)
#pragma unroll
        for (int j = 0; j < 4; j++)
#pragma unroll
            for (int e = 0; e < 4; e++) acc[i][j][e] = 0.f;

    for (int kc = 0; kc < nch; kc++) {
        int kk0 = kc << 6;
        int seg = kk0 >> cinLog2;
        int ci0 = kk0 & (cin - 1);
        if (kc) __syncthreads();
        // ---- stage A: 128 rows x 32 uint2 (64 packed elems/row) ----
#pragma unroll
        for (int i = 0; i < 16; i++) {
            int idx = t + i * 256;
            int r = idx >> 5, p = idx & 31;
            int m = m0 + r;
            uint2 v = make_uint2(0u, 0u);
            if (nseg == 1) {
                v = ((const uint2*)(Ap + (size_t)m * cin + ci0))[p];
            } else {
                int s = m & (S_ - 1);
                int srow = s + seg - pad;
                if (srow >= 0 && srow < S_)
                    v = ((const uint2*)(Ap + (size_t)(m + srow - s) * cin + ci0))[p];
            }
            unsigned hi = __byte_perm(v.x, v.y, 0x7632);
            unsigned lo = __byte_perm(v.x, v.y, 0x5410);
            *(unsigned*)(smem + OFF_AHI + r * PITCH + p * 4) = hi;
            *(unsigned*)(smem + OFF_ALO + r * PITCH + p * 4) = lo;
        }
        // ---- stage B: rows n0..n0+127 of W[n][Kdim] ----
#pragma unroll
        for (int i = 0; i < 16; i++) {
            int idx = t + i * 256;
            int r = idx >> 5, p = idx & 31;
            int n = n0 + r;
            uint2 v = make_uint2(0u, 0u);
            if (n < N)
                v = ((const uint2*)(Wp + (size_t)n * Kdim + kk0))[p];
            unsigned hi = __byte_perm(v.x, v.y, 0x7632);
            unsigned lo = __byte_perm(v.x, v.y, 0x5410);
            *(unsigned*)(smem + OFF_BHI + r * PITCH + p * 4) = hi;
            *(unsigned*)(smem + OFF_BLO + r * PITCH + p * 4) = lo;
        }
        __syncthreads();

        // ---- compute: 4 k-steps of 16 ----
#pragma unroll
        for (int ks = 0; ks < 4; ks++) {
            uint32_t ah[4][4], al[4][4], bh[2][4], bl[2][4];
            int kb = ks * 32 + (lane >> 4) * 16;
            int rsel = lane & 15;
#pragma unroll
            for (int i = 0; i < 4; i++) {
                uint32_t rowa = sb + (wm + i * 16 + rsel) * PITCH + kb;
                ldsm4(ah[i], rowa + OFF_AHI);
                ldsm4(al[i], rowa + OFF_ALO);
            }
#pragma unroll
            for (int jj = 0; jj < 2; jj++) {
                uint32_t rowb = sb + (wn + jj * 16 + rsel) * PITCH + kb;
                ldsm4(bh[jj], rowb + OFF_BHI);
                ldsm4(bl[jj], rowb + OFF_BLO);
            }
#pragma unroll
            for (int i = 0; i < 4; i++)
#pragma unroll
                for (int j = 0; j < 4; j++) {
                    int jj = j >> 1, o = j & 1;
                    mma16816(acc[i][j], ah[i], bh[jj][o], bh[jj][o + 2]);
                    mma16816(acc[i][j], ah[i], bl[jj][o], bl[jj][o + 2]);
                    mma16816(acc[i][j], al[i], bh[jj][o], bh[jj][o + 2]);
                }
        }
    }

    // ---- epilogue ----
    int r0 = lane >> 2, c0 = (lane & 3) * 2;
#pragma unroll
    for (int i = 0; i < 4; i++) {
        int mA = m0 + wm + i * 16 + r0;
        int mB = mA + 8;
        int sA = mA & (S_ - 1), bA = mA >> 9;
        int sB = mB & (S_ - 1), bB = mB >> 9;
        float mvA = 1.f, mvB = 1.f;
        if (flags & FLAG_MASK) {
            mvA = (sA >= lengths[bA]) ? 1.f : 0.f;
            mvB = (sB >= lengths[bB]) ? 1.f : 0.f;
        }
#pragma unroll
        for (int j = 0; j < 4; j++) {
            int nb = n0 + wn + j * 8 + c0;
            if (nb + 1 < N || nb < N) {
                float b0 = (nb < N) ? __ldg(bias + nb) : 0.f;
                float b1 = (nb + 1 < N) ? __ldg(bias + nb + 1) : 0.f;
                float v00 = acc[i][j][0] + b0, v01 = acc[i][j][1] + b1;
                float v10 = acc[i][j][2] + b0, v11 = acc[i][j][3] + b1;
                if (flags & FLAG_RELU) {
                    v00 = fmaxf(v00, 0.f); v01 = fmaxf(v01, 0.f);
                    v10 = fmaxf(v10, 0.f); v11 = fmaxf(v11, 0.f);
                }
                v00 *= mvA; v01 *= mvA; v10 *= mvB; v11 *= mvB;
                if (flags & FLAG_TRANS) {
                    float* o = (float*)Cout;
                    if (nb < N)     { o[((size_t)bA * N + nb)     * S_ + sA] = v00;
                                      o[((size_t)bB * N + nb)     * S_ + sB] = v10; }
                    if (nb + 1 < N) { o[((size_t)bA * N + nb + 1) * S_ + sA] = v01;
                                      o[((size_t)bB * N + nb + 1) * S_ + sB] = v11; }
                } else if (flags & FLAG_PACKOUT) {
                    unsigned* o = (unsigned*)Cout;
                    *(uint2*)(o + (size_t)mA * N + nb) = make_uint2(pack_hl(v00), pack_hl(v01));
                    *(uint2*)(o + (size_t)mB * N + nb) = make_uint2(pack_hl(v10), pack_hl(v11));
                } else {
                    float* o = (float*)Cout;
                    if (nb + 1 < N) {
                        *(float2*)(o + (size_t)mA * N + nb) = make_float2(v00, v01);
                        *(float2*)(o + (size_t)mB * N + nb) = make_float2(v10, v11);
                    } else if (nb < N) {
                        o[(size_t)mA * N + nb] = v00;
                        o[(size_t)mB * N + nb] = v10;
                    }
                }
            }
        }
    }
}

// ---------------- flash attention (fp32, HD=64, S=512) ----------------
__global__ __launch_bounds__(256) void attn_kernel(
    const float* __restrict__ q, const float* __restrict__ k,
    const float* __restrict__ v, float* __restrict__ o,
    const int* __restrict__ lengths)
{
    extern __shared__ float sm[];
    float* Qs = sm;
    float* Ks = sm + 64 * 68;
    float* Vs = sm + 2 * 64 * 68;
    float* Ps = sm + 3 * 64 * 68;

    int t  = threadIdx.x;
    int tx = t & 15, ty = t >> 4;
    int qt = blockIdx.x, hh = blockIdx.y, b = blockIdx.z;
    int len = lengths[b];
    const int rowstride = H_;

    const float* qbase = q + (((size_t)b * S_ + qt * 64) * NH_ + hh) * HD_;
    int lr = t >> 4;
    int d4 = (t & 15) * 4;
#pragma unroll
    for (int i = 0; i < 4; i++) {
        int r = lr + i * 16;
        float4 qv = *(const float4*)(qbase + (size_t)r * rowstride + d4);
        Qs[(d4 + 0) * 68 + r] = qv.x;
        Qs[(d4 + 1) * 68 + r] = qv.y;
        Qs[(d4 + 2) * 68 + r] = qv.z;
        Qs[(d4 + 3) * 68 + r] = qv.w;
    }

    float acc[4][4];
    float mI[4], lI[4];
#pragma unroll
    for (int i = 0; i < 4; i++) {
        mI[i] = -INFINITY; lI[i] = 0.f;
#pragma unroll
        for (int j = 0; j < 4; j++) acc[i][j] = 0.f;
    }

    for (int kt0 = 0; kt0 < S_; kt0 += 64) {
        const float* kbase = k + (((size_t)b * S_ + kt0) * NH_ + hh) * HD_;
        const float* vbase = v + (((size_t)b * S_ + kt0) * NH_ + hh) * HD_;
#pragma unroll
        for (int i = 0; i < 4; i++) {
            int r = lr + i * 16;
            float4 kv = *(const float4*)(kbase + (size_t)r * rowstride + d4);
            Ks[(d4 + 0) * 68 + r] = kv.x;
            Ks[(d4 + 1) * 68 + r] = kv.y;
            Ks[(d4 + 2) * 68 + r] = kv.z;
            Ks[(d4 + 3) * 68 + r] = kv.w;
            float4 vv = *(const float4*)(vbase + (size_t)r * rowstride + d4);
            *(float4*)&Vs[r * 68 + d4] = vv;
        }
        __syncthreads();

        float sv[4][4];
#pragma unroll
        for (int i = 0; i < 4; i++)
#pragma unroll
            for (int j = 0; j < 4; j++) sv[i][j] = 0.f;

        for (int d = 0; d < 64; d++) {
            float4 aa = *(const float4*)&Qs[d * 68 + ty * 4];
            float4 bb = *(const float4*)&Ks[d * 68 + tx * 4];
            float av[4] = {aa.x, aa.y, aa.z, aa.w};
            float bv[4] = {bb.x, bb.y, bb.z, bb.w};
#pragma unroll
            for (int i = 0; i < 4; i++)
#pragma unroll
                for (int j = 0; j < 4; j++)
                    sv[i][j] += av[i] * bv[j];
        }
#pragma unroll
        for (int i = 0; i < 4; i++)
#pragma unroll
            for (int j = 0; j < 4; j++) {
                int kp = kt0 + tx * 4 + j;
                float x = sv[i][j] * 0.125f;
                sv[i][j] = (kp >= len) ? x : -1e9f;   // reference's inverted mask
            }

#pragma unroll
        for (int i = 0; i < 4; i++) {
            float rmax = fmaxf(fmaxf(sv[i][0], sv[i][1]), fmaxf(sv[i][2], sv[i][3]));
#pragma unroll
            for (int off = 1; off < 16; off <<= 1)
                rmax = fmaxf(rmax, __shfl_xor_sync(0xffffffffu, rmax, off));
            float mn    = fmaxf(mI[i], rmax);
            float alpha = __expf(mI[i] - mn);
            mI[i] = mn;
            float ssum = 0.f;
#pragma unroll
            for (int j = 0; j < 4; j++) {
                float p = __expf(sv[i][j] - mn);
                Ps[(tx * 4 + j) * 68 + ty * 4 + i] = p;
                ssum += p;
            }
#pragma unroll
            for (int off = 1; off < 16; off <<= 1)
                ssum += __shfl_xor_sync(0xffffffffu, ssum, off);
            lI[i] = lI[i] * alpha + ssum;
#pragma unroll
            for (int j = 0; j < 4; j++) acc[i][j] *= alpha;
        }
        __syncthreads();

        for (int kk = 0; kk < 64; kk++) {
            float4 pv = *(const float4*)&Ps[kk * 68 + ty * 4];
            float4 vv = *(const float4*)&Vs[kk * 68 + tx * 4];
            float pa[4] = {pv.x, pv.y, pv.z, pv.w};
            float va[4] = {vv.x, vv.y, vv.z, vv.w};
#pragma unroll
            for (int i = 0; i < 4; i++)
#pragma unroll
                for (int j = 0; j < 4; j++)
                    acc[i][j] += pa[i] * va[j];
        }
        __syncthreads();
    }

    float* obase = o + (((size_t)b * S_ + qt * 64) * NH_ + hh) * HD_;
#pragma unroll
    for (int i = 0; i < 4; i++) {
        int r = ty * 4 + i;
        float inv = 1.f / lI[i];
        float4 ov = make_float4(acc[i][0] * inv, acc[i][1] * inv,
                                acc[i][2] * inv, acc[i][3] * inv);
        *(float4*)(obase + (size_t)r * rowstride + tx * 4) = ov;
    }
}

// ---------------- LayerNorm (optionally fused residual add) ----------------
__global__ __launch_bounds__(128) void ln_kernel(
    const float* __restrict__ x, const float* __restrict__ res,
    const float* __restrict__ g, const float* __restrict__ be,
    float* __restrict__ out, int C)
{
    int m = blockIdx.x, t = threadIdx.x;
    int nv = C >> 2;
    float4 v = make_float4(0.f, 0.f, 0.f, 0.f);
    if (t < nv) {
        v = ((const float4*)(x + (size_t)m * C))[t];
        if (res) {
            float4 w = ((const float4*)(res + (size_t)m * C))[t];
            v.x += w.x; v.y += w.y; v.z += w.z; v.w += w.w;
        }
    }
    float sum = v.x + v.y + v.z + v.w;
    float sq  = v.x * v.x + v.y * v.y + v.z * v.z + v.w * v.w;
#pragma unroll
    for (int off = 16; off; off >>= 1) {
        sum += __shfl_xor_sync(0xffffffffu, sum, off);
        sq  += __shfl_xor_sync(0xffffffffu, sq,  off);
    }
    __shared__ float s1[4], s2[4];
    if ((t & 31) == 0) { s1[t >> 5] = sum; s2[t >> 5] = sq; }
    __syncthreads();
    sum = s1[0] + s1[1] + s1[2] + s1[3];
    sq  = s2[0] + s2[1] + s2[2] + s2[3];
    float mean = sum / C;
    float var  = sq / C - mean * mean;
    float inv  = rsqrtf(var + 1e-5f);
    if (t < nv) {
        float4 gv = ((const float4*)g)[t];
        float4 bv = ((const float4*)be)[t];
        float4 o4;
        o4.x = (v.x - mean) * inv * gv.x + bv.x;
        o4.y = (v.y - mean) * inv * gv.y + bv.y;
        o4.z = (v.z - mean) * inv * gv.z + bv.z;
        o4.w = (v.w - mean) * inv * gv.w + bv.w;
        ((float4*)(out + (size_t)m * C))[t] = o4;
    }
}

// ---------------- small helpers ----------------
__global__ __launch_bounds__(256) void embed_kernel(
    const int* __restrict__ x, const float* __restrict__ emb, float* __restrict__ h)
{
    int idx = blockIdx.x * blockDim.x + threadIdx.x;
    if (idx >= M_ * (H_ / 4)) return;
    int m = idx >> 7, c4 = idx & 127;
    int tok = x[m];
    float4 e = ((const float4*)(emb + (size_t)tok * H_))[c4];
    const float sc = 22.62741699796952f;  // sqrt(512)
    e.x *= sc; e.y *= sc; e.z *= sc; e.w *= sc;
    ((float4*)(h + (size_t)m * H_))[c4] = e;
}

__global__ __launch_bounds__(256) void rope_kernel(float* __restrict__ p)
{
    int idx = blockIdx.x * blockDim.x + threadIdx.x;
    if (idx >= M_ * NH_ * 32) return;
    int j   = idx & 31;
    int row = idx >> 5;
    int s   = (row >> 3) & (S_ - 1);
    float theta = expf(-(float)j * 0.28782313662425574f);
    float ang = (float)s * theta;
    float sn, cs;
    sincosf(ang, &sn, &cs);
    float* pr = p + (size_t)row * HD_;
    float x0 = pr[j], x1 = pr[j + 32];
    pr[j]      = x0 * cs - x1 * sn;
    pr[j + 32] = x1 * cs + x0 * sn;
}

__global__ __launch_bounds__(256) void maskmul_kernel(
    const float* __restrict__ in, float* __restrict__ out,
    const int* __restrict__ lengths)
{
    int idx = blockIdx.x * blockDim.x + threadIdx.x;
    if (idx >= M_ * H_) return;
    int m = idx >> 9;
    int s = m & (S_ - 1), b = m >> 9;
    out[idx] = in[idx] * ((s >= lengths[b]) ? 1.f : 0.f);
}

// (CO,CI,K) -> packed (CO,K,CI)
__global__ __launch_bounds__(256) void transpose_pack_w_kernel(
    const float* __restrict__ in, unsigned* __restrict__ out,
    int CO, int CI, int KK)
{
    int idx = blockIdx.x * blockDim.x + threadIdx.x;
    if (idx >= CO * CI * KK) return;
    int kk = idx % KK;
    int rest = idx / KK;
    int ci = rest % CI;
    int co = rest / CI;
    out[((size_t)co * KK + kk) * CI + ci] = pack_hl(in[idx]);
}

__global__ __launch_bounds__(256) void pack_w_kernel(
    const float* __restrict__ in, unsigned* __restrict__ out, int n)
{
    int i = blockIdx.x * blockDim.x + threadIdx.x;
    if (i < n) out[i] = pack_hl(in[i]);
}

__global__ __launch_bounds__(256) void pack_a_kernel(
    const float* __restrict__ x, unsigned* __restrict__ p, int n4)
{
    int i = blockIdx.x * blockDim.x + threadIdx.x;
    if (i >= n4) return;
    float4 v = ((const float4*)x)[i];
    uint4 o;
    o.x = pack_hl(v.x); o.y = pack_hl(v.y); o.z = pack_hl(v.z); o.w = pack_hl(v.w);
    ((uint4*)p)[i] = o;
}

__global__ __launch_bounds__(256) void dp_final_kernel(
    const float* __restrict__ x, const float* __restrict__ w,
    const float* __restrict__ pb, const int* __restrict__ lengths,
    float* __restrict__ out)
{
    int warp = threadIdx.x >> 5, lane = threadIdx.x & 31;
    int m = blockIdx.x * 8 + warp;
    if (m >= M_) return;
    const float* xr = x + (size_t)m * FD_;
    float s = 0.f;
    for (int c = lane; c < FD_; c += 32) s += xr[c] * w[c];
#pragma unroll
    for (int off = 16; off; off >>= 1) s += __shfl_xor_sync(0xffffffffu, s, off);
    if (lane == 0) {
        int b = m >> 9, sp = m & (S_ - 1);
        float mv = (sp >= lengths[b]) ? 1.f : 0.f;
        float val = (s + pb[0]) * mv;
        out[(size_t)b * S_ + sp] = ceilf(expf(val));
    }
}

// ---------------- orchestration ----------------
extern "C" void kernel_launch(void* const* d_in, const int* in_sizes, int n_in,
                              void* d_out, int out_size)
{
    const int*   x      = (const int*)  d_in[0];
    const int*   xlen   = (const int*)  d_in[1];
    const float* emb    = (const float*)d_in[2];
    const float* Wq     = (const float*)d_in[3];
    const float* bq     = (const float*)d_in[4];
    const float* Wk     = (const float*)d_in[5];
    const float* bk     = (const float*)d_in[6];
    const float* Wv     = (const float*)d_in[7];
    const float* bv     = (const float*)d_in[8];
    const float* Wo     = (const float*)d_in[9];
    const float* bo     = (const float*)d_in[10];
    const float* c1w    = (const float*)d_in[11];
    const float* c1b    = (const float*)d_in[12];
    const float* c2w    = (const float*)d_in[13];
    const float* c2b    = (const float*)d_in[14];
    const float* ln1g   = (const float*)d_in[15];
    const float* ln1b   = (const float*)d_in[16];
    const float* ln2g   = (const float*)d_in[17];
    const float* ln2b   = (const float*)d_in[18];
    const float* projw  = (const float*)d_in[19];
    const float* projb  = (const float*)d_in[20];
    const float* dpc1w  = (const float*)d_in[21];
    const float* dpc1b  = (const float*)d_in[22];
    const float* dpln1g = (const float*)d_in[23];
    const float* dpln1b = (const float*)d_in[24];
    const float* dpc2w  = (const float*)d_in[25];
    const float* dpc2b  = (const float*)d_in[26];
    const float* dpln2g = (const float*)d_in[27];
    const float* dpln2b = (const float*)d_in[28];
    const float* dppw   = (const float*)d_in[29];
    const float* dppb   = (const float*)d_in[30];
    float* out = (float*)d_out;

    float *h, *qb, *kb, *vb, *ab, *x1;
    unsigned *mid, *pa, *pw1t, *pw2t, *pwq, *pwk, *pwv, *pwo, *pproj, *pdp1, *pdp2;
    cudaGetSymbolAddress((void**)&h,    g_h);
    cudaGetSymbolAddress((void**)&qb,   g_q);
    cudaGetSymbolAddress((void**)&kb,   g_k);
    cudaGetSymbolAddress((void**)&vb,   g_v);
    cudaGetSymbolAddress((void**)&ab,   g_attn);
    cudaGetSymbolAddress((void**)&x1,   g_x1);
    cudaGetSymbolAddress((void**)&mid,  g_mid);
    cudaGetSymbolAddress((void**)&pa,   g_pa);
    cudaGetSymbolAddress((void**)&pw1t, g_pw1t);
    cudaGetSymbolAddress((void**)&pw2t, g_pw2t);
    cudaGetSymbolAddress((void**)&pwq,  g_pwq);
    cudaGetSymbolAddress((void**)&pwk,  g_pwk);
    cudaGetSymbolAddress((void**)&pwv,  g_pwv);
    cudaGetSymbolAddress((void**)&pwo,  g_pwo);
    cudaGetSymbolAddress((void**)&pproj, g_pproj);
    cudaGetSymbolAddress((void**)&pdp1, g_pdp1);
    cudaGetSymbolAddress((void**)&pdp2, g_pdp2);

    cudaFuncSetAttribute((const void*)attn_kernel,
                         cudaFuncAttributeMaxDynamicSharedMemorySize, 4 * 64 * 68 * 4);
    cudaFuncSetAttribute((const void*)hgemm_kernel,
                         cudaFuncAttributeMaxDynamicSharedMemorySize, 4 * PLANE);

    // ---- weight packing ----
    {
        int tot;
        tot = L_ * F_ * H_ * 3;
        transpose_pack_w_kernel<<<(tot + 255) / 256, 256>>>(c1w, pw1t, L_ * F_, H_, 3);
        tot = L_ * H_ * F_ * 3;
        transpose_pack_w_kernel<<<(tot + 255) / 256, 256>>>(c2w, pw2t, L_ * H_, F_, 3);
        tot = FD_ * H_ * 3;
        transpose_pack_w_kernel<<<(tot + 255) / 256, 256>>>(dpc1w, pdp1, FD_, H_, 3);
        tot = FD_ * FD_ * 3;
        transpose_pack_w_kernel<<<(tot + 255) / 256, 256>>>(dpc2w, pdp2, FD_, FD_, 3);
        tot = L_ * H_ * H_;
        pack_w_kernel<<<(tot + 255) / 256, 256>>>(Wq, pwq, tot);
        pack_w_kernel<<<(tot + 255) / 256, 256>>>(Wk, pwk, tot);
        pack_w_kernel<<<(tot + 255) / 256, 256>>>(Wv, pwv, tot);
        pack_w_kernel<<<(tot + 255) / 256, 256>>>(Wo, pwo, tot);
        tot = OUT_ * H_;
        pack_w_kernel<<<(tot + 255) / 256, 256>>>(projw, pproj, tot);
    }

    embed_kernel<<<M_ * (H_ / 4) / 256, 256>>>(x, emb, h);

    const int SMEM_G = 4 * PLANE;
    dim3 gH(H_ / 128, M_ / 128);        // (4,128)
    dim3 gF(F_ / 128, M_ / 128);        // (16,128)
    dim3 gMu(1, M_ / 128);
    dim3 gDp(FD_ / 128, M_ / 128);      // (2,128)
    dim3 ga(S_ / 64, NH_, B_);
    const int PACK_H  = M_ * H_ / 4 / 256;
    const int PACK_FD = M_ * FD_ / 4 / 256;

    for (int l = 0; l < L_; l++) {
        size_t wOff = (size_t)l * H_ * H_;
        pack_a_kernel<<<PACK_H, 256>>>(h, pa, M_ * H_ / 4);
        hgemm_kernel<<<gH, 256, SMEM_G>>>(pa, pwq + wOff, bq + l * H_, qb, H_, 9, 1, 0, 0, xlen);
        hgemm_kernel<<<gH, 256, SMEM_G>>>(pa, pwk + wOff, bk + l * H_, kb, H_, 9, 1, 0, 0, xlen);
        hgemm_kernel<<<gH, 256, SMEM_G>>>(pa, pwv + wOff, bv + l * H_, vb, H_, 9, 1, 0, 0, xlen);
        rope_kernel<<<M_ * NH_ * 32 / 256, 256>>>(qb);
        rope_kernel<<<M_ * NH_ * 32 / 256, 256>>>(kb);
        attn_kernel<<<ga, 256, 4 * 64 * 68 * 4>>>(qb, kb, vb, ab, xlen);
        pack_a_kernel<<<PACK_H, 256>>>(ab, pa, M_ * H_ / 4);
        hgemm_kernel<<<gH, 256, SMEM_G>>>(pa, pwo + wOff, bo + l * H_, qb, H_, 9, 1, 0, 0, xlen);
        ln_kernel<<<M_, 128>>>(qb, h, ln1g + l * H_, ln1b + l * H_, x1, H_);
        pack_a_kernel<<<PACK_H, 256>>>(x1, pa, M_ * H_ / 4);
        hgemm_kernel<<<gF, 256, SMEM_G>>>(pa, pw1t + (size_t)l * F_ * 3 * H_, c1b + l * F_,
                                          mid, F_, 9, 3, 1, FLAG_RELU | FLAG_PACKOUT, xlen);
        hgemm_kernel<<<gH, 256, SMEM_G>>>(mid, pw2t + (size_t)l * H_ * 3 * F_, c2b + l * H_,
                                          vb, H_, 11, 3, 1, 0, xlen);
        ln_kernel<<<M_, 128>>>(vb, x1, ln2g + l * H_, ln2b + l * H_, h, H_);
    }

    // mu = pointwise conv (transposed store to (B,OUT,S))
    pack_a_kernel<<<PACK_H, 256>>>(h, pa, M_ * H_ / 4);
    hgemm_kernel<<<gMu, 256, SMEM_G>>>(pa, pproj, projb, out, OUT_, 9, 1, 0, FLAG_TRANS, xlen);

    // duration predictor
    maskmul_kernel<<<M_ * H_ / 256, 256>>>(h, qb, xlen);
    pack_a_kernel<<<PACK_H, 256>>>(qb, pa, M_ * H_ / 4);
    hgemm_kernel<<<gDp, 256, SMEM_G>>>(pa, pdp1, dpc1b, kb, FD_, 9, 3, 1,
                                       FLAG_RELU | FLAG_MASK, xlen);
    ln_kernel<<<M_, 128>>>(kb, nullptr, dpln1g, dpln1b, vb, FD_);
    pack_a_kernel<<<PACK_FD, 256>>>(vb, pa, M_ * FD_ / 4);
    hgemm_kernel<<<gDp, 256, SMEM_G>>>(pa, pdp2, dpc2b, kb, FD_, 8, 3, 1,
                                       FLAG_RELU | FLAG_MASK, xlen);
    ln_kernel<<<M_, 128>>>(kb, nullptr, dpln2g, dpln2b, vb, FD_);
    dp_final_kernel<<<M_ / 8, 256>>>(vb, dppw, dppb, xlen,
                                     out + ((size_t)out_size - (size_t)B_ * S_));
}

// round 4
// speedup vs baseline: 3.1197x; 1.4741x over previous
#include <cuda_runtime.h>
#include <cuda_bf16.h>
#include <math.h>
#include <stdint.h>

#define B_   32
#define S_   512
#define H_   512
#define NH_  8
#define HD_  64
#define F_   2048
#define L_   6
#define OUT_ 80
#define FD_  256
#define M_   (B_*S_)   // 16384 tokens

typedef __nv_bfloat16  bf16;
typedef __nv_bfloat162 bf162;

// ---------------- scratch (static device globals) ----------------
__device__ float g_h   [M_*H_];
__device__ float g_x1  [M_*H_];
__device__ float g_op  [M_*H_];
__device__ float g_cv2 [M_*H_];
__device__ float g_qkv [M_*3*H_];
__device__ bf16  g_hh  [M_*H_],  g_hl  [M_*H_];
__device__ bf16  g_x1h [M_*H_],  g_x1l [M_*H_];
__device__ bf16  g_ah  [M_*H_],  g_al  [M_*H_];
__device__ bf16  g_midh[M_*F_],  g_midl[M_*F_];
__device__ bf16  g_mkh [M_*H_],  g_mkl [M_*H_];
__device__ bf16  g_dpxh[M_*FD_], g_dpxl[M_*FD_];
// weights (hi/lo split, GEMM-ready layout [n][Kdim])
__device__ bf16  g_wqkvh[L_*3*H_*H_], g_wqkvl[L_*3*H_*H_];
__device__ bf16  g_woh [L_*H_*H_],    g_wol [L_*H_*H_];
__device__ bf16  g_w1h [L_*F_*3*H_],  g_w1l [L_*F_*3*H_];
__device__ bf16  g_w2h [L_*H_*3*F_],  g_w2l [L_*H_*3*F_];
__device__ bf16  g_pjh [OUT_*H_],     g_pjl [OUT_*H_];
__device__ bf16  g_d1h [FD_*3*H_],    g_d1l [FD_*3*H_];
__device__ bf16  g_d2h [FD_*3*FD_],   g_d2l [FD_*3*FD_];
__device__ float g_bqkv[L_*3*H_];

#define FLAG_RELU  1
#define FLAG_MASK  2
#define FLAG_TRANS 4

// ---------------- helpers ----------------
__device__ __forceinline__ void split_hl(float x, bf16& h, bf16& l) {
    h = __float2bfloat16_rn(x);
    l = __float2bfloat16_rn(x - __bfloat162float(h));
}

__device__ __forceinline__ uint32_t smem_u32(const void* p) {
    uint32_t a;
    asm("{ .reg .u64 t; cvta.to.shared.u64 t, %1; cvt.u32.u64 %0, t; }" : "=r"(a) : "l"(p));
    return a;
}

__device__ __forceinline__ void cpa16(uint32_t dst, const void* src, int sz) {
    asm volatile("cp.async.cg.shared.global [%0], [%1], 16, %2;"
                 :: "r"(dst), "l"(src), "r"(sz));
}

__device__ __forceinline__ void ldsm4(uint32_t* r, uint32_t addr) {
    asm volatile("ldmatrix.sync.aligned.m8n8.x4.shared.b16 {%0,%1,%2,%3}, [%4];"
                 : "=r"(r[0]), "=r"(r[1]), "=r"(r[2]), "=r"(r[3]) : "r"(addr));
}

__device__ __forceinline__ void mma16816(float* c, const uint32_t* a,
                                         uint32_t b0, uint32_t b1) {
    asm volatile(
        "mma.sync.aligned.m16n8k16.row.col.f32.bf16.bf16.f32 "
        "{%0,%1,%2,%3}, {%4,%5,%6,%7}, {%8,%9}, {%0,%1,%2,%3};"
        : "+f"(c[0]), "+f"(c[1]), "+f"(c[2]), "+f"(c[3])
        : "r"(a[0]), "r"(a[1]), "r"(a[2]), "r"(a[3]), "r"(b0), "r"(b1));
}

// ---------------- split-bf16 HMMA GEMM ----------------
// C[m,n] = sum_kk A_virt[m,kk]*W[n,kk]; A/W given as pre-split hi/lo bf16 planes.
// Tile 64(M) x 128(N), K-chunk 64; 128 threads (4 warps, 2x2, warp tile 32x64).
// smem: Ahi 8K | Alo 8K | Bhi 16K | Blo 16K = 48KB, XOR-swizzled 128B rows.
__global__ __launch_bounds__(128, 4) void hgemm_kernel(
    const bf16* __restrict__ Ahi, const bf16* __restrict__ Alo,
    const bf16* __restrict__ Whi, const bf16* __restrict__ Wlo,
    const float* __restrict__ bias,
    float* __restrict__ Cf, bf16* __restrict__ Chi, bf16* __restrict__ Clo,
    int N, int cinLog2, int nseg, int pad, int flags,
    const int* __restrict__ lengths)
{
    extern __shared__ __align__(16) char smem[];
    const uint32_t sb   = smem_u32(smem);
    const uint32_t sAHI = sb, sALO = sb + 8192, sBHI = sb + 16384, sBLO = sb + 32768;

    int t = threadIdx.x, wid = t >> 5, lane = t & 31;
    int m0 = blockIdx.y * 64, n0 = blockIdx.x * 128;
    int cin  = 1 << cinLog2;
    int Kdim = nseg << cinLog2;
    int nch  = Kdim >> 6;
    int wm = (wid >> 1) * 32, wn = (wid & 1) * 64;

    float acc[2][8][4];
#pragma unroll
    for (int i = 0; i < 2; i++)
#pragma unroll
        for (int j = 0; j < 8; j++)
#pragma unroll
            for (int e = 0; e < 4; e++) acc[i][j][e] = 0.f;

    for (int kc = 0; kc < nch; kc++) {
        int kk0 = kc << 6;
        int seg = kk0 >> cinLog2;
        int ci0 = kk0 & (cin - 1);
        // ---- A: 64 rows x 8 chunks of 16B per plane ----
#pragma unroll
        for (int it = 0; it < 4; it++) {
            int idx = t + it * 128;
            int r = idx >> 3, c = idx & 7;
            int m = m0 + r;
            const bf16 *sh = Ahi, *sl = Alo;
            int sz = 16;
            if (nseg == 1) {
                size_t off = (size_t)m * cin + kk0 + c * 8;
                sh = Ahi + off; sl = Alo + off;
            } else {
                int s = m & (S_ - 1);
                int srow = s + seg - pad;
                if (srow >= 0 && srow < S_) {
                    size_t off = (size_t)(m + srow - s) * cin + ci0 + c * 8;
                    sh = Ahi + off; sl = Alo + off;
                } else sz = 0;
            }
            uint32_t d = (uint32_t)(r * 128 + ((c ^ (r & 7)) << 4));
            cpa16(sAHI + d, sh, sz);
            cpa16(sALO + d, sl, sz);
        }
        // ---- B: 128 rows x 8 chunks per plane ----
#pragma unroll
        for (int it = 0; it < 8; it++) {
            int idx = t + it * 128;
            int r = idx >> 3, c = idx & 7;
            int n = n0 + r;
            int sz = (n < N) ? 16 : 0;
            size_t off = (n < N) ? ((size_t)n * Kdim + kk0 + c * 8) : 0;
            uint32_t d = (uint32_t)(r * 128 + ((c ^ (r & 7)) << 4));
            cpa16(sBHI + d, Whi + off, sz);
            cpa16(sBLO + d, Wlo + off, sz);
        }
        asm volatile("cp.async.commit_group;");
        asm volatile("cp.async.wait_group 0;");
        __syncthreads();

        // ---- compute: 4 k16-steps ----
        int rsel = lane & 15;
        int chalf = lane >> 4;
#pragma unroll
        for (int ks = 0; ks < 4; ks++) {
            int cbase = ks * 2 + chalf;
            uint32_t ah[2][4], al[2][4];
#pragma unroll
            for (int i = 0; i < 2; i++) {
                int rr = wm + i * 16 + rsel;
                uint32_t off = (uint32_t)(rr * 128 + ((cbase ^ (rr & 7)) << 4));
                ldsm4(ah[i], sAHI + off);
                ldsm4(al[i], sALO + off);
            }
#pragma unroll
            for (int jj = 0; jj < 4; jj++) {
                uint32_t bh[4], bl[4];
                int rr = wn + jj * 16 + rsel;
                uint32_t off = (uint32_t)(rr * 128 + ((cbase ^ (rr & 7)) << 4));
                ldsm4(bh, sBHI + off);
                ldsm4(bl, sBLO + off);
#pragma unroll
                for (int i = 0; i < 2; i++)
#pragma unroll
                    for (int o = 0; o < 2; o++) {
                        float* a4 = acc[i][jj * 2 + o];
                        mma16816(a4, ah[i], bh[o], bh[o + 2]);
                        mma16816(a4, ah[i], bl[o], bl[o + 2]);
                        mma16816(a4, al[i], bh[o], bh[o + 2]);
                    }
            }
        }
        __syncthreads();
    }

    // ---- epilogue ----
    int r0 = lane >> 2, c0 = (lane & 3) * 2;
#pragma unroll
    for (int i = 0; i < 2; i++) {
        int mA = m0 + wm + i * 16 + r0;
        int mB = mA + 8;
        int sA = mA & (S_ - 1), bA = mA >> 9;
        int sB = mB & (S_ - 1), bB = mB >> 9;
        float mvA = 1.f, mvB = 1.f;
        if (flags & FLAG_MASK) {
            mvA = (sA >= lengths[bA]) ? 1.f : 0.f;   // reference's inverted mask
            mvB = (sB >= lengths[bB]) ? 1.f : 0.f;
        }
#pragma unroll
        for (int j = 0; j < 8; j++) {
            int nb = n0 + wn + j * 8 + c0;
            if (nb >= N) continue;
            float b0 = __ldg(bias + nb);
            float b1 = (nb + 1 < N) ? __ldg(bias + nb + 1) : 0.f;
            float v00 = acc[i][j][0] + b0, v01 = acc[i][j][1] + b1;
            float v10 = acc[i][j][2] + b0, v11 = acc[i][j][3] + b1;
            if (flags & FLAG_RELU) {
                v00 = fmaxf(v00, 0.f); v01 = fmaxf(v01, 0.f);
                v10 = fmaxf(v10, 0.f); v11 = fmaxf(v11, 0.f);
            }
            v00 *= mvA; v01 *= mvA; v10 *= mvB; v11 *= mvB;
            if (flags & FLAG_TRANS) {
                Cf[((size_t)bA * N + nb) * S_ + sA] = v00;
                Cf[((size_t)bB * N + nb) * S_ + sB] = v10;
                if (nb + 1 < N) {
                    Cf[((size_t)bA * N + nb + 1) * S_ + sA] = v01;
                    Cf[((size_t)bB * N + nb + 1) * S_ + sB] = v11;
                }
            } else {
                if (Cf) {
                    *(float2*)(Cf + (size_t)mA * N + nb) = make_float2(v00, v01);
                    *(float2*)(Cf + (size_t)mB * N + nb) = make_float2(v10, v11);
                }
                if (Chi) {
                    bf16 h0, l0, h1, l1;
                    split_hl(v00, h0, l0); split_hl(v01, h1, l1);
                    *(bf162*)(Chi + (size_t)mA * N + nb) = bf162(h0, h1);
                    *(bf162*)(Clo + (size_t)mA * N + nb) = bf162(l0, l1);
                    split_hl(v10, h0, l0); split_hl(v11, h1, l1);
                    *(bf162*)(Chi + (size_t)mB * N + nb) = bf162(h0, h1);
                    *(bf162*)(Clo + (size_t)mB * N + nb) = bf162(l0, l1);
                }
            }
        }
    }
}

// ---------------- flash attention (fp32, HD=64, S=512), rope fused ----------------
// reads fused qkv buffer [m][1536]: q at hh*64, k at 512+hh*64, v at 1024+hh*64
__global__ __launch_bounds__(256) void attn_kernel(
    const float* __restrict__ qkv,
    bf16* __restrict__ ohi, bf16* __restrict__ olo,
    const int* __restrict__ lengths)
{
    extern __shared__ float sm[];
    float* Qs = sm;
    float* Ks = sm + 64 * 68;
    float* Vs = sm + 2 * 64 * 68;
    float* Ps = sm + 3 * 64 * 68;

    int t  = threadIdx.x;
    int tx = t & 15, ty = t >> 4;
    int qt = blockIdx.x, hh = blockIdx.y, b = blockIdx.z;
    int len = lengths[b];
    const int RS = 3 * H_;  // qkv row stride

    int lr = t >> 4;
    int d4 = (t & 15) * 4;
    int jb = d4 & 31;           // rope theta index base
    float th[4];
#pragma unroll
    for (int e = 0; e < 4; e++)
        th[e] = expf(-(float)(jb + e) * 0.28782313662425574f);
    float sgn = (d4 < 32) ? -1.f : 1.f;

    // load Q with rope
    const float* qbase = qkv + ((size_t)b * S_ + qt * 64) * RS + hh * HD_;
#pragma unroll
    for (int i = 0; i < 4; i++) {
        int r = lr + i * 16;
        int s = qt * 64 + r;
        float4 xv = *(const float4*)(qbase + (size_t)r * RS + d4);
        float4 pv = *(const float4*)(qbase + (size_t)r * RS + (d4 ^ 32));
        float xa[4] = {xv.x, xv.y, xv.z, xv.w};
        float pa[4] = {pv.x, pv.y, pv.z, pv.w};
#pragma unroll
        for (int e = 0; e < 4; e++) {
            float sn, cs;
            sincosf((float)s * th[e], &sn, &cs);
            Qs[(d4 + e) * 68 + r] = xa[e] * cs + sgn * pa[e] * sn;
        }
    }

    float acc[4][4];
    float mI[4], lI[4];
#pragma unroll
    for (int i = 0; i < 4; i++) {
        mI[i] = -INFINITY; lI[i] = 0.f;
#pragma unroll
        for (int j = 0; j < 4; j++) acc[i][j] = 0.f;
    }

    for (int kt0 = 0; kt0 < S_; kt0 += 64) {
        const float* kbase = qkv + ((size_t)b * S_ + kt0) * RS + H_ + hh * HD_;
        const float* vbase = qkv + ((size_t)b * S_ + kt0) * RS + 2 * H_ + hh * HD_;
#pragma unroll
        for (int i = 0; i < 4; i++) {
            int r = lr + i * 16;
            int s = kt0 + r;
            float4 kv = *(const float4*)(kbase + (size_t)r * RS + d4);
            float4 pv = *(const float4*)(kbase + (size_t)r * RS + (d4 ^ 32));
            float ka[4] = {kv.x, kv.y, kv.z, kv.w};
            float pa[4] = {pv.x, pv.y, pv.z, pv.w};
#pragma unroll
            for (int e = 0; e < 4; e++) {
                float sn, cs;
                sincosf((float)s * th[e], &sn, &cs);
                Ks[(d4 + e) * 68 + r] = ka[e] * cs + sgn * pa[e] * sn;
            }
            float4 vv = *(const float4*)(vbase + (size_t)r * RS + d4);
            *(float4*)&Vs[r * 68 + d4] = vv;
        }
        __syncthreads();

        float sv[4][4];
#pragma unroll
        for (int i = 0; i < 4; i++)
#pragma unroll
            for (int j = 0; j < 4; j++) sv[i][j] = 0.f;

        for (int d = 0; d < 64; d++) {
            float4 aa = *(const float4*)&Qs[d * 68 + ty * 4];
            float4 bb = *(const float4*)&Ks[d * 68 + tx * 4];
            float av[4] = {aa.x, aa.y, aa.z, aa.w};
            float bv[4] = {bb.x, bb.y, bb.z, bb.w};
#pragma unroll
            for (int i = 0; i < 4; i++)
#pragma unroll
                for (int j = 0; j < 4; j++)
                    sv[i][j] += av[i] * bv[j];
        }
#pragma unroll
        for (int i = 0; i < 4; i++)
#pragma unroll
            for (int j = 0; j < 4; j++) {
                int kp = kt0 + tx * 4 + j;
                float x = sv[i][j] * 0.125f;
                sv[i][j] = (kp >= len) ? x : -1e9f;   // reference's inverted mask
            }

#pragma unroll
        for (int i = 0; i < 4; i++) {
            float rmax = fmaxf(fmaxf(sv[i][0], sv[i][1]), fmaxf(sv[i][2], sv[i][3]));
#pragma unroll
            for (int off = 1; off < 16; off <<= 1)
                rmax = fmaxf(rmax, __shfl_xor_sync(0xffffffffu, rmax, off));
            float mn    = fmaxf(mI[i], rmax);
            float alpha = __expf(mI[i] - mn);
            mI[i] = mn;
            float ssum = 0.f;
#pragma unroll
            for (int j = 0; j < 4; j++) {
                float p = __expf(sv[i][j] - mn);
                Ps[(tx * 4 + j) * 68 + ty * 4 + i] = p;
                ssum += p;
            }
#pragma unroll
            for (int off = 1; off < 16; off <<= 1)
                ssum += __shfl_xor_sync(0xffffffffu, ssum, off);
            lI[i] = lI[i] * alpha + ssum;
#pragma unroll
            for (int j = 0; j < 4; j++) acc[i][j] *= alpha;
        }
        __syncthreads();

        for (int kk = 0; kk < 64; kk++) {
            float4 pv = *(const float4*)&Ps[kk * 68 + ty * 4];
            float4 vv = *(const float4*)&Vs[kk * 68 + tx * 4];
            float pa[4] = {pv.x, pv.y, pv.z, pv.w};
            float va[4] = {vv.x, vv.y, vv.z, vv.w};
#pragma unroll
            for (int i = 0; i < 4; i++)
#pragma unroll
                for (int j = 0; j < 4; j++)
                    acc[i][j] += pa[i] * va[j];
        }
        __syncthreads();
    }

    // epilogue: split-store into [m][H] hi/lo planes
#pragma unroll
    for (int i = 0; i < 4; i++) {
        int r = ty * 4 + i;
        size_t row = ((size_t)b * S_ + qt * 64 + r) * H_ + hh * HD_ + tx * 4;
        float inv = 1.f / lI[i];
        bf16 h0, l0, h1, l1;
        split_hl(acc[i][0] * inv, h0, l0); split_hl(acc[i][1] * inv, h1, l1);
        *(bf162*)(ohi + row)     = bf162(h0, h1);
        *(bf162*)(olo + row)     = bf162(l0, l1);
        split_hl(acc[i][2] * inv, h0, l0); split_hl(acc[i][3] * inv, h1, l1);
        *(bf162*)(ohi + row + 2) = bf162(h0, h1);
        *(bf162*)(olo + row + 2) = bf162(l0, l1);
    }
}

// ---------------- LayerNorm (residual add + optional split outputs) ----------------
__global__ __launch_bounds__(128) void ln_kernel(
    const float* __restrict__ x, const float* __restrict__ res,
    const float* __restrict__ g, const float* __restrict__ be,
    float* __restrict__ out, bf16* __restrict__ ohi, bf16* __restrict__ olo, int C)
{
    int m = blockIdx.x, t = threadIdx.x;
    int nv = C >> 2;
    float4 v = make_float4(0.f, 0.f, 0.f, 0.f);
    if (t < nv) {
        v = ((const float4*)(x + (size_t)m * C))[t];
        if (res) {
            float4 w = ((const float4*)(res + (size_t)m * C))[t];
            v.x += w.x; v.y += w.y; v.z += w.z; v.w += w.w;
        }
    }
    float sum = v.x + v.y + v.z + v.w;
    float sq  = v.x * v.x + v.y * v.y + v.z * v.z + v.w * v.w;
#pragma unroll
    for (int off = 16; off; off >>= 1) {
        sum += __shfl_xor_sync(0xffffffffu, sum, off);
        sq  += __shfl_xor_sync(0xffffffffu, sq,  off);
    }
    __shared__ float s1[4], s2[4];
    if ((t & 31) == 0) { s1[t >> 5] = sum; s2[t >> 5] = sq; }
    __syncthreads();
    sum = s1[0] + s1[1] + s1[2] + s1[3];
    sq  = s2[0] + s2[1] + s2[2] + s2[3];
    float mean = sum / C;
    float var  = sq / C - mean * mean;
    float inv  = rsqrtf(var + 1e-5f);
    if (t < nv) {
        float4 gv = ((const float4*)g)[t];
        float4 bv = ((const float4*)be)[t];
        float4 o4;
        o4.x = (v.x - mean) * inv * gv.x + bv.x;
        o4.y = (v.y - mean) * inv * gv.y + bv.y;
        o4.z = (v.z - mean) * inv * gv.z + bv.z;
        o4.w = (v.w - mean) * inv * gv.w + bv.w;
        if (out) ((float4*)(out + (size_t)m * C))[t] = o4;
        if (ohi) {
            bf16 h0, l0, h1, l1, h2, l2, h3, l3;
            split_hl(o4.x, h0, l0); split_hl(o4.y, h1, l1);
            split_hl(o4.z, h2, l2); split_hl(o4.w, h3, l3);
            *(bf162*)(ohi + (size_t)m * C + t * 4)     = bf162(h0, h1);
            *(bf162*)(ohi + (size_t)m * C + t * 4 + 2) = bf162(h2, h3);
            *(bf162*)(olo + (size_t)m * C + t * 4)     = bf162(l0, l1);
            *(bf162*)(olo + (size_t)m * C + t * 4 + 2) = bf162(l2, l3);
        }
    }
}

// ---------------- small kernels ----------------
__global__ __launch_bounds__(256) void embed_kernel(
    const int* __restrict__ x, const float* __restrict__ emb,
    float* __restrict__ h, bf16* __restrict__ hh, bf16* __restrict__ hl)
{
    int idx = blockIdx.x * blockDim.x + threadIdx.x;
    if (idx >= M_ * (H_ / 4)) return;
    int m = idx >> 7, c4 = idx & 127;
    int tok = x[m];
    float4 e = ((const float4*)(emb + (size_t)tok * H_))[c4];
    const float sc = 22.62741699796952f;  // sqrt(512)
    e.x *= sc; e.y *= sc; e.z *= sc; e.w *= sc;
    ((float4*)(h + (size_t)m * H_))[c4] = e;
    bf16 h0, l0, h1, l1, h2, l2, h3, l3;
    split_hl(e.x, h0, l0); split_hl(e.y, h1, l1);
    split_hl(e.z, h2, l2); split_hl(e.w, h3, l3);
    *(bf162*)(hh + (size_t)m * H_ + c4 * 4)     = bf162(h0, h1);
    *(bf162*)(hh + (size_t)m * H_ + c4 * 4 + 2) = bf162(h2, h3);
    *(bf162*)(hl + (size_t)m * H_ + c4 * 4)     = bf162(l0, l1);
    *(bf162*)(hl + (size_t)m * H_ + c4 * 4 + 2) = bf162(l2, l3);
}

__global__ __launch_bounds__(256) void maskmul_kernel(
    const float* __restrict__ in, bf16* __restrict__ ohi, bf16* __restrict__ olo,
    const int* __restrict__ lengths)
{
    int idx = blockIdx.x * blockDim.x + threadIdx.x;
    if (idx >= M_ * H_) return;
    int m = idx >> 9;
    int s = m & (S_ - 1), b = m >> 9;
    float v = in[idx] * ((s >= lengths[b]) ? 1.f : 0.f);  // inverted mask
    bf16 h, l;
    split_hl(v, h, l);
    ohi[idx] = h; olo[idx] = l;
}

// all conv-style weights: (CO,CI,K) -> split [co][kk*CI+ci]
#define NW1 (L_*F_*H_*3)
#define NW2 (L_*H_*F_*3)
#define ND1 (FD_*H_*3)
#define ND2 (FD_*FD_*3)
__global__ __launch_bounds__(256) void prep_conv_kernel(
    const float* __restrict__ c1w, const float* __restrict__ c2w,
    const float* __restrict__ d1w, const float* __restrict__ d2w)
{
    int idx = blockIdx.x * blockDim.x + threadIdx.x;
    const float* src; bf16 *dh, *dl; int CI; int base;
    if (idx < NW1)                       { src = c1w; dh = g_w1h; dl = g_w1l; CI = H_; base = idx; }
    else if (idx < NW1 + NW2)            { src = c2w; dh = g_w2h; dl = g_w2l; CI = F_; base = idx - NW1; }
    else if (idx < NW1 + NW2 + ND1)      { src = d1w; dh = g_d1h; dl = g_d1l; CI = H_; base = idx - NW1 - NW2; }
    else if (idx < NW1 + NW2 + ND1 + ND2){ src = d2w; dh = g_d2h; dl = g_d2l; CI = FD_; base = idx - NW1 - NW2 - ND1; }
    else return;
    int kk = base % 3;
    int rest = base / 3;
    int ci = rest % CI;
    int co = rest / CI;
    float v = src[base];
    bf16 h, l; split_hl(v, h, l);
    size_t o = (size_t)co * (3 * CI) + kk * CI + ci;
    dh[o] = h; dl[o] = l;
}

#define NQKV (L_*3*H_*H_)
#define NWO  (L_*H_*H_)
#define NPJ  (OUT_*H_)
#define NBQ  (L_*3*H_)
__global__ __launch_bounds__(256) void prep_lin_kernel(
    const float* __restrict__ Wq, const float* __restrict__ Wk,
    const float* __restrict__ Wv, const float* __restrict__ Wo,
    const float* __restrict__ pj,
    const float* __restrict__ bq, const float* __restrict__ bk,
    const float* __restrict__ bv)
{
    int idx = blockIdx.x * blockDim.x + threadIdx.x;
    if (idx < NQKV) {
        int e = idx % H_;
        int n = (idx / H_) % (3 * H_);
        int l = idx / (3 * H_ * H_);
        const float* W = (n < H_) ? Wq : (n < 2 * H_) ? Wk : Wv;
        int nn = n & (H_ - 1);
        float v = W[(size_t)l * H_ * H_ + (size_t)nn * H_ + e];
        bf16 h, lo; split_hl(v, h, lo);
        g_wqkvh[idx] = h; g_wqkvl[idx] = lo;
        return;
    }
    int i2 = idx - NQKV;
    if (i2 < NWO) {
        float v = Wo[i2];
        bf16 h, lo; split_hl(v, h, lo);
        g_woh[i2] = h; g_wol[i2] = lo;
        return;
    }
    int i3 = i2 - NWO;
    if (i3 < NPJ) {
        float v = pj[i3];
        bf16 h, lo; split_hl(v, h, lo);
        g_pjh[i3] = h; g_pjl[i3] = lo;
        return;
    }
    int i4 = i3 - NPJ;
    if (i4 < NBQ) {
        int n = i4 % (3 * H_);
        int l = i4 / (3 * H_);
        const float* bb = (n < H_) ? bq : (n < 2 * H_) ? bk : bv;
        g_bqkv[i4] = bb[l * H_ + (n & (H_ - 1))];
    }
}

__global__ __launch_bounds__(256) void dp_final_kernel(
    const float* __restrict__ x, const float* __restrict__ w,
    const float* __restrict__ pb, const int* __restrict__ lengths,
    float* __restrict__ out)
{
    int warp = threadIdx.x >> 5, lane = threadIdx.x & 31;
    int m = blockIdx.x * 8 + warp;
    if (m >= M_) return;
    const float* xr = x + (size_t)m * FD_;
    float s = 0.f;
    for (int c = lane; c < FD_; c += 32) s += xr[c] * w[c];
#pragma unroll
    for (int off = 16; off; off >>= 1) s += __shfl_xor_sync(0xffffffffu, s, off);
    if (lane == 0) {
        int b = m >> 9, sp = m & (S_ - 1);
        float mv = (sp >= lengths[b]) ? 1.f : 0.f;
        float val = (s + pb[0]) * mv;
        out[(size_t)b * S_ + sp] = ceilf(expf(val));
    }
}

// ---------------- orchestration ----------------
extern "C" void kernel_launch(void* const* d_in, const int* in_sizes, int n_in,
                              void* d_out, int out_size)
{
    const int*   x      = (const int*)  d_in[0];
    const int*   xlen   = (const int*)  d_in[1];
    const float* emb    = (const float*)d_in[2];
    const float* Wq     = (const float*)d_in[3];
    const float* bq     = (const float*)d_in[4];
    const float* Wk     = (const float*)d_in[5];
    const float* bk     = (const float*)d_in[6];
    const float* Wv     = (const float*)d_in[7];
    const float* bv     = (const float*)d_in[8];
    const float* Wo     = (const float*)d_in[9];
    const float* bo     = (const float*)d_in[10];
    const float* c1w    = (const float*)d_in[11];
    const float* c1b    = (const float*)d_in[12];
    const float* c2w    = (const float*)d_in[13];
    const float* c2b    = (const float*)d_in[14];
    const float* ln1g   = (const float*)d_in[15];
    const float* ln1b   = (const float*)d_in[16];
    const float* ln2g   = (const float*)d_in[17];
    const float* ln2b   = (const float*)d_in[18];
    const float* projw  = (const float*)d_in[19];
    const float* projb  = (const float*)d_in[20];
    const float* dpc1w  = (const float*)d_in[21];
    const float* dpc1b  = (const float*)d_in[22];
    const float* dpln1g = (const float*)d_in[23];
    const float* dpln1b = (const float*)d_in[24];
    const float* dpc2w  = (const float*)d_in[25];
    const float* dpc2b  = (const float*)d_in[26];
    const float* dpln2g = (const float*)d_in[27];
    const float* dpln2b = (const float*)d_in[28];
    const float* dppw   = (const float*)d_in[29];
    const float* dppb   = (const float*)d_in[30];
    float* out = (float*)d_out;

    float *h, *x1, *op, *cv2, *qkv, *bqkv;
    bf16 *hh, *hl, *x1h, *x1l, *ah, *al, *midh, *midl, *mkh, *mkl, *dpxh, *dpxl;
    bf16 *wqh, *wql, *woh, *wol, *w1h, *w1l, *w2h, *w2l, *pjh, *pjl, *d1h, *d1l, *d2h, *d2l;
    cudaGetSymbolAddress((void**)&h,    g_h);
    cudaGetSymbolAddress((void**)&x1,   g_x1);
    cudaGetSymbolAddress((void**)&op,   g_op);
    cudaGetSymbolAddress((void**)&cv2,  g_cv2);
    cudaGetSymbolAddress((void**)&qkv,  g_qkv);
    cudaGetSymbolAddress((void**)&hh,   g_hh);
    cudaGetSymbolAddress((void**)&hl,   g_hl);
    cudaGetSymbolAddress((void**)&x1h,  g_x1h);
    cudaGetSymbolAddress((void**)&x1l,  g_x1l);
    cudaGetSymbolAddress((void**)&ah,   g_ah);
    cudaGetSymbolAddress((void**)&al,   g_al);
    cudaGetSymbolAddress((void**)&midh, g_midh);
    cudaGetSymbolAddress((void**)&midl, g_midl);
    cudaGetSymbolAddress((void**)&mkh,  g_mkh);
    cudaGetSymbolAddress((void**)&mkl,  g_mkl);
    cudaGetSymbolAddress((void**)&dpxh, g_dpxh);
    cudaGetSymbolAddress((void**)&dpxl, g_dpxl);
    cudaGetSymbolAddress((void**)&wqh,  g_wqkvh);
    cudaGetSymbolAddress((void**)&wql,  g_wqkvl);
    cudaGetSymbolAddress((void**)&woh,  g_woh);
    cudaGetSymbolAddress((void**)&wol,  g_wol);
    cudaGetSymbolAddress((void**)&w1h,  g_w1h);
    cudaGetSymbolAddress((void**)&w1l,  g_w1l);
    cudaGetSymbolAddress((void**)&w2h,  g_w2h);
    cudaGetSymbolAddress((void**)&w2l,  g_w2l);
    cudaGetSymbolAddress((void**)&pjh,  g_pjh);
    cudaGetSymbolAddress((void**)&pjl,  g_pjl);
    cudaGetSymbolAddress((void**)&d1h,  g_d1h);
    cudaGetSymbolAddress((void**)&d1l,  g_d1l);
    cudaGetSymbolAddress((void**)&d2h,  g_d2h);
    cudaGetSymbolAddress((void**)&d2l,  g_d2l);
    cudaGetSymbolAddress((void**)&bqkv, g_bqkv);

    cudaFuncSetAttribute((const void*)attn_kernel,
                         cudaFuncAttributeMaxDynamicSharedMemorySize, 4 * 64 * 68 * 4);
    cudaFuncSetAttribute((const void*)hgemm_kernel,
                         cudaFuncAttributeMaxDynamicSharedMemorySize, 49152);

    // launch #1, #2: weight prep (ordered so launch #6 = O-proj hgemm for ncu -s 5)
    {
        int tot = NW1 + NW2 + ND1 + ND2;
        prep_conv_kernel<<<(tot + 255) / 256, 256>>>(c1w, c2w, dpc1w, dpc2w);
        tot = NQKV + NWO + NPJ + NBQ;
        prep_lin_kernel<<<(tot + 255) / 256, 256>>>(Wq, Wk, Wv, Wo, projw, bq, bk, bv);
    }
    // #3
    embed_kernel<<<M_ * (H_ / 4) / 256, 256>>>(x, emb, h, hh, hl);

    const int SM_G = 49152;
    dim3 gQKV(3 * H_ / 128, M_ / 64);   // (12,256)
    dim3 gH(H_ / 128, M_ / 64);         // (4,256)
    dim3 gF(F_ / 128, M_ / 64);         // (16,256)
    dim3 gMu(1, M_ / 64);
    dim3 gDp(FD_ / 128, M_ / 64);       // (2,256)
    dim3 ga(S_ / 64, NH_, B_);

    for (int l = 0; l < L_; l++) {
        size_t wOff = (size_t)l * H_ * H_;
        size_t wqOff = (size_t)l * 3 * H_ * H_;
        hgemm_kernel<<<gQKV, 128, SM_G>>>(hh, hl, wqh + wqOff, wql + wqOff,
                                          bqkv + l * 3 * H_, qkv, nullptr, nullptr,
                                          3 * H_, 9, 1, 0, 0, xlen);
        attn_kernel<<<ga, 256, 4 * 64 * 68 * 4>>>(qkv, ah, al, xlen);
        hgemm_kernel<<<gH, 128, SM_G>>>(ah, al, woh + wOff, wol + wOff,
                                        bo + l * H_, op, nullptr, nullptr,
                                        H_, 9, 1, 0, 0, xlen);
        ln_kernel<<<M_, 128>>>(op, h, ln1g + l * H_, ln1b + l * H_, x1, x1h, x1l, H_);
        hgemm_kernel<<<gF, 128, SM_G>>>(x1h, x1l,
                                        w1h + (size_t)l * F_ * 3 * H_, w1l + (size_t)l * F_ * 3 * H_,
                                        c1b + l * F_, nullptr, midh, midl,
                                        F_, 9, 3, 1, FLAG_RELU, xlen);
        hgemm_kernel<<<gH, 128, SM_G>>>(midh, midl,
                                        w2h + (size_t)l * H_ * 3 * F_, w2l + (size_t)l * H_ * 3 * F_,
                                        c2b + l * H_, cv2, nullptr, nullptr,
                                        H_, 11, 3, 1, 0, xlen);
        ln_kernel<<<M_, 128>>>(cv2, x1, ln2g + l * H_, ln2b + l * H_, h, hh, hl, H_);
    }

    // mu = pointwise conv (transposed store to (B,OUT,S))
    hgemm_kernel<<<gMu, 128, SM_G>>>(hh, hl, pjh, pjl, projb, out, nullptr, nullptr,
                                     OUT_, 9, 1, 0, FLAG_TRANS, xlen);

    // duration predictor
    maskmul_kernel<<<M_ * H_ / 256, 256>>>(h, mkh, mkl, xlen);
    hgemm_kernel<<<gDp, 128, SM_G>>>(mkh, mkl, d1h, d1l, dpc1b, op, nullptr, nullptr,
                                     FD_, 9, 3, 1, FLAG_RELU | FLAG_MASK, xlen);
    ln_kernel<<<M_, 128>>>(op, nullptr, dpln1g, dpln1b, cv2, dpxh, dpxl, FD_);
    hgemm_kernel<<<gDp, 128, SM_G>>>(dpxh, dpxl, d2h, d2l, dpc2b, op, nullptr, nullptr,
                                     FD_, 8, 3, 1, FLAG_RELU | FLAG_MASK, xlen);
    ln_kernel<<<M_, 128>>>(op, nullptr, dpln2g, dpln2b, x1, nullptr, nullptr, FD_);
    dp_final_kernel<<<M_ / 8, 256>>>(x1, dppw, dppb, xlen,
                                     out + ((size_t)out_size - (size_t)B_ * S_));
}

// round 5
// speedup vs baseline: 3.6018x; 1.1545x over previous
#include <cuda_runtime.h>
#include <cuda_bf16.h>
#include <math.h>
#include <stdint.h>

#define B_   32
#define S_   512
#define H_   512
#define NH_  8
#define HD_  64
#define F_   2048
#define L_   6
#define OUT_ 80
#define FD_  256
#define M_   (B_*S_)   // 16384 tokens

typedef __nv_bfloat16  bf16;
typedef __nv_bfloat162 bf162;

// ---------------- scratch (static device globals) ----------------
__device__ float g_h   [M_*H_];
__device__ float g_x1  [M_*H_];
__device__ float g_op  [M_*H_];
__device__ float g_cv2 [M_*H_];
__device__ float g_qkv [M_*3*H_];
__device__ bf16  g_hh  [M_*H_],  g_hl  [M_*H_];
__device__ bf16  g_x1h [M_*H_],  g_x1l [M_*H_];
__device__ bf16  g_ah  [M_*H_],  g_al  [M_*H_];
__device__ bf16  g_midh[M_*F_],  g_midl[M_*F_];
__device__ bf16  g_mkh [M_*H_],  g_mkl [M_*H_];
__device__ bf16  g_dpxh[M_*FD_], g_dpxl[M_*FD_];
__device__ bf16  g_wqkvh[L_*3*H_*H_], g_wqkvl[L_*3*H_*H_];
__device__ bf16  g_woh [L_*H_*H_],    g_wol [L_*H_*H_];
__device__ bf16  g_w1h [L_*F_*3*H_],  g_w1l [L_*F_*3*H_];
__device__ bf16  g_w2h [L_*H_*3*F_],  g_w2l [L_*H_*3*F_];
__device__ bf16  g_pjh [OUT_*H_],     g_pjl [OUT_*H_];
__device__ bf16  g_d1h [FD_*3*H_],    g_d1l [FD_*3*H_];
__device__ bf16  g_d2h [FD_*3*FD_],   g_d2l [FD_*3*FD_];
__device__ float g_bqkv[L_*3*H_];
__device__ float2 g_rope[S_*32];

#define FLAG_RELU  1
#define FLAG_MASK  2
#define FLAG_TRANS 4

#define SWZ64(r,c)  ((uint32_t)((r)*64  + ((((c) ^ ((r)&3))) << 4)))
#define SWZ128(r,c) ((uint32_t)((r)*128 + ((((c) ^ ((r)&7))) << 4)))

// ---------------- helpers ----------------
__device__ __forceinline__ void split_hl(float x, bf16& h, bf16& l) {
    h = __float2bfloat16_rn(x);
    l = __float2bfloat16_rn(x - __bfloat162float(h));
}

__device__ __forceinline__ uint32_t packb(bf16 x, bf16 y) {
    return (uint32_t)__bfloat16_as_ushort(x) | ((uint32_t)__bfloat16_as_ushort(y) << 16);
}

__device__ __forceinline__ uint32_t smem_u32(const void* p) {
    uint32_t a;
    asm("{ .reg .u64 t; cvta.to.shared.u64 t, %1; cvt.u32.u64 %0, t; }" : "=r"(a) : "l"(p));
    return a;
}

__device__ __forceinline__ void cpa16(uint32_t dst, const void* src, int sz) {
    asm volatile("cp.async.cg.shared.global [%0], [%1], 16, %2;"
                 :: "r"(dst), "l"(src), "r"(sz));
}

__device__ __forceinline__ void ldsm4(uint32_t* r, uint32_t addr) {
    asm volatile("ldmatrix.sync.aligned.m8n8.x4.shared.b16 {%0,%1,%2,%3}, [%4];"
                 : "=r"(r[0]), "=r"(r[1]), "=r"(r[2]), "=r"(r[3]) : "r"(addr));
}

__device__ __forceinline__ void ldsm4t(uint32_t* r, uint32_t addr) {
    asm volatile("ldmatrix.sync.aligned.m8n8.x4.trans.shared.b16 {%0,%1,%2,%3}, [%4];"
                 : "=r"(r[0]), "=r"(r[1]), "=r"(r[2]), "=r"(r[3]) : "r"(addr));
}

__device__ __forceinline__ void mma16816(float* c, const uint32_t* a,
                                         uint32_t b0, uint32_t b1) {
    asm volatile(
        "mma.sync.aligned.m16n8k16.row.col.f32.bf16.bf16.f32 "
        "{%0,%1,%2,%3}, {%4,%5,%6,%7}, {%8,%9}, {%0,%1,%2,%3};"
        : "+f"(c[0]), "+f"(c[1]), "+f"(c[2]), "+f"(c[3])
        : "r"(a[0]), "r"(a[1]), "r"(a[2]), "r"(a[3]), "r"(b0), "r"(b1));
}

// ---------------- split-bf16 HMMA GEMM, 2-stage cp.async pipeline ----------------
// Tile 64(M) x 128(N), K-chunk 32. Stage = [Ahi 4K|Alo 4K|Bhi 8K|Blo 8K] = 24KB, x2 = 48KB.
__global__ __launch_bounds__(128, 4) void hgemm_kernel(
    const bf16* __restrict__ Ahi, const bf16* __restrict__ Alo,
    const bf16* __restrict__ Whi, const bf16* __restrict__ Wlo,
    const float* __restrict__ bias,
    float* __restrict__ Cf, bf16* __restrict__ Chi, bf16* __restrict__ Clo,
    int N, int cinLog2, int nseg, int pad, int flags,
    const int* __restrict__ lengths)
{
    extern __shared__ __align__(16) char smem[];
    const uint32_t sb = smem_u32(smem);

    int t = threadIdx.x, wid = t >> 5, lane = t & 31;
    int m0 = blockIdx.y * 64, n0 = blockIdx.x * 128;
    int cin  = 1 << cinLog2;
    int Kdim = nseg << cinLog2;
    int nch  = Kdim >> 5;
    int wm = (wid >> 1) * 32, wn = (wid & 1) * 64;

    float acc[2][8][4];
#pragma unroll
    for (int i = 0; i < 2; i++)
#pragma unroll
        for (int j = 0; j < 8; j++)
#pragma unroll
            for (int e = 0; e < 4; e++) acc[i][j][e] = 0.f;

    auto load_chunk = [&](int kc, int stg) {
        uint32_t base = sb + stg * 24576;
        int kk0 = kc << 5;
        int seg = kk0 >> cinLog2;
        int ci0 = kk0 & (cin - 1);
#pragma unroll
        for (int it = 0; it < 2; it++) {
            int idx = t + it * 128;
            int r = idx >> 2, c = idx & 3;
            int m = m0 + r;
            const bf16 *sh = Ahi, *sl = Alo;
            int sz = 16;
            if (nseg == 1) {
                size_t off = (size_t)m * cin + kk0 + c * 8;
                sh += off; sl += off;
            } else {
                int s = m & (S_ - 1);
                int srow = s + seg - pad;
                if (srow >= 0 && srow < S_) {
                    size_t off = (size_t)(m + srow - s) * cin + ci0 + c * 8;
                    sh += off; sl += off;
                } else sz = 0;
            }
            uint32_t d = SWZ64(r, c);
            cpa16(base + d, sh, sz);
            cpa16(base + 4096 + d, sl, sz);
        }
#pragma unroll
        for (int it = 0; it < 4; it++) {
            int idx = t + it * 128;
            int r = idx >> 2, c = idx & 3;
            int n = n0 + r;
            int sz = (n < N) ? 16 : 0;
            size_t off = (n < N) ? ((size_t)n * Kdim + kk0 + c * 8) : 0;
            uint32_t d = SWZ64(r, c);
            cpa16(base + 8192 + d, Whi + off, sz);
            cpa16(base + 16384 + d, Wlo + off, sz);
        }
        asm volatile("cp.async.commit_group;");
    };

    int rsel = lane & 15, chalf = lane >> 4;
    auto compute_chunk = [&](int stg) {
        uint32_t base = sb + stg * 24576;
#pragma unroll
        for (int ks = 0; ks < 2; ks++) {
            int cc = ks * 2 + chalf;
            uint32_t ah[2][4], al[2][4];
#pragma unroll
            for (int i = 0; i < 2; i++) {
                int rr = wm + i * 16 + rsel;
                uint32_t off = SWZ64(rr, cc);
                ldsm4(ah[i], base + off);
                ldsm4(al[i], base + 4096 + off);
            }
#pragma unroll
            for (int jj = 0; jj < 4; jj++) {
                uint32_t bh[4], bl[4];
                int rr = wn + jj * 16 + rsel;
                uint32_t off = SWZ64(rr, cc);
                ldsm4(bh, base + 8192 + off);
                ldsm4(bl, base + 16384 + off);
#pragma unroll
                for (int i = 0; i < 2; i++)
#pragma unroll
                    for (int o = 0; o < 2; o++) {
                        float* a4 = acc[i][jj * 2 + o];
                        mma16816(a4, ah[i], bh[o], bh[o + 2]);
                        mma16816(a4, ah[i], bl[o], bl[o + 2]);
                        mma16816(a4, al[i], bh[o], bh[o + 2]);
                    }
            }
        }
    };

    load_chunk(0, 0);
    for (int kc = 0; kc < nch; kc++) {
        if (kc + 1 < nch) {
            load_chunk(kc + 1, (kc + 1) & 1);
            asm volatile("cp.async.wait_group 1;");
        } else {
            asm volatile("cp.async.wait_group 0;");
        }
        __syncthreads();
        compute_chunk(kc & 1);
        __syncthreads();
    }

    // ---- epilogue ----
    int r0 = lane >> 2, c0 = (lane & 3) * 2;
#pragma unroll
    for (int i = 0; i < 2; i++) {
        int mA = m0 + wm + i * 16 + r0;
        int mB = mA + 8;
        int sA = mA & (S_ - 1), bA = mA >> 9;
        int sB = mB & (S_ - 1), bB = mB >> 9;
        float mvA = 1.f, mvB = 1.f;
        if (flags & FLAG_MASK) {
            mvA = (sA >= lengths[bA]) ? 1.f : 0.f;   // reference's inverted mask
            mvB = (sB >= lengths[bB]) ? 1.f : 0.f;
        }
#pragma unroll
        for (int j = 0; j < 8; j++) {
            int nb = n0 + wn + j * 8 + c0;
            if (nb >= N) continue;
            float b0 = __ldg(bias + nb);
            float b1 = (nb + 1 < N) ? __ldg(bias + nb + 1) : 0.f;
            float v00 = acc[i][j][0] + b0, v01 = acc[i][j][1] + b1;
            float v10 = acc[i][j][2] + b0, v11 = acc[i][j][3] + b1;
            if (flags & FLAG_RELU) {
                v00 = fmaxf(v00, 0.f); v01 = fmaxf(v01, 0.f);
                v10 = fmaxf(v10, 0.f); v11 = fmaxf(v11, 0.f);
            }
            v00 *= mvA; v01 *= mvA; v10 *= mvB; v11 *= mvB;
            if (flags & FLAG_TRANS) {
                Cf[((size_t)bA * N + nb) * S_ + sA] = v00;
                Cf[((size_t)bB * N + nb) * S_ + sB] = v10;
                if (nb + 1 < N) {
                    Cf[((size_t)bA * N + nb + 1) * S_ + sA] = v01;
                    Cf[((size_t)bB * N + nb + 1) * S_ + sB] = v11;
                }
            } else {
                if (Cf) {
                    *(float2*)(Cf + (size_t)mA * N + nb) = make_float2(v00, v01);
                    *(float2*)(Cf + (size_t)mB * N + nb) = make_float2(v10, v11);
                }
                if (Chi) {
                    bf16 h0, l0, h1, l1;
                    split_hl(v00, h0, l0); split_hl(v01, h1, l1);
                    *(bf162*)(Chi + (size_t)mA * N + nb) = bf162(h0, h1);
                    *(bf162*)(Clo + (size_t)mA * N + nb) = bf162(l0, l1);
                    split_hl(v10, h0, l0); split_hl(v11, h1, l1);
                    *(bf162*)(Chi + (size_t)mB * N + nb) = bf162(h0, h1);
                    *(bf162*)(Clo + (size_t)mB * N + nb) = bf162(l0, l1);
                }
            }
        }
    }
}

// ---------------- HMMA flash attention (split-bf16, rope table, tile skipping) ----
// qkv fp32 [m][1536]: q at hh*64, k at 512+hh*64, v at 1024+hh*64.
// Reference quirk: scores KEPT where kpos >= len, -1e9 where kpos < len; len<=511,
// so tiles fully below len contribute p==0 exactly -> skip kt < len>>6.
__global__ __launch_bounds__(128) void attn_kernel(
    const float* __restrict__ qkv, const float2* __restrict__ rt,
    bf16* __restrict__ ohi, bf16* __restrict__ olo,
    const int* __restrict__ lengths)
{
    extern __shared__ __align__(16) char sm[];
    const uint32_t sb = smem_u32(sm);
    const uint32_t QH = 0, QL = 8192, KH = 16384, KL = 24576, VH = 32768, VL = 40960;

    int t = threadIdx.x, wid = t >> 5, lane = t & 31;
    int qt = blockIdx.x, hh = blockIdx.y, b = blockIdx.z;
    int len = lengths[b];

    // ---- Q load + rope + split ----
#pragma unroll
    for (int it = 0; it < 4; it++) {
        int idx = t + it * 128;
        int r = idx >> 3, c = idx & 7;
        int s = qt * 64 + r;
        const float* base = qkv + ((size_t)b * S_ + s) * (3 * H_) + hh * HD_;
        int d0 = c * 8;
        float4 xa = *(const float4*)(base + d0);
        float4 xb = *(const float4*)(base + d0 + 4);
        float4 pa = *(const float4*)(base + (d0 ^ 32));
        float4 pb = *(const float4*)(base + (d0 ^ 32) + 4);
        float xs[8] = {xa.x, xa.y, xa.z, xa.w, xb.x, xb.y, xb.z, xb.w};
        float ps[8] = {pa.x, pa.y, pa.z, pa.w, pb.x, pb.y, pb.z, pb.w};
        float sgn = (d0 < 32) ? -1.f : 1.f;
        const float2* rte = rt + s * 32 + (d0 & 31);
        uint32_t wh[4], wl[4];
#pragma unroll
        for (int e = 0; e < 8; e += 2) {
            float2 cs0 = rte[e], cs1 = rte[e + 1];
            float v0 = xs[e] * cs0.x + sgn * ps[e] * cs0.y;
            float v1 = xs[e + 1] * cs1.x + sgn * ps[e + 1] * cs1.y;
            bf16 h0, l0, h1, l1;
            split_hl(v0, h0, l0); split_hl(v1, h1, l1);
            wh[e >> 1] = packb(h0, h1); wl[e >> 1] = packb(l0, l1);
        }
        uint32_t off = SWZ128(r, c);
        *(uint4*)(sm + QH + off) = make_uint4(wh[0], wh[1], wh[2], wh[3]);
        *(uint4*)(sm + QL + off) = make_uint4(wl[0], wl[1], wl[2], wl[3]);
    }
    __syncthreads();

    int rsel = lane & 15, chalf = lane >> 4;
    uint32_t qh[4][4], ql[4][4];
#pragma unroll
    for (int ks = 0; ks < 4; ks++) {
        int rr = wid * 16 + rsel;
        uint32_t off = SWZ128(rr, ks * 2 + chalf);
        ldsm4(qh[ks], sb + QH + off);
        ldsm4(ql[ks], sb + QL + off);
    }

    float oc[8][4];
#pragma unroll
    for (int dt = 0; dt < 8; dt++)
#pragma unroll
        for (int e = 0; e < 4; e++) oc[dt][e] = 0.f;
    float m0 = -INFINITY, m1 = -INFINITY, ls0 = 0.f, ls1 = 0.f;

    int kt0 = len >> 6;
    if (kt0 > 7) kt0 = 7;

    for (int kt = kt0; kt < 8; kt++) {
        __syncthreads();
        // ---- K (rope) + V load + split ----
#pragma unroll
        for (int it = 0; it < 4; it++) {
            int idx = t + it * 128;
            int r = idx >> 3, c = idx & 7;
            int s = kt * 64 + r;
            const float* base = qkv + ((size_t)b * S_ + s) * (3 * H_) + H_ + hh * HD_;
            int d0 = c * 8;
            float4 xa = *(const float4*)(base + d0);
            float4 xb = *(const float4*)(base + d0 + 4);
            float4 pa = *(const float4*)(base + (d0 ^ 32));
            float4 pb = *(const float4*)(base + (d0 ^ 32) + 4);
            float xs[8] = {xa.x, xa.y, xa.z, xa.w, xb.x, xb.y, xb.z, xb.w};
            float ps[8] = {pa.x, pa.y, pa.z, pa.w, pb.x, pb.y, pb.z, pb.w};
            float sgn = (d0 < 32) ? -1.f : 1.f;
            const float2* rte = rt + s * 32 + (d0 & 31);
            uint32_t wh[4], wl[4];
#pragma unroll
            for (int e = 0; e < 8; e += 2) {
                float2 cs0 = rte[e], cs1 = rte[e + 1];
                float v0 = xs[e] * cs0.x + sgn * ps[e] * cs0.y;
                float v1 = xs[e + 1] * cs1.x + sgn * ps[e + 1] * cs1.y;
                bf16 h0, l0, h1, l1;
                split_hl(v0, h0, l0); split_hl(v1, h1, l1);
                wh[e >> 1] = packb(h0, h1); wl[e >> 1] = packb(l0, l1);
            }
            uint32_t off = SWZ128(r, c);
            *(uint4*)(sm + KH + off) = make_uint4(wh[0], wh[1], wh[2], wh[3]);
            *(uint4*)(sm + KL + off) = make_uint4(wl[0], wl[1], wl[2], wl[3]);
            // V (no rope)
            const float* vbase = base + H_;
            float4 va = *(const float4*)(vbase + d0);
            float4 vb2 = *(const float4*)(vbase + d0 + 4);
            float vs[8] = {va.x, va.y, va.z, va.w, vb2.x, vb2.y, vb2.z, vb2.w};
#pragma unroll
            for (int e = 0; e < 8; e += 2) {
                bf16 h0, l0, h1, l1;
                split_hl(vs[e], h0, l0); split_hl(vs[e + 1], h1, l1);
                wh[e >> 1] = packb(h0, h1); wl[e >> 1] = packb(l0, l1);
            }
            *(uint4*)(sm + VH + off) = make_uint4(wh[0], wh[1], wh[2], wh[3]);
            *(uint4*)(sm + VL + off) = make_uint4(wl[0], wl[1], wl[2], wl[3]);
        }
        __syncthreads();

        // ---- S = Q K^T (3 split passes) ----
        float sv[8][4];
#pragma unroll
        for (int jt = 0; jt < 8; jt++)
#pragma unroll
            for (int e = 0; e < 4; e++) sv[jt][e] = 0.f;
#pragma unroll
        for (int ks = 0; ks < 4; ks++) {
#pragma unroll
            for (int jj = 0; jj < 4; jj++) {
                uint32_t bh[4], bl[4];
                int rr = jj * 16 + rsel;
                uint32_t off = SWZ128(rr, ks * 2 + chalf);
                ldsm4(bh, sb + KH + off);
                ldsm4(bl, sb + KL + off);
#pragma unroll
                for (int o = 0; o < 2; o++) {
                    float* a4 = sv[jj * 2 + o];
                    mma16816(a4, qh[ks], bh[o], bh[o + 2]);
                    mma16816(a4, qh[ks], bl[o], bl[o + 2]);
                    mma16816(a4, ql[ks], bh[o], bh[o + 2]);
                }
            }
        }

        // ---- scale + inverted mask + online softmax ----
        int colb = kt * 64 + (lane & 3) * 2;
        float rm0 = -INFINITY, rm1 = -INFINITY;
#pragma unroll
        for (int jt = 0; jt < 8; jt++) {
#pragma unroll
            for (int e = 0; e < 2; e++) {
                int kp = colb + jt * 8 + e;
                bool keep = (kp >= len);
                float v0 = sv[jt][e] * 0.125f;
                float v1 = sv[jt][2 + e] * 0.125f;
                sv[jt][e]     = keep ? v0 : -1e9f;
                sv[jt][2 + e] = keep ? v1 : -1e9f;
                rm0 = fmaxf(rm0, sv[jt][e]);
                rm1 = fmaxf(rm1, sv[jt][2 + e]);
            }
        }
        rm0 = fmaxf(rm0, __shfl_xor_sync(0xffffffffu, rm0, 1));
        rm0 = fmaxf(rm0, __shfl_xor_sync(0xffffffffu, rm0, 2));
        rm1 = fmaxf(rm1, __shfl_xor_sync(0xffffffffu, rm1, 1));
        rm1 = fmaxf(rm1, __shfl_xor_sync(0xffffffffu, rm1, 2));
        float mn0 = fmaxf(m0, rm0), mn1 = fmaxf(m1, rm1);
        float a0 = __expf(m0 - mn0), a1 = __expf(m1 - mn1);
        m0 = mn0; m1 = mn1;
        float s0 = 0.f, s1 = 0.f;
#pragma unroll
        for (int jt = 0; jt < 8; jt++) {
            sv[jt][0] = __expf(sv[jt][0] - mn0);
            sv[jt][1] = __expf(sv[jt][1] - mn0);
            sv[jt][2] = __expf(sv[jt][2] - mn1);
            sv[jt][3] = __expf(sv[jt][3] - mn1);
            s0 += sv[jt][0] + sv[jt][1];
            s1 += sv[jt][2] + sv[jt][3];
        }
        s0 += __shfl_xor_sync(0xffffffffu, s0, 1);
        s0 += __shfl_xor_sync(0xffffffffu, s0, 2);
        s1 += __shfl_xor_sync(0xffffffffu, s1, 1);
        s1 += __shfl_xor_sync(0xffffffffu, s1, 2);
        ls0 = ls0 * a0 + s0;
        ls1 = ls1 * a1 + s1;
#pragma unroll
        for (int dt = 0; dt < 8; dt++) {
            oc[dt][0] *= a0; oc[dt][1] *= a0;
            oc[dt][2] *= a1; oc[dt][3] *= a1;
        }

        // ---- O += P V (P split hi/lo, register C->A fragment conversion) ----
#pragma unroll
        for (int jp = 0; jp < 4; jp++) {
            uint32_t pah[4], pal[4];
#pragma unroll
            for (int half = 0; half < 2; half++) {
                bf16 h0, lo0, h1, lo1, h2, lo2, h3, lo3;
                split_hl(sv[2 * jp + half][0], h0, lo0);
                split_hl(sv[2 * jp + half][1], h1, lo1);
                split_hl(sv[2 * jp + half][2], h2, lo2);
                split_hl(sv[2 * jp + half][3], h3, lo3);
                pah[2 * half + 0] = packb(h0, h1);  pal[2 * half + 0] = packb(lo0, lo1);
                pah[2 * half + 1] = packb(h2, h3);  pal[2 * half + 1] = packb(lo2, lo3);
            }
            int vrow = jp * 16 + ((lane >> 3) & 1) * 8 + (lane & 7);
#pragma unroll
            for (int g = 0; g < 4; g++) {
                int cch = 2 * g + (lane >> 4);
                uint32_t off = SWZ128(vrow, cch);
                uint32_t vh[4], vl[4];
                ldsm4t(vh, sb + VH + off);
                ldsm4t(vl, sb + VL + off);
                mma16816(oc[2 * g],     pah, vh[0], vh[1]);
                mma16816(oc[2 * g + 1], pah, vh[2], vh[3]);
                mma16816(oc[2 * g],     pah, vl[0], vl[1]);
                mma16816(oc[2 * g + 1], pah, vl[2], vl[3]);
                mma16816(oc[2 * g],     pal, vh[0], vh[1]);
                mma16816(oc[2 * g + 1], pal, vh[2], vh[3]);
            }
        }
    }

    // ---- epilogue ----
    float i0 = 1.f / ls0, i1 = 1.f / ls1;
    int r0 = qt * 64 + wid * 16 + (lane >> 2);
#pragma unroll
    for (int dt = 0; dt < 8; dt++) {
        int d = hh * HD_ + dt * 8 + (lane & 3) * 2;
        size_t o0 = ((size_t)b * S_ + r0) * H_ + d;
        size_t o1 = o0 + (size_t)8 * H_;
        bf16 h0, lo0, h1, lo1;
        split_hl(oc[dt][0] * i0, h0, lo0);
        split_hl(oc[dt][1] * i0, h1, lo1);
        *(bf162*)(ohi + o0) = bf162(h0, h1);
        *(bf162*)(olo + o0) = bf162(lo0, lo1);
        split_hl(oc[dt][2] * i1, h0, lo0);
        split_hl(oc[dt][3] * i1, h1, lo1);
        *(bf162*)(ohi + o1) = bf162(h0, h1);
        *(bf162*)(olo + o1) = bf162(lo0, lo1);
    }
}

// ---------------- LayerNorm (residual add + optional split outputs) ----------------
__global__ __launch_bounds__(128) void ln_kernel(
    const float* __restrict__ x, const float* __restrict__ res,
    const float* __restrict__ g, const float* __restrict__ be,
    float* __restrict__ out, bf16* __restrict__ ohi, bf16* __restrict__ olo, int C)
{
    int m = blockIdx.x, t = threadIdx.x;
    int nv = C >> 2;
    float4 v = make_float4(0.f, 0.f, 0.f, 0.f);
    if (t < nv) {
        v = ((const float4*)(x + (size_t)m * C))[t];
        if (res) {
            float4 w = ((const float4*)(res + (size_t)m * C))[t];
            v.x += w.x; v.y += w.y; v.z += w.z; v.w += w.w;
        }
    }
    float sum = v.x + v.y + v.z + v.w;
    float sq  = v.x * v.x + v.y * v.y + v.z * v.z + v.w * v.w;
#pragma unroll
    for (int off = 16; off; off >>= 1) {
        sum += __shfl_xor_sync(0xffffffffu, sum, off);
        sq  += __shfl_xor_sync(0xffffffffu, sq,  off);
    }
    __shared__ float s1[4], s2[4];
    if ((t & 31) == 0) { s1[t >> 5] = sum; s2[t >> 5] = sq; }
    __syncthreads();
    sum = s1[0] + s1[1] + s1[2] + s1[3];
    sq  = s2[0] + s2[1] + s2[2] + s2[3];
    float mean = sum / C;
    float var  = sq / C - mean * mean;
    float inv  = rsqrtf(var + 1e-5f);
    if (t < nv) {
        float4 gv = ((const float4*)g)[t];
        float4 bv = ((const float4*)be)[t];
        float4 o4;
        o4.x = (v.x - mean) * inv * gv.x + bv.x;
        o4.y = (v.y - mean) * inv * gv.y + bv.y;
        o4.z = (v.z - mean) * inv * gv.z + bv.z;
        o4.w = (v.w - mean) * inv * gv.w + bv.w;
        if (out) ((float4*)(out + (size_t)m * C))[t] = o4;
        if (ohi) {
            bf16 h0, l0, h1, l1, h2, l2, h3, l3;
            split_hl(o4.x, h0, l0); split_hl(o4.y, h1, l1);
            split_hl(o4.z, h2, l2); split_hl(o4.w, h3, l3);
            *(bf162*)(ohi + (size_t)m * C + t * 4)     = bf162(h0, h1);
            *(bf162*)(ohi + (size_t)m * C + t * 4 + 2) = bf162(h2, h3);
            *(bf162*)(olo + (size_t)m * C + t * 4)     = bf162(l0, l1);
            *(bf162*)(olo + (size_t)m * C + t * 4 + 2) = bf162(l2, l3);
        }
    }
}

// ---------------- small kernels ----------------
__global__ __launch_bounds__(256) void embed_kernel(
    const int* __restrict__ x, const float* __restrict__ emb,
    float* __restrict__ h, bf16* __restrict__ hh, bf16* __restrict__ hl)
{
    int idx = blockIdx.x * blockDim.x + threadIdx.x;
    if (idx >= M_ * (H_ / 4)) return;
    int m = idx >> 7, c4 = idx & 127;
    int tok = x[m];
    float4 e = ((const float4*)(emb + (size_t)tok * H_))[c4];
    const float sc = 22.62741699796952f;  // sqrt(512)
    e.x *= sc; e.y *= sc; e.z *= sc; e.w *= sc;
    ((float4*)(h + (size_t)m * H_))[c4] = e;
    bf16 h0, l0, h1, l1, h2, l2, h3, l3;
    split_hl(e.x, h0, l0); split_hl(e.y, h1, l1);
    split_hl(e.z, h2, l2); split_hl(e.w, h3, l3);
    *(bf162*)(hh + (size_t)m * H_ + c4 * 4)     = bf162(h0, h1);
    *(bf162*)(hh + (size_t)m * H_ + c4 * 4 + 2) = bf162(h2, h3);
    *(bf162*)(hl + (size_t)m * H_ + c4 * 4)     = bf162(l0, l1);
    *(bf162*)(hl + (size_t)m * H_ + c4 * 4 + 2) = bf162(l2, l3);
}

__global__ __launch_bounds__(256) void maskmul_kernel(
    const float* __restrict__ in, bf16* __restrict__ ohi, bf16* __restrict__ olo,
    const int* __restrict__ lengths)
{
    int idx = blockIdx.x * blockDim.x + threadIdx.x;
    if (idx >= M_ * H_) return;
    int m = idx >> 9;
    int s = m & (S_ - 1), b = m >> 9;
    float v = in[idx] * ((s >= lengths[b]) ? 1.f : 0.f);  // inverted mask
    bf16 h, l;
    split_hl(v, h, l);
    ohi[idx] = h; olo[idx] = l;
}

#define NW1 (L_*F_*H_*3)
#define NW2 (L_*H_*F_*3)
#define ND1 (FD_*H_*3)
#define ND2 (FD_*FD_*3)
__global__ __launch_bounds__(256) void prep_conv_kernel(
    const float* __restrict__ c1w, const float* __restrict__ c2w,
    const float* __restrict__ d1w, const float* __restrict__ d2w)
{
    int idx = blockIdx.x * blockDim.x + threadIdx.x;
    const float* src; bf16 *dh, *dl; int CI; int base;
    if (idx < NW1)                        { src = c1w; dh = g_w1h; dl = g_w1l; CI = H_;  base = idx; }
    else if (idx < NW1 + NW2)             { src = c2w; dh = g_w2h; dl = g_w2l; CI = F_;  base = idx - NW1; }
    else if (idx < NW1 + NW2 + ND1)       { src = d1w; dh = g_d1h; dl = g_d1l; CI = H_;  base = idx - NW1 - NW2; }
    else if (idx < NW1 + NW2 + ND1 + ND2) { src = d2w; dh = g_d2h; dl = g_d2l; CI = FD_; base = idx - NW1 - NW2 - ND1; }
    else return;
    int kk = base % 3;
    int rest = base / 3;
    int ci = rest % CI;
    int co = rest / CI;
    float v = src[base];
    bf16 h, l; split_hl(v, h, l);
    size_t o = (size_t)co * (3 * CI) + kk * CI + ci;
    dh[o] = h; dl[o] = l;
}

#define NQKV (L_*3*H_*H_)
#define NWO  (L_*H_*H_)
#define NPJ  (OUT_*H_)
#define NBQ  (L_*3*H_)
#define NRT  (S_*32)
__global__ __launch_bounds__(256) void prep_lin_kernel(
    const float* __restrict__ Wq, const float* __restrict__ Wk,
    const float* __restrict__ Wv, const float* __restrict__ Wo,
    const float* __restrict__ pj,
    const float* __restrict__ bq, const float* __restrict__ bk,
    const float* __restrict__ bv)
{
    int idx = blockIdx.x * blockDim.x + threadIdx.x;
    if (idx < NQKV) {
        int e = idx % H_;
        int n = (idx / H_) % (3 * H_);
        int l = idx / (3 * H_ * H_);
        const float* W = (n < H_) ? Wq : (n < 2 * H_) ? Wk : Wv;
        int nn = n & (H_ - 1);
        float v = W[(size_t)l * H_ * H_ + (size_t)nn * H_ + e];
        bf16 h, lo; split_hl(v, h, lo);
        g_wqkvh[idx] = h; g_wqkvl[idx] = lo;
        return;
    }
    int i2 = idx - NQKV;
    if (i2 < NWO) {
        float v = Wo[i2];
        bf16 h, lo; split_hl(v, h, lo);
        g_woh[i2] = h; g_wol[i2] = lo;
        return;
    }
    int i3 = i2 - NWO;
    if (i3 < NPJ) {
        float v = pj[i3];
        bf16 h, lo; split_hl(v, h, lo);
        g_pjh[i3] = h; g_pjl[i3] = lo;
        return;
    }
    int i4 = i3 - NPJ;
    if (i4 < NBQ) {
        int n = i4 % (3 * H_);
        int l = i4 / (3 * H_);
        const float* bb = (n < H_) ? bq : (n < 2 * H_) ? bk : bv;
        g_bqkv[i4] = bb[l * H_ + (n & (H_ - 1))];
        return;
    }
    int i5 = i4 - NBQ;
    if (i5 < NRT) {
        int s = i5 >> 5, j = i5 & 31;
        float th = expf(-(float)j * 0.28782313662425574f);
        float sn, cs;
        sincosf((float)s * th, &sn, &cs);
        g_rope[i5] = make_float2(cs, sn);
    }
}

__global__ __launch_bounds__(256) void dp_final_kernel(
    const float* __restrict__ x, const float* __restrict__ w,
    const float* __restrict__ pb, const int* __restrict__ lengths,
    float* __restrict__ out)
{
    int warp = threadIdx.x >> 5, lane = threadIdx.x & 31;
    int m = blockIdx.x * 8 + warp;
    if (m >= M_) return;
    const float* xr = x + (size_t)m * FD_;
    float s = 0.f;
    for (int c = lane; c < FD_; c += 32) s += xr[c] * w[c];
#pragma unroll
    for (int off = 16; off; off >>= 1) s += __shfl_xor_sync(0xffffffffu, s, off);
    if (lane == 0) {
        int b = m >> 9, sp = m & (S_ - 1);
        float mv = (sp >= lengths[b]) ? 1.f : 0.f;
        float val = (s + pb[0]) * mv;
        out[(size_t)b * S_ + sp] = ceilf(expf(val));
    }
}

// ---------------- orchestration ----------------
extern "C" void kernel_launch(void* const* d_in, const int* in_sizes, int n_in,
                              void* d_out, int out_size)
{
    const int*   x      = (const int*)  d_in[0];
    const int*   xlen   = (const int*)  d_in[1];
    const float* emb    = (const float*)d_in[2];
    const float* Wq     = (const float*)d_in[3];
    const float* bq     = (const float*)d_in[4];
    const float* Wk     = (const float*)d_in[5];
    const float* bk     = (const float*)d_in[6];
    const float* Wv     = (const float*)d_in[7];
    const float* bv     = (const float*)d_in[8];
    const float* Wo     = (const float*)d_in[9];
    const float* bo     = (const float*)d_in[10];
    const float* c1w    = (const float*)d_in[11];
    const float* c1b    = (const float*)d_in[12];
    const float* c2w    = (const float*)d_in[13];
    const float* c2b    = (const float*)d_in[14];
    const float* ln1g   = (const float*)d_in[15];
    const float* ln1b   = (const float*)d_in[16];
    const float* ln2g   = (const float*)d_in[17];
    const float* ln2b   = (const float*)d_in[18];
    const float* projw  = (const float*)d_in[19];
    const float* projb  = (const float*)d_in[20];
    const float* dpc1w  = (const float*)d_in[21];
    const float* dpc1b  = (const float*)d_in[22];
    const float* dpln1g = (const float*)d_in[23];
    const float* dpln1b = (const float*)d_in[24];
    const float* dpc2w  = (const float*)d_in[25];
    const float* dpc2b  = (const float*)d_in[26];
    const float* dpln2g = (const float*)d_in[27];
    const float* dpln2b = (const float*)d_in[28];
    const float* dppw   = (const float*)d_in[29];
    const float* dppb   = (const float*)d_in[30];
    float* out = (float*)d_out;

    float *h, *x1, *op, *cv2, *qkv, *bqkv;
    float2* rtab;
    bf16 *hh, *hl, *x1h, *x1l, *ah, *al, *midh, *midl, *mkh, *mkl, *dpxh, *dpxl;
    bf16 *wqh, *wql, *woh, *wol, *w1h, *w1l, *w2h, *w2l, *pjh, *pjl, *d1h, *d1l, *d2h, *d2l;
    cudaGetSymbolAddress((void**)&h,    g_h);
    cudaGetSymbolAddress((void**)&x1,   g_x1);
    cudaGetSymbolAddress((void**)&op,   g_op);
    cudaGetSymbolAddress((void**)&cv2,  g_cv2);
    cudaGetSymbolAddress((void**)&qkv,  g_qkv);
    cudaGetSymbolAddress((void**)&rtab, g_rope);
    cudaGetSymbolAddress((void**)&hh,   g_hh);
    cudaGetSymbolAddress((void**)&hl,   g_hl);
    cudaGetSymbolAddress((void**)&x1h,  g_x1h);
    cudaGetSymbolAddress((void**)&x1l,  g_x1l);
    cudaGetSymbolAddress((void**)&ah,   g_ah);
    cudaGetSymbolAddress((void**)&al,   g_al);
    cudaGetSymbolAddress((void**)&midh, g_midh);
    cudaGetSymbolAddress((void**)&midl, g_midl);
    cudaGetSymbolAddress((void**)&mkh,  g_mkh);
    cudaGetSymbolAddress((void**)&mkl,  g_mkl);
    cudaGetSymbolAddress((void**)&dpxh, g_dpxh);
    cudaGetSymbolAddress((void**)&dpxl, g_dpxl);
    cudaGetSymbolAddress((void**)&wqh,  g_wqkvh);
    cudaGetSymbolAddress((void**)&wql,  g_wqkvl);
    cudaGetSymbolAddress((void**)&woh,  g_woh);
    cudaGetSymbolAddress((void**)&wol,  g_wol);
    cudaGetSymbolAddress((void**)&w1h,  g_w1h);
    cudaGetSymbolAddress((void**)&w1l,  g_w1l);
    cudaGetSymbolAddress((void**)&w2h,  g_w2h);
    cudaGetSymbolAddress((void**)&w2l,  g_w2l);
    cudaGetSymbolAddress((void**)&pjh,  g_pjh);
    cudaGetSymbolAddress((void**)&pjl,  g_pjl);
    cudaGetSymbolAddress((void**)&d1h,  g_d1h);
    cudaGetSymbolAddress((void**)&d1l,  g_d1l);
    cudaGetSymbolAddress((void**)&d2h,  g_d2h);
    cudaGetSymbolAddress((void**)&d2l,  g_d2l);
    cudaGetSymbolAddress((void**)&bqkv, g_bqkv);

    cudaFuncSetAttribute((const void*)attn_kernel,
                         cudaFuncAttributeMaxDynamicSharedMemorySize, 49152);
    cudaFuncSetAttribute((const void*)hgemm_kernel,
                         cudaFuncAttributeMaxDynamicSharedMemorySize, 49152);

    // #1, #2: weight prep (+rope table); #3: embed; #4 qkv; #5 attn; #6 o-proj (ncu)
    {
        int tot = NW1 + NW2 + ND1 + ND2;
        prep_conv_kernel<<<(tot + 255) / 256, 256>>>(c1w, c2w, dpc1w, dpc2w);
        tot = NQKV + NWO + NPJ + NBQ + NRT;
        prep_lin_kernel<<<(tot + 255) / 256, 256>>>(Wq, Wk, Wv, Wo, projw, bq, bk, bv);
    }
    embed_kernel<<<M_ * (H_ / 4) / 256, 256>>>(x, emb, h, hh, hl);

    const int SM_G = 49152;
    dim3 gQKV(3 * H_ / 128, M_ / 64);   // (12,256)
    dim3 gH(H_ / 128, M_ / 64);         // (4,256)
    dim3 gF(F_ / 128, M_ / 64);         // (16,256)
    dim3 gMu(1, M_ / 64);
    dim3 gDp(FD_ / 128, M_ / 64);       // (2,256)
    dim3 ga(S_ / 64, NH_, B_);

    for (int l = 0; l < L_; l++) {
        size_t wOff = (size_t)l * H_ * H_;
        size_t wqOff = (size_t)l * 3 * H_ * H_;
        hgemm_kernel<<<gQKV, 128, SM_G>>>(hh, hl, wqh + wqOff, wql + wqOff,
                                          bqkv + l * 3 * H_, qkv, nullptr, nullptr,
                                          3 * H_, 9, 1, 0, 0, xlen);
        attn_kernel<<<ga, 128, SM_G>>>(qkv, rtab, ah, al, xlen);
        hgemm_kernel<<<gH, 128, SM_G>>>(ah, al, woh + wOff, wol + wOff,
                                        bo + l * H_, op, nullptr, nullptr,
                                        H_, 9, 1, 0, 0, xlen);
        ln_kernel<<<M_, 128>>>(op, h, ln1g + l * H_, ln1b + l * H_, x1, x1h, x1l, H_);
        hgemm_kernel<<<gF, 128, SM_G>>>(x1h, x1l,
                                        w1h + (size_t)l * F_ * 3 * H_, w1l + (size_t)l * F_ * 3 * H_,
                                        c1b + l * F_, nullptr, midh, midl,
                                        F_, 9, 3, 1, FLAG_RELU, xlen);
        hgemm_kernel<<<gH, 128, SM_G>>>(midh, midl,
                                        w2h + (size_t)l * H_ * 3 * F_, w2l + (size_t)l * H_ * 3 * F_,
                                        c2b + l * H_, cv2, nullptr, nullptr,
                                        H_, 11, 3, 1, 0, xlen);
        ln_kernel<<<M_, 128>>>(cv2, x1, ln2g + l * H_, ln2b + l * H_, h, hh, hl, H_);
    }

    // mu = pointwise conv (transposed store to (B,OUT,S))
    hgemm_kernel<<<gMu, 128, SM_G>>>(hh, hl, pjh, pjl, projb, out, nullptr, nullptr,
                                     OUT_, 9, 1, 0, FLAG_TRANS, xlen);

    // duration predictor
    maskmul_kernel<<<M_ * H_ / 256, 256>>>(h, mkh, mkl, xlen);
    hgemm_kernel<<<gDp, 128, SM_G>>>(mkh, mkl, d1h, d1l, dpc1b, op, nullptr, nullptr,
                                     FD_, 9, 3, 1, FLAG_RELU | FLAG_MASK, xlen);
    ln_kernel<<<M_, 128>>>(op, nullptr, dpln1g, dpln1b, cv2, dpxh, dpxl, FD_);
    hgemm_kernel<<<gDp, 128, SM_G>>>(dpxh, dpxl, d2h, d2l, dpc2b, op, nullptr, nullptr,
                                     FD_, 8, 3, 1, FLAG_RELU | FLAG_MASK, xlen);
    ln_kernel<<<M_, 128>>>(op, nullptr, dpln2g, dpln2b, x1, nullptr, nullptr, FD_);
    dp_final_kernel<<<M_ / 8, 256>>>(x1, dppw, dppb, xlen,
                                     out + ((size_t)out_size - (size_t)B_ * S_));
}

// round 6
// speedup vs baseline: 3.6030x; 1.0003x over previous
#include <cuda_runtime.h>
#include <cuda_bf16.h>
#include <math.h>
#include <stdint.h>

#define B_   32
#define S_   512
#define H_   512
#define NH_  8
#define HD_  64
#define F_   2048
#define L_   6
#define OUT_ 80
#define FD_  256
#define M_   (B_*S_)   // 16384 tokens

typedef __nv_bfloat16  bf16;
typedef __nv_bfloat162 bf162;

// ---------------- scratch (static device globals) ----------------
__device__ float g_h   [M_*H_];
__device__ float g_x1  [M_*H_];
__device__ float g_op  [M_*H_];
__device__ float g_cv2 [M_*H_];
__device__ float g_qkv [M_*3*H_];
__device__ bf16  g_hh  [M_*H_],  g_hl  [M_*H_];
__device__ bf16  g_x1h [M_*H_],  g_x1l [M_*H_];
__device__ bf16  g_ah  [M_*H_],  g_al  [M_*H_];
__device__ bf16  g_midh[M_*F_],  g_midl[M_*F_];
__device__ bf16  g_mkh [M_*H_],  g_mkl [M_*H_];
__device__ bf16  g_dpxh[M_*FD_], g_dpxl[M_*FD_];
__device__ bf16  g_wqkvh[L_*3*H_*H_], g_wqkvl[L_*3*H_*H_];
__device__ bf16  g_woh [L_*H_*H_],    g_wol [L_*H_*H_];
__device__ bf16  g_w1h [L_*F_*3*H_],  g_w1l [L_*F_*3*H_];
__device__ bf16  g_w2h [L_*H_*3*F_],  g_w2l [L_*H_*3*F_];
__device__ bf16  g_pjh [OUT_*H_],     g_pjl [OUT_*H_];
__device__ bf16  g_d1h [FD_*3*H_],    g_d1l [FD_*3*H_];
__device__ bf16  g_d2h [FD_*3*FD_],   g_d2l [FD_*3*FD_];
__device__ float g_bqkv[L_*3*H_];
__device__ float2 g_rope[S_*32];

#define FLAG_RELU  1
#define FLAG_MASK  2
#define FLAG_TRANS 4

#define SWZ64(r,c)  ((uint32_t)((r)*64  + ((((c) ^ ((r)&3))) << 4)))
#define SWZ128(r,c) ((uint32_t)((r)*128 + ((((c) ^ ((r)&7))) << 4)))

// ---------------- helpers ----------------
__device__ __forceinline__ void split_hl(float x, bf16& h, bf16& l) {
    h = __float2bfloat16_rn(x);
    l = __float2bfloat16_rn(x - __bfloat162float(h));
}

__device__ __forceinline__ uint32_t packb(bf16 x, bf16 y) {
    return (uint32_t)__bfloat16_as_ushort(x) | ((uint32_t)__bfloat16_as_ushort(y) << 16);
}

__device__ __forceinline__ uint32_t smem_u32(const void* p) {
    uint32_t a;
    asm("{ .reg .u64 t; cvta.to.shared.u64 t, %1; cvt.u32.u64 %0, t; }" : "=r"(a) : "l"(p));
    return a;
}

__device__ __forceinline__ void cpa16(uint32_t dst, const void* src, int sz) {
    asm volatile("cp.async.cg.shared.global [%0], [%1], 16, %2;"
                 :: "r"(dst), "l"(src), "r"(sz));
}

__device__ __forceinline__ void ldsm4(uint32_t* r, uint32_t addr) {
    asm volatile("ldmatrix.sync.aligned.m8n8.x4.shared.b16 {%0,%1,%2,%3}, [%4];"
                 : "=r"(r[0]), "=r"(r[1]), "=r"(r[2]), "=r"(r[3]) : "r"(addr));
}

__device__ __forceinline__ void ldsm4t(uint32_t* r, uint32_t addr) {
    asm volatile("ldmatrix.sync.aligned.m8n8.x4.trans.shared.b16 {%0,%1,%2,%3}, [%4];"
                 : "=r"(r[0]), "=r"(r[1]), "=r"(r[2]), "=r"(r[3]) : "r"(addr));
}

__device__ __forceinline__ void mma16816(float* c, const uint32_t* a,
                                         uint32_t b0, uint32_t b1) {
    asm volatile(
        "mma.sync.aligned.m16n8k16.row.col.f32.bf16.bf16.f32 "
        "{%0,%1,%2,%3}, {%4,%5,%6,%7}, {%8,%9}, {%0,%1,%2,%3};"
        : "+f"(c[0]), "+f"(c[1]), "+f"(c[2]), "+f"(c[3])
        : "r"(a[0]), "r"(a[1]), "r"(a[2]), "r"(a[3]), "r"(b0), "r"(b1));
}

// ---------------- split-bf16 HMMA GEMM, 2-stage cp.async pipeline ----------------
// Tile 64(M) x 128(N), K-chunk 32. Stage = [Ahi 4K|Alo 4K|Bhi 8K|Blo 8K] = 24KB, x2.
// MMAs ordered pass-major per jj block: same-accumulator reuse distance 4.
__global__ __launch_bounds__(128, 4) void hgemm_kernel(
    const bf16* __restrict__ Ahi, const bf16* __restrict__ Alo,
    const bf16* __restrict__ Whi, const bf16* __restrict__ Wlo,
    const float* __restrict__ bias,
    float* __restrict__ Cf, bf16* __restrict__ Chi, bf16* __restrict__ Clo,
    int N, int cinLog2, int nseg, int pad, int flags,
    const int* __restrict__ lengths)
{
    extern __shared__ __align__(16) char smem[];
    const uint32_t sb = smem_u32(smem);

    int t = threadIdx.x, wid = t >> 5, lane = t & 31;
    int m0 = blockIdx.y * 64, n0 = blockIdx.x * 128;
    int cin  = 1 << cinLog2;
    int Kdim = nseg << cinLog2;
    int nch  = Kdim >> 5;
    int wm = (wid >> 1) * 32, wn = (wid & 1) * 64;

    float acc[2][8][4];
#pragma unroll
    for (int i = 0; i < 2; i++)
#pragma unroll
        for (int j = 0; j < 8; j++)
#pragma unroll
            for (int e = 0; e < 4; e++) acc[i][j][e] = 0.f;

    auto load_chunk = [&](int kc, int stg) {
        uint32_t base = sb + stg * 24576;
        int kk0 = kc << 5;
        int seg = kk0 >> cinLog2;
        int ci0 = kk0 & (cin - 1);
#pragma unroll
        for (int it = 0; it < 2; it++) {
            int idx = t + it * 128;
            int r = idx >> 2, c = idx & 3;
            int m = m0 + r;
            const bf16 *sh = Ahi, *sl = Alo;
            int sz = 16;
            if (nseg == 1) {
                size_t off = (size_t)m * cin + kk0 + c * 8;
                sh += off; sl += off;
            } else {
                int s = m & (S_ - 1);
                int srow = s + seg - pad;
                if (srow >= 0 && srow < S_) {
                    size_t off = (size_t)(m + srow - s) * cin + ci0 + c * 8;
                    sh += off; sl += off;
                } else sz = 0;
            }
            uint32_t d = SWZ64(r, c);
            cpa16(base + d, sh, sz);
            cpa16(base + 4096 + d, sl, sz);
        }
#pragma unroll
        for (int it = 0; it < 4; it++) {
            int idx = t + it * 128;
            int r = idx >> 2, c = idx & 3;
            int n = n0 + r;
            int sz = (n < N) ? 16 : 0;
            size_t off = (n < N) ? ((size_t)n * Kdim + kk0 + c * 8) : 0;
            uint32_t d = SWZ64(r, c);
            cpa16(base + 8192 + d, Whi + off, sz);
            cpa16(base + 16384 + d, Wlo + off, sz);
        }
        asm volatile("cp.async.commit_group;");
    };

    int rsel = lane & 15, chalf = lane >> 4;
    auto compute_chunk = [&](int stg) {
        uint32_t base = sb + stg * 24576;
#pragma unroll
        for (int ks = 0; ks < 2; ks++) {
            int cc = ks * 2 + chalf;
            uint32_t ah[2][4], al[2][4];
#pragma unroll
            for (int i = 0; i < 2; i++) {
                int rr = wm + i * 16 + rsel;
                uint32_t off = SWZ64(rr, cc);
                ldsm4(ah[i], base + off);
                ldsm4(al[i], base + 4096 + off);
            }
#pragma unroll
            for (int jj = 0; jj < 4; jj++) {
                uint32_t bh[4], bl[4];
                int rr = wn + jj * 16 + rsel;
                uint32_t off = SWZ64(rr, cc);
                ldsm4(bh, base + 8192 + off);
                ldsm4(bl, base + 16384 + off);
                // pass-major: 4 independent accs between same-acc reuses
                mma16816(acc[0][jj * 2 + 0], ah[0], bh[0], bh[2]);
                mma16816(acc[0][jj * 2 + 1], ah[0], bh[1], bh[3]);
                mma16816(acc[1][jj * 2 + 0], ah[1], bh[0], bh[2]);
                mma16816(acc[1][jj * 2 + 1], ah[1], bh[1], bh[3]);
                mma16816(acc[0][jj * 2 + 0], ah[0], bl[0], bl[2]);
                mma16816(acc[0][jj * 2 + 1], ah[0], bl[1], bl[3]);
                mma16816(acc[1][jj * 2 + 0], ah[1], bl[0], bl[2]);
                mma16816(acc[1][jj * 2 + 1], ah[1], bl[1], bl[3]);
                mma16816(acc[0][jj * 2 + 0], al[0], bh[0], bh[2]);
                mma16816(acc[0][jj * 2 + 1], al[0], bh[1], bh[3]);
                mma16816(acc[1][jj * 2 + 0], al[1], bh[0], bh[2]);
                mma16816(acc[1][jj * 2 + 1], al[1], bh[1], bh[3]);
            }
        }
    };

    load_chunk(0, 0);
    for (int kc = 0; kc < nch; kc++) {
        if (kc + 1 < nch) {
            load_chunk(kc + 1, (kc + 1) & 1);
            asm volatile("cp.async.wait_group 1;");
        } else {
            asm volatile("cp.async.wait_group 0;");
        }
        __syncthreads();
        compute_chunk(kc & 1);
        __syncthreads();
    }

    // ---- epilogue ----
    int r0 = lane >> 2, c0 = (lane & 3) * 2;
#pragma unroll
    for (int i = 0; i < 2; i++) {
        int mA = m0 + wm + i * 16 + r0;
        int mB = mA + 8;
        int sA = mA & (S_ - 1), bA = mA >> 9;
        int sB = mB & (S_ - 1), bB = mB >> 9;
        float mvA = 1.f, mvB = 1.f;
        if (flags & FLAG_MASK) {
            mvA = (sA >= lengths[bA]) ? 1.f : 0.f;   // reference's inverted mask
            mvB = (sB >= lengths[bB]) ? 1.f : 0.f;
        }
#pragma unroll
        for (int j = 0; j < 8; j++) {
            int nb = n0 + wn + j * 8 + c0;
            if (nb >= N) continue;
            float b0 = __ldg(bias + nb);
            float b1 = (nb + 1 < N) ? __ldg(bias + nb + 1) : 0.f;
            float v00 = acc[i][j][0] + b0, v01 = acc[i][j][1] + b1;
            float v10 = acc[i][j][2] + b0, v11 = acc[i][j][3] + b1;
            if (flags & FLAG_RELU) {
                v00 = fmaxf(v00, 0.f); v01 = fmaxf(v01, 0.f);
                v10 = fmaxf(v10, 0.f); v11 = fmaxf(v11, 0.f);
            }
            v00 *= mvA; v01 *= mvA; v10 *= mvB; v11 *= mvB;
            if (flags & FLAG_TRANS) {
                Cf[((size_t)bA * N + nb) * S_ + sA] = v00;
                Cf[((size_t)bB * N + nb) * S_ + sB] = v10;
                if (nb + 1 < N) {
                    Cf[((size_t)bA * N + nb + 1) * S_ + sA] = v01;
                    Cf[((size_t)bB * N + nb + 1) * S_ + sB] = v11;
                }
            } else {
                if (Cf) {
                    *(float2*)(Cf + (size_t)mA * N + nb) = make_float2(v00, v01);
                    *(float2*)(Cf + (size_t)mB * N + nb) = make_float2(v10, v11);
                }
                if (Chi) {
                    bf16 h0, l0, h1, l1;
                    split_hl(v00, h0, l0); split_hl(v01, h1, l1);
                    *(bf162*)(Chi + (size_t)mA * N + nb) = bf162(h0, h1);
                    *(bf162*)(Clo + (size_t)mA * N + nb) = bf162(l0, l1);
                    split_hl(v10, h0, l0); split_hl(v11, h1, l1);
                    *(bf162*)(Chi + (size_t)mB * N + nb) = bf162(h0, h1);
                    *(bf162*)(Clo + (size_t)mB * N + nb) = bf162(l0, l1);
                }
            }
        }
    }
}

// ---------------- HMMA flash attention (split-bf16, rope table, tile skipping) ----
__global__ __launch_bounds__(128) void attn_kernel(
    const float* __restrict__ qkv, const float2* __restrict__ rt,
    bf16* __restrict__ ohi, bf16* __restrict__ olo,
    const int* __restrict__ lengths)
{
    extern __shared__ __align__(16) char sm[];
    const uint32_t sb = smem_u32(sm);
    const uint32_t QH = 0, QL = 8192, KH = 16384, KL = 24576, VH = 32768, VL = 40960;

    int t = threadIdx.x, wid = t >> 5, lane = t & 31;
    int qt = blockIdx.x, hh = blockIdx.y, b = blockIdx.z;
    int len = lengths[b];

    // ---- Q load + rope + split ----
#pragma unroll
    for (int it = 0; it < 4; it++) {
        int idx = t + it * 128;
        int r = idx >> 3, c = idx & 7;
        int s = qt * 64 + r;
        const float* base = qkv + ((size_t)b * S_ + s) * (3 * H_) + hh * HD_;
        int d0 = c * 8;
        float4 xa = *(const float4*)(base + d0);
        float4 xb = *(const float4*)(base + d0 + 4);
        float4 pa = *(const float4*)(base + (d0 ^ 32));
        float4 pb = *(const float4*)(base + (d0 ^ 32) + 4);
        float xs[8] = {xa.x, xa.y, xa.z, xa.w, xb.x, xb.y, xb.z, xb.w};
        float ps[8] = {pa.x, pa.y, pa.z, pa.w, pb.x, pb.y, pb.z, pb.w};
        float sgn = (d0 < 32) ? -1.f : 1.f;
        const float2* rte = rt + s * 32 + (d0 & 31);
        uint32_t wh[4], wl[4];
#pragma unroll
        for (int e = 0; e < 8; e += 2) {
            float2 cs0 = rte[e], cs1 = rte[e + 1];
            float v0 = xs[e] * cs0.x + sgn * ps[e] * cs0.y;
            float v1 = xs[e + 1] * cs1.x + sgn * ps[e + 1] * cs1.y;
            bf16 h0, l0, h1, l1;
            split_hl(v0, h0, l0); split_hl(v1, h1, l1);
            wh[e >> 1] = packb(h0, h1); wl[e >> 1] = packb(l0, l1);
        }
        uint32_t off = SWZ128(r, c);
        *(uint4*)(sm + QH + off) = make_uint4(wh[0], wh[1], wh[2], wh[3]);
        *(uint4*)(sm + QL + off) = make_uint4(wl[0], wl[1], wl[2], wl[3]);
    }
    __syncthreads();

    int rsel = lane & 15, chalf = lane >> 4;
    uint32_t qh[4][4], ql[4][4];
#pragma unroll
    for (int ks = 0; ks < 4; ks++) {
        int rr = wid * 16 + rsel;
        uint32_t off = SWZ128(rr, ks * 2 + chalf);
        ldsm4(qh[ks], sb + QH + off);
        ldsm4(ql[ks], sb + QL + off);
    }

    float oc[8][4];
#pragma unroll
    for (int dt = 0; dt < 8; dt++)
#pragma unroll
        for (int e = 0; e < 4; e++) oc[dt][e] = 0.f;
    float m0 = -INFINITY, m1 = -INFINITY, ls0 = 0.f, ls1 = 0.f;

    int kt0 = len >> 6;
    if (kt0 > 7) kt0 = 7;

    for (int kt = kt0; kt < 8; kt++) {
        __syncthreads();
        // ---- K (rope) + V load + split ----
#pragma unroll
        for (int it = 0; it < 4; it++) {
            int idx = t + it * 128;
            int r = idx >> 3, c = idx & 7;
            int s = kt * 64 + r;
            const float* base = qkv + ((size_t)b * S_ + s) * (3 * H_) + H_ + hh * HD_;
            int d0 = c * 8;
            float4 xa = *(const float4*)(base + d0);
            float4 xb = *(const float4*)(base + d0 + 4);
            float4 pa = *(const float4*)(base + (d0 ^ 32));
            float4 pb = *(const float4*)(base + (d0 ^ 32) + 4);
            float xs[8] = {xa.x, xa.y, xa.z, xa.w, xb.x, xb.y, xb.z, xb.w};
            float ps[8] = {pa.x, pa.y, pa.z, pa.w, pb.x, pb.y, pb.z, pb.w};
            float sgn = (d0 < 32) ? -1.f : 1.f;
            const float2* rte = rt + s * 32 + (d0 & 31);
            uint32_t wh[4], wl[4];
#pragma unroll
            for (int e = 0; e < 8; e += 2) {
                float2 cs0 = rte[e], cs1 = rte[e + 1];
                float v0 = xs[e] * cs0.x + sgn * ps[e] * cs0.y;
                float v1 = xs[e + 1] * cs1.x + sgn * ps[e + 1] * cs1.y;
                bf16 h0, l0, h1, l1;
                split_hl(v0, h0, l0); split_hl(v1, h1, l1);
                wh[e >> 1] = packb(h0, h1); wl[e >> 1] = packb(l0, l1);
            }
            uint32_t off = SWZ128(r, c);
            *(uint4*)(sm + KH + off) = make_uint4(wh[0], wh[1], wh[2], wh[3]);
            *(uint4*)(sm + KL + off) = make_uint4(wl[0], wl[1], wl[2], wl[3]);
            const float* vbase = base + H_;
            float4 va = *(const float4*)(vbase + d0);
            float4 vb2 = *(const float4*)(vbase + d0 + 4);
            float vs[8] = {va.x, va.y, va.z, va.w, vb2.x, vb2.y, vb2.z, vb2.w};
#pragma unroll
            for (int e = 0; e < 8; e += 2) {
                bf16 h0, l0, h1, l1;
                split_hl(vs[e], h0, l0); split_hl(vs[e + 1], h1, l1);
                wh[e >> 1] = packb(h0, h1); wl[e >> 1] = packb(l0, l1);
            }
            *(uint4*)(sm + VH + off) = make_uint4(wh[0], wh[1], wh[2], wh[3]);
            *(uint4*)(sm + VL + off) = make_uint4(wl[0], wl[1], wl[2], wl[3]);
        }
        __syncthreads();

        // ---- S = Q K^T (pass-major per jj: acc reuse distance 2) ----
        float sv[8][4];
#pragma unroll
        for (int jt = 0; jt < 8; jt++)
#pragma unroll
            for (int e = 0; e < 4; e++) sv[jt][e] = 0.f;
#pragma unroll
        for (int ks = 0; ks < 4; ks++) {
#pragma unroll
            for (int jj = 0; jj < 4; jj++) {
                uint32_t bh[4], bl[4];
                int rr = jj * 16 + rsel;
                uint32_t off = SWZ128(rr, ks * 2 + chalf);
                ldsm4(bh, sb + KH + off);
                ldsm4(bl, sb + KL + off);
                mma16816(sv[jj * 2 + 0], qh[ks], bh[0], bh[2]);
                mma16816(sv[jj * 2 + 1], qh[ks], bh[1], bh[3]);
                mma16816(sv[jj * 2 + 0], qh[ks], bl[0], bl[2]);
                mma16816(sv[jj * 2 + 1], qh[ks], bl[1], bl[3]);
                mma16816(sv[jj * 2 + 0], ql[ks], bh[0], bh[2]);
                mma16816(sv[jj * 2 + 1], ql[ks], bh[1], bh[3]);
            }
        }

        // ---- scale + inverted mask + online softmax ----
        int colb = kt * 64 + (lane & 3) * 2;
        float rm0 = -INFINITY, rm1 = -INFINITY;
#pragma unroll
        for (int jt = 0; jt < 8; jt++) {
#pragma unroll
            for (int e = 0; e < 2; e++) {
                int kp = colb + jt * 8 + e;
                bool keep = (kp >= len);
                float v0 = sv[jt][e] * 0.125f;
                float v1 = sv[jt][2 + e] * 0.125f;
                sv[jt][e]     = keep ? v0 : -1e9f;
                sv[jt][2 + e] = keep ? v1 : -1e9f;
                rm0 = fmaxf(rm0, sv[jt][e]);
                rm1 = fmaxf(rm1, sv[jt][2 + e]);
            }
        }
        rm0 = fmaxf(rm0, __shfl_xor_sync(0xffffffffu, rm0, 1));
        rm0 = fmaxf(rm0, __shfl_xor_sync(0xffffffffu, rm0, 2));
        rm1 = fmaxf(rm1, __shfl_xor_sync(0xffffffffu, rm1, 1));
        rm1 = fmaxf(rm1, __shfl_xor_sync(0xffffffffu, rm1, 2));
        float mn0 = fmaxf(m0, rm0), mn1 = fmaxf(m1, rm1);
        float a0 = __expf(m0 - mn0), a1 = __expf(m1 - mn1);
        m0 = mn0; m1 = mn1;
        float s0 = 0.f, s1 = 0.f;
#pragma unroll
        for (int jt = 0; jt < 8; jt++) {
            sv[jt][0] = __expf(sv[jt][0] - mn0);
            sv[jt][1] = __expf(sv[jt][1] - mn0);
            sv[jt][2] = __expf(sv[jt][2] - mn1);
            sv[jt][3] = __expf(sv[jt][3] - mn1);
            s0 += sv[jt][0] + sv[jt][1];
            s1 += sv[jt][2] + sv[jt][3];
        }
        s0 += __shfl_xor_sync(0xffffffffu, s0, 1);
        s0 += __shfl_xor_sync(0xffffffffu, s0, 2);
        s1 += __shfl_xor_sync(0xffffffffu, s1, 1);
        s1 += __shfl_xor_sync(0xffffffffu, s1, 2);
        ls0 = ls0 * a0 + s0;
        ls1 = ls1 * a1 + s1;
#pragma unroll
        for (int dt = 0; dt < 8; dt++) {
            oc[dt][0] *= a0; oc[dt][1] *= a0;
            oc[dt][2] *= a1; oc[dt][3] *= a1;
        }

        // ---- O += P V ----
#pragma unroll
        for (int jp = 0; jp < 4; jp++) {
            uint32_t pah[4], pal[4];
#pragma unroll
            for (int half = 0; half < 2; half++) {
                bf16 h0, lo0, h1, lo1, h2, lo2, h3, lo3;
                split_hl(sv[2 * jp + half][0], h0, lo0);
                split_hl(sv[2 * jp + half][1], h1, lo1);
                split_hl(sv[2 * jp + half][2], h2, lo2);
                split_hl(sv[2 * jp + half][3], h3, lo3);
                pah[2 * half + 0] = packb(h0, h1);  pal[2 * half + 0] = packb(lo0, lo1);
                pah[2 * half + 1] = packb(h2, h3);  pal[2 * half + 1] = packb(lo2, lo3);
            }
            int vrow = jp * 16 + ((lane >> 3) & 1) * 8 + (lane & 7);
#pragma unroll
            for (int g = 0; g < 4; g++) {
                int cch = 2 * g + (lane >> 4);
                uint32_t off = SWZ128(vrow, cch);
                uint32_t vh[4], vl[4];
                ldsm4t(vh, sb + VH + off);
                ldsm4t(vl, sb + VL + off);
                mma16816(oc[2 * g],     pah, vh[0], vh[1]);
                mma16816(oc[2 * g + 1], pah, vh[2], vh[3]);
                mma16816(oc[2 * g],     pah, vl[0], vl[1]);
                mma16816(oc[2 * g + 1], pah, vl[2], vl[3]);
                mma16816(oc[2 * g],     pal, vh[0], vh[1]);
                mma16816(oc[2 * g + 1], pal, vh[2], vh[3]);
            }
        }
    }

    // ---- epilogue ----
    float i0 = 1.f / ls0, i1 = 1.f / ls1;
    int r0 = qt * 64 + wid * 16 + (lane >> 2);
#pragma unroll
    for (int dt = 0; dt < 8; dt++) {
        int d = hh * HD_ + dt * 8 + (lane & 3) * 2;
        size_t o0 = ((size_t)b * S_ + r0) * H_ + d;
        size_t o1 = o0 + (size_t)8 * H_;
        bf16 h0, lo0, h1, lo1;
        split_hl(oc[dt][0] * i0, h0, lo0);
        split_hl(oc[dt][1] * i0, h1, lo1);
        *(bf162*)(ohi + o0) = bf162(h0, h1);
        *(bf162*)(olo + o0) = bf162(lo0, lo1);
        split_hl(oc[dt][2] * i1, h0, lo0);
        split_hl(oc[dt][3] * i1, h1, lo1);
        *(bf162*)(ohi + o1) = bf162(h0, h1);
        *(bf162*)(olo + o1) = bf162(lo0, lo1);
    }
}

// ---------------- LayerNorm (residual add + optional split outputs) ----------------
__global__ __launch_bounds__(128) void ln_kernel(
    const float* __restrict__ x, const float* __restrict__ res,
    const float* __restrict__ g, const float* __restrict__ be,
    float* __restrict__ out, bf16* __restrict__ ohi, bf16* __restrict__ olo, int C)
{
    int m = blockIdx.x, t = threadIdx.x;
    int nv = C >> 2;
    float4 v = make_float4(0.f, 0.f, 0.f, 0.f);
    if (t < nv) {
        v = ((const float4*)(x + (size_t)m * C))[t];
        if (res) {
            float4 w = ((const float4*)(res + (size_t)m * C))[t];
            v.x += w.x; v.y += w.y; v.z += w.z; v.w += w.w;
        }
    }
    float sum = v.x + v.y + v.z + v.w;
    float sq  = v.x * v.x + v.y * v.y + v.z * v.z + v.w * v.w;
#pragma unroll
    for (int off = 16; off; off >>= 1) {
        sum += __shfl_xor_sync(0xffffffffu, sum, off);
        sq  += __shfl_xor_sync(0xffffffffu, sq,  off);
    }
    __shared__ float s1[4], s2[4];
    if ((t & 31) == 0) { s1[t >> 5] = sum; s2[t >> 5] = sq; }
    __syncthreads();
    sum = s1[0] + s1[1] + s1[2] + s1[3];
    sq  = s2[0] + s2[1] + s2[2] + s2[3];
    float mean = sum / C;
    float var  = sq / C - mean * mean;
    float inv  = rsqrtf(var + 1e-5f);
    if (t < nv) {
        float4 gv = ((const float4*)g)[t];
        float4 bv = ((const float4*)be)[t];
        float4 o4;
        o4.x = (v.x - mean) * inv * gv.x + bv.x;
        o4.y = (v.y - mean) * inv * gv.y + bv.y;
        o4.z = (v.z - mean) * inv * gv.z + bv.z;
        o4.w = (v.w - mean) * inv * gv.w + bv.w;
        if (out) ((float4*)(out + (size_t)m * C))[t] = o4;
        if (ohi) {
            bf16 h0, l0, h1, l1, h2, l2, h3, l3;
            split_hl(o4.x, h0, l0); split_hl(o4.y, h1, l1);
            split_hl(o4.z, h2, l2); split_hl(o4.w, h3, l3);
            *(bf162*)(ohi + (size_t)m * C + t * 4)     = bf162(h0, h1);
            *(bf162*)(ohi + (size_t)m * C + t * 4 + 2) = bf162(h2, h3);
            *(bf162*)(olo + (size_t)m * C + t * 4)     = bf162(l0, l1);
            *(bf162*)(olo + (size_t)m * C + t * 4 + 2) = bf162(l2, l3);
        }
    }
}

// ---------------- small kernels ----------------
__global__ __launch_bounds__(256) void embed_kernel(
    const int* __restrict__ x, const float* __restrict__ emb,
    float* __restrict__ h, bf16* __restrict__ hh, bf16* __restrict__ hl)
{
    int idx = blockIdx.x * blockDim.x + threadIdx.x;
    if (idx >= M_ * (H_ / 4)) return;
    int m = idx >> 7, c4 = idx & 127;
    int tok = x[m];
    float4 e = ((const float4*)(emb + (size_t)tok * H_))[c4];
    const float sc = 22.62741699796952f;  // sqrt(512)
    e.x *= sc; e.y *= sc; e.z *= sc; e.w *= sc;
    ((float4*)(h + (size_t)m * H_))[c4] = e;
    bf16 h0, l0, h1, l1, h2, l2, h3, l3;
    split_hl(e.x, h0, l0); split_hl(e.y, h1, l1);
    split_hl(e.z, h2, l2); split_hl(e.w, h3, l3);
    *(bf162*)(hh + (size_t)m * H_ + c4 * 4)     = bf162(h0, h1);
    *(bf162*)(hh + (size_t)m * H_ + c4 * 4 + 2) = bf162(h2, h3);
    *(bf162*)(hl + (size_t)m * H_ + c4 * 4)     = bf162(l0, l1);
    *(bf162*)(hl + (size_t)m * H_ + c4 * 4 + 2) = bf162(l2, l3);
}

__global__ __launch_bounds__(256) void maskmul_kernel(
    const float* __restrict__ in, bf16* __restrict__ ohi, bf16* __restrict__ olo,
    const int* __restrict__ lengths)
{
    int idx = blockIdx.x * blockDim.x + threadIdx.x;
    if (idx >= M_ * H_) return;
    int m = idx >> 9;
    int s = m & (S_ - 1), b = m >> 9;
    float v = in[idx] * ((s >= lengths[b]) ? 1.f : 0.f);  // inverted mask
    bf16 h, l;
    split_hl(v, h, l);
    ohi[idx] = h; olo[idx] = l;
}

#define NW1 (L_*F_*H_*3)
#define NW2 (L_*H_*F_*3)
#define ND1 (FD_*H_*3)
#define ND2 (FD_*FD_*3)
__global__ __launch_bounds__(256) void prep_conv_kernel(
    const float* __restrict__ c1w, const float* __restrict__ c2w,
    const float* __restrict__ d1w, const float* __restrict__ d2w)
{
    int idx = blockIdx.x * blockDim.x + threadIdx.x;
    const float* src; bf16 *dh, *dl; int CI; int base;
    if (idx < NW1)                        { src = c1w; dh = g_w1h; dl = g_w1l; CI = H_;  base = idx; }
    else if (idx < NW1 + NW2)             { src = c2w; dh = g_w2h; dl = g_w2l; CI = F_;  base = idx - NW1; }
    else if (idx < NW1 + NW2 + ND1)       { src = d1w; dh = g_d1h; dl = g_d1l; CI = H_;  base = idx - NW1 - NW2; }
    else if (idx < NW1 + NW2 + ND1 + ND2) { src = d2w; dh = g_d2h; dl = g_d2l; CI = FD_; base = idx - NW1 - NW2 - ND1; }
    else return;
    int kk = base % 3;
    int rest = base / 3;
    int ci = rest % CI;
    int co = rest / CI;
    float v = src[base];
    bf16 h, l; split_hl(v, h, l);
    size_t o = (size_t)co * (3 * CI) + kk * CI + ci;
    dh[o] = h; dl[o] = l;
}

#define NQKV (L_*3*H_*H_)
#define NWO  (L_*H_*H_)
#define NPJ  (OUT_*H_)
#define NBQ  (L_*3*H_)
#define NRT  (S_*32)
__global__ __launch_bounds__(256) void prep_lin_kernel(
    const float* __restrict__ Wq, const float* __restrict__ Wk,
    const float* __restrict__ Wv, const float* __restrict__ Wo,
    const float* __restrict__ pj,
    const float* __restrict__ bq, const float* __restrict__ bk,
    const float* __restrict__ bv)
{
    int idx = blockIdx.x * blockDim.x + threadIdx.x;
    if (idx < NQKV) {
        int e = idx % H_;
        int n = (idx / H_) % (3 * H_);
        int l = idx / (3 * H_ * H_);
        const float* W = (n < H_) ? Wq : (n < 2 * H_) ? Wk : Wv;
        int nn = n & (H_ - 1);
        float v = W[(size_t)l * H_ * H_ + (size_t)nn * H_ + e];
        bf16 h, lo; split_hl(v, h, lo);
        g_wqkvh[idx] = h; g_wqkvl[idx] = lo;
        return;
    }
    int i2 = idx - NQKV;
    if (i2 < NWO) {
        float v = Wo[i2];
        bf16 h, lo; split_hl(v, h, lo);
        g_woh[i2] = h; g_wol[i2] = lo;
        return;
    }
    int i3 = i2 - NWO;
    if (i3 < NPJ) {
        float v = pj[i3];
        bf16 h, lo; split_hl(v, h, lo);
        g_pjh[i3] = h; g_pjl[i3] = lo;
        return;
    }
    int i4 = i3 - NPJ;
    if (i4 < NBQ) {
        int n = i4 % (3 * H_);
        int l = i4 / (3 * H_);
        const float* bb = (n < H_) ? bq : (n < 2 * H_) ? bk : bv;
        g_bqkv[i4] = bb[l * H_ + (n & (H_ - 1))];
        return;
    }
    int i5 = i4 - NBQ;
    if (i5 < NRT) {
        int s = i5 >> 5, j = i5 & 31;
        float th = expf(-(float)j * 0.28782313662425574f);
        float sn, cs;
        sincosf((float)s * th, &sn, &cs);
        g_rope[i5] = make_float2(cs, sn);
    }
}

__global__ __launch_bounds__(256) void dp_final_kernel(
    const float* __restrict__ x, const float* __restrict__ w,
    const float* __restrict__ pb, const int* __restrict__ lengths,
    float* __restrict__ out)
{
    int warp = threadIdx.x >> 5, lane = threadIdx.x & 31;
    int m = blockIdx.x * 8 + warp;
    if (m >= M_) return;
    const float* xr = x + (size_t)m * FD_;
    float s = 0.f;
    for (int c = lane; c < FD_; c += 32) s += xr[c] * w[c];
#pragma unroll
    for (int off = 16; off; off >>= 1) s += __shfl_xor_sync(0xffffffffu, s, off);
    if (lane == 0) {
        int b = m >> 9, sp = m & (S_ - 1);
        float mv = (sp >= lengths[b]) ? 1.f : 0.f;
        float val = (s + pb[0]) * mv;
        out[(size_t)b * S_ + sp] = ceilf(expf(val));
    }
}

// ---------------- orchestration ----------------
extern "C" void kernel_launch(void* const* d_in, const int* in_sizes, int n_in,
                              void* d_out, int out_size)
{
    const int*   x      = (const int*)  d_in[0];
    const int*   xlen   = (const int*)  d_in[1];
    const float* emb    = (const float*)d_in[2];
    const float* Wq     = (const float*)d_in[3];
    const float* bq     = (const float*)d_in[4];
    const float* Wk     = (const float*)d_in[5];
    const float* bk     = (const float*)d_in[6];
    const float* Wv     = (const float*)d_in[7];
    const float* bv     = (const float*)d_in[8];
    const float* Wo     = (const float*)d_in[9];
    const float* bo     = (const float*)d_in[10];
    const float* c1w    = (const float*)d_in[11];
    const float* c1b    = (const float*)d_in[12];
    const float* c2w    = (const float*)d_in[13];
    const float* c2b    = (const float*)d_in[14];
    const float* ln1g   = (const float*)d_in[15];
    const float* ln1b   = (const float*)d_in[16];
    const float* ln2g   = (const float*)d_in[17];
    const float* ln2b   = (const float*)d_in[18];
    const float* projw  = (const float*)d_in[19];
    const float* projb  = (const float*)d_in[20];
    const float* dpc1w  = (const float*)d_in[21];
    const float* dpc1b  = (const float*)d_in[22];
    const float* dpln1g = (const float*)d_in[23];
    const float* dpln1b = (const float*)d_in[24];
    const float* dpc2w  = (const float*)d_in[25];
    const float* dpc2b  = (const float*)d_in[26];
    const float* dpln2g = (const float*)d_in[27];
    const float* dpln2b = (const float*)d_in[28];
    const float* dppw   = (const float*)d_in[29];
    const float* dppb   = (const float*)d_in[30];
    float* out = (float*)d_out;

    float *h, *x1, *op, *cv2, *qkv, *bqkv;
    float2* rtab;
    bf16 *hh, *hl, *x1h, *x1l, *ah, *al, *midh, *midl, *mkh, *mkl, *dpxh, *dpxl;
    bf16 *wqh, *wql, *woh, *wol, *w1h, *w1l, *w2h, *w2l, *pjh, *pjl, *d1h, *d1l, *d2h, *d2l;
    cudaGetSymbolAddress((void**)&h,    g_h);
    cudaGetSymbolAddress((void**)&x1,   g_x1);
    cudaGetSymbolAddress((void**)&op,   g_op);
    cudaGetSymbolAddress((void**)&cv2,  g_cv2);
    cudaGetSymbolAddress((void**)&qkv,  g_qkv);
    cudaGetSymbolAddress((void**)&rtab, g_rope);
    cudaGetSymbolAddress((void**)&hh,   g_hh);
    cudaGetSymbolAddress((void**)&hl,   g_hl);
    cudaGetSymbolAddress((void**)&x1h,  g_x1h);
    cudaGetSymbolAddress((void**)&x1l,  g_x1l);
    cudaGetSymbolAddress((void**)&ah,   g_ah);
    cudaGetSymbolAddress((void**)&al,   g_al);
    cudaGetSymbolAddress((void**)&midh, g_midh);
    cudaGetSymbolAddress((void**)&midl, g_midl);
    cudaGetSymbolAddress((void**)&mkh,  g_mkh);
    cudaGetSymbolAddress((void**)&mkl,  g_mkl);
    cudaGetSymbolAddress((void**)&dpxh, g_dpxh);
    cudaGetSymbolAddress((void**)&dpxl, g_dpxl);
    cudaGetSymbolAddress((void**)&wqh,  g_wqkvh);
    cudaGetSymbolAddress((void**)&wql,  g_wqkvl);
    cudaGetSymbolAddress((void**)&woh,  g_woh);
    cudaGetSymbolAddress((void**)&wol,  g_wol);
    cudaGetSymbolAddress((void**)&w1h,  g_w1h);
    cudaGetSymbolAddress((void**)&w1l,  g_w1l);
    cudaGetSymbolAddress((void**)&w2h,  g_w2h);
    cudaGetSymbolAddress((void**)&w2l,  g_w2l);
    cudaGetSymbolAddress((void**)&pjh,  g_pjh);
    cudaGetSymbolAddress((void**)&pjl,  g_pjl);
    cudaGetSymbolAddress((void**)&d1h,  g_d1h);
    cudaGetSymbolAddress((void**)&d1l,  g_d1l);
    cudaGetSymbolAddress((void**)&d2h,  g_d2h);
    cudaGetSymbolAddress((void**)&d2l,  g_d2l);
    cudaGetSymbolAddress((void**)&bqkv, g_bqkv);

    cudaFuncSetAttribute((const void*)attn_kernel,
                         cudaFuncAttributeMaxDynamicSharedMemorySize, 49152);
    cudaFuncSetAttribute((const void*)hgemm_kernel,
                         cudaFuncAttributeMaxDynamicSharedMemorySize, 49152);

    {
        int tot = NW1 + NW2 + ND1 + ND2;
        prep_conv_kernel<<<(tot + 255) / 256, 256>>>(c1w, c2w, dpc1w, dpc2w);
        tot = NQKV + NWO + NPJ + NBQ + NRT;
        prep_lin_kernel<<<(tot + 255) / 256, 256>>>(Wq, Wk, Wv, Wo, projw, bq, bk, bv);
    }
    embed_kernel<<<M_ * (H_ / 4) / 256, 256>>>(x, emb, h, hh, hl);

    const int SM_G = 49152;
    dim3 gQKV(3 * H_ / 128, M_ / 64);   // (12,256)
    dim3 gH(H_ / 128, M_ / 64);         // (4,256)
    dim3 gF(F_ / 128, M_ / 64);         // (16,256)
    dim3 gMu(1, M_ / 64);
    dim3 gDp(FD_ / 128, M_ / 64);       // (2,256)
    dim3 ga(S_ / 64, NH_, B_);

    for (int l = 0; l < L_; l++) {
        size_t wOff = (size_t)l * H_ * H_;
        size_t wqOff = (size_t)l * 3 * H_ * H_;
        hgemm_kernel<<<gQKV, 128, SM_G>>>(hh, hl, wqh + wqOff, wql + wqOff,
                                          bqkv + l * 3 * H_, qkv, nullptr, nullptr,
                                          3 * H_, 9, 1, 0, 0, xlen);
        attn_kernel<<<ga, 128, SM_G>>>(qkv, rtab, ah, al, xlen);
        hgemm_kernel<<<gH, 128, SM_G>>>(ah, al, woh + wOff, wol + wOff,
                                        bo + l * H_, op, nullptr, nullptr,
                                        H_, 9, 1, 0, 0, xlen);
        ln_kernel<<<M_, 128>>>(op, h, ln1g + l * H_, ln1b + l * H_, x1, x1h, x1l, H_);
        hgemm_kernel<<<gF, 128, SM_G>>>(x1h, x1l,
                                        w1h + (size_t)l * F_ * 3 * H_, w1l + (size_t)l * F_ * 3 * H_,
                                        c1b + l * F_, nullptr, midh, midl,
                                        F_, 9, 3, 1, FLAG_RELU, xlen);
        hgemm_kernel<<<gH, 128, SM_G>>>(midh, midl,
                                        w2h + (size_t)l * H_ * 3 * F_, w2l + (size_t)l * H_ * 3 * F_,
                                        c2b + l * H_, cv2, nullptr, nullptr,
                                        H_, 11, 3, 1, 0, xlen);
        ln_kernel<<<M_, 128>>>(cv2, x1, ln2g + l * H_, ln2b + l * H_, h, hh, hl, H_);
    }

    hgemm_kernel<<<gMu, 128, SM_G>>>(hh, hl, pjh, pjl, projb, out, nullptr, nullptr,
                                     OUT_, 9, 1, 0, FLAG_TRANS, xlen);

    maskmul_kernel<<<M_ * H_ / 256, 256>>>(h, mkh, mkl, xlen);
    hgemm_kernel<<<gDp, 128, SM_G>>>(mkh, mkl, d1h, d1l, dpc1b, op, nullptr, nullptr,
                                     FD_, 9, 3, 1, FLAG_RELU | FLAG_MASK, xlen);
    ln_kernel<<<M_, 128>>>(op, nullptr, dpln1g, dpln1b, cv2, dpxh, dpxl, FD_);
    hgemm_kernel<<<gDp, 128, SM_G>>>(dpxh, dpxl, d2h, d2l, dpc2b, op, nullptr, nullptr,
                                     FD_, 8, 3, 1, FLAG_RELU | FLAG_MASK, xlen);
    ln_kernel<<<M_, 128>>>(op, nullptr, dpln2g, dpln2b, x1, nullptr, nullptr, FD_);
    dp_final_kernel<<<M_ / 8, 256>>>(x1, dppw, dppb, xlen,
                                     out + ((size_t)out_size - (size_t)B_ * S_));
}

// round 7
// speedup vs baseline: 3.7733x; 1.0473x over previous
#include <cuda_runtime.h>
#include <cuda_bf16.h>
#include <math.h>
#include <stdint.h>

#define B_   32
#define S_   512
#define H_   512
#define NH_  8
#define HD_  64
#define F_   2048
#define L_   6
#define OUT_ 80
#define FD_  256
#define M_   (B_*S_)   // 16384 tokens

typedef __nv_bfloat16  bf16;
typedef __nv_bfloat162 bf162;

// ---------------- scratch (static device globals) ----------------
__device__ float g_h   [M_*H_];
__device__ float g_x1  [M_*H_];
__device__ float g_op  [M_*H_];
__device__ float g_cv2 [M_*H_];
__device__ float g_qkv [M_*3*H_];
__device__ bf16  g_hh  [M_*H_],  g_hl  [M_*H_];
__device__ bf16  g_x1h [M_*H_],  g_x1l [M_*H_];
__device__ bf16  g_ah  [M_*H_],  g_al  [M_*H_];
__device__ bf16  g_midh[M_*F_],  g_midl[M_*F_];
__device__ bf16  g_mkh [M_*H_],  g_mkl [M_*H_];
__device__ bf16  g_dpxh[M_*FD_], g_dpxl[M_*FD_];
__device__ bf16  g_wqkvh[L_*3*H_*H_], g_wqkvl[L_*3*H_*H_];
__device__ bf16  g_woh [L_*H_*H_],    g_wol [L_*H_*H_];
__device__ bf16  g_w1h [L_*F_*3*H_],  g_w1l [L_*F_*3*H_];
__device__ bf16  g_w2h [L_*H_*3*F_],  g_w2l [L_*H_*3*F_];
__device__ bf16  g_pjh [OUT_*H_],     g_pjl [OUT_*H_];
__device__ bf16  g_d1h [FD_*3*H_],    g_d1l [FD_*3*H_];
__device__ bf16  g_d2h [FD_*3*FD_],   g_d2l [FD_*3*FD_];
__device__ float g_bqkv[L_*3*H_];
__device__ float2 g_rope[S_*32];

#define FLAG_RELU  1
#define FLAG_MASK  2
#define FLAG_TRANS 4

#define SWZ128(r,c) ((uint32_t)((r)*128 + ((((c) ^ ((r)&7))) << 4)))

// ---------------- helpers ----------------
__device__ __forceinline__ void split_hl(float x, bf16& h, bf16& l) {
    h = __float2bfloat16_rn(x);
    l = __float2bfloat16_rn(x - __bfloat162float(h));
}

__device__ __forceinline__ uint32_t packb(bf16 x, bf16 y) {
    return (uint32_t)__bfloat16_as_ushort(x) | ((uint32_t)__bfloat16_as_ushort(y) << 16);
}

__device__ __forceinline__ uint32_t smem_u32(const void* p) {
    uint32_t a;
    asm("{ .reg .u64 t; cvta.to.shared.u64 t, %1; cvt.u32.u64 %0, t; }" : "=r"(a) : "l"(p));
    return a;
}

__device__ __forceinline__ void cpa16(uint32_t dst, const void* src, int sz) {
    asm volatile("cp.async.cg.shared.global [%0], [%1], 16, %2;"
                 :: "r"(dst), "l"(src), "r"(sz));
}

__device__ __forceinline__ void ldsm4(uint32_t* r, uint32_t addr) {
    asm volatile("ldmatrix.sync.aligned.m8n8.x4.shared.b16 {%0,%1,%2,%3}, [%4];"
                 : "=r"(r[0]), "=r"(r[1]), "=r"(r[2]), "=r"(r[3]) : "r"(addr));
}

__device__ __forceinline__ void ldsm4t(uint32_t* r, uint32_t addr) {
    asm volatile("ldmatrix.sync.aligned.m8n8.x4.trans.shared.b16 {%0,%1,%2,%3}, [%4];"
                 : "=r"(r[0]), "=r"(r[1]), "=r"(r[2]), "=r"(r[3]) : "r"(addr));
}

__device__ __forceinline__ void mma16816(float* c, const uint32_t* a,
                                         uint32_t b0, uint32_t b1) {
    asm volatile(
        "mma.sync.aligned.m16n8k16.row.col.f32.bf16.bf16.f32 "
        "{%0,%1,%2,%3}, {%4,%5,%6,%7}, {%8,%9}, {%0,%1,%2,%3};"
        : "+f"(c[0]), "+f"(c[1]), "+f"(c[2]), "+f"(c[3])
        : "r"(a[0]), "r"(a[1]), "r"(a[2]), "r"(a[3]), "r"(b0), "r"(b1));
}

// ---------------- split-bf16 HMMA GEMM, 2-stage cp.async pipeline ----------------
// Tile 64(M) x 128(N), K-chunk 32. Smem rows are 128B holding TWO K-chunks
// (chunk kc occupies column-half (kc&1)*4), swizzled over the full 8-col space
// -> conflict-free ldmatrix. Planes: Ahi 8K | Alo 8K | Bhi 16K | Blo 16K = 48KB.
__global__ __launch_bounds__(128, 4) void hgemm_kernel(
    const bf16* __restrict__ Ahi, const bf16* __restrict__ Alo,
    const bf16* __restrict__ Whi, const bf16* __restrict__ Wlo,
    const float* __restrict__ bias,
    float* __restrict__ Cf, bf16* __restrict__ Chi, bf16* __restrict__ Clo,
    int N, int cinLog2, int nseg, int pad, int flags,
    const int* __restrict__ lengths)
{
    extern __shared__ __align__(16) char smem[];
    const uint32_t sb = smem_u32(smem);
    const uint32_t sAHI = sb, sALO = sb + 8192, sBHI = sb + 16384, sBLO = sb + 32768;

    int t = threadIdx.x, wid = t >> 5, lane = t & 31;
    int m0 = blockIdx.y * 64, n0 = blockIdx.x * 128;
    int cin  = 1 << cinLog2;
    int Kdim = nseg << cinLog2;
    int nch  = Kdim >> 5;
    int wm = (wid >> 1) * 32, wn = (wid & 1) * 64;

    float acc[2][8][4];
#pragma unroll
    for (int i = 0; i < 2; i++)
#pragma unroll
        for (int j = 0; j < 8; j++)
#pragma unroll
            for (int e = 0; e < 4; e++) acc[i][j][e] = 0.f;

    auto load_chunk = [&](int kc) {
        int kh4 = (kc & 1) * 4;        // column-half within 128B rows
        int kk0 = kc << 5;
        int seg = kk0 >> cinLog2;
        int ci0 = kk0 & (cin - 1);
#pragma unroll
        for (int it = 0; it < 2; it++) {
            int idx = t + it * 128;
            int r = idx >> 2, c = idx & 3;
            int m = m0 + r;
            const bf16 *sh = Ahi, *sl = Alo;
            int sz = 16;
            if (nseg == 1) {
                size_t off = (size_t)m * cin + kk0 + c * 8;
                sh += off; sl += off;
            } else {
                int s = m & (S_ - 1);
                int srow = s + seg - pad;
                if (srow >= 0 && srow < S_) {
                    size_t off = (size_t)(m + srow - s) * cin + ci0 + c * 8;
                    sh += off; sl += off;
                } else sz = 0;
            }
            uint32_t d = SWZ128(r, kh4 + c);
            cpa16(sAHI + d, sh, sz);
            cpa16(sALO + d, sl, sz);
        }
#pragma unroll
        for (int it = 0; it < 4; it++) {
            int idx = t + it * 128;
            int r = idx >> 2, c = idx & 3;
            int n = n0 + r;
            int sz = (n < N) ? 16 : 0;
            size_t off = (n < N) ? ((size_t)n * Kdim + kk0 + c * 8) : 0;
            uint32_t d = SWZ128(r, kh4 + c);
            cpa16(sBHI + d, Whi + off, sz);
            cpa16(sBLO + d, Wlo + off, sz);
        }
        asm volatile("cp.async.commit_group;");
    };

    int rsel = lane & 15, chalf = lane >> 4;
    auto compute_chunk = [&](int kc) {
        int kh4 = (kc & 1) * 4;
#pragma unroll
        for (int ks = 0; ks < 2; ks++) {
            int cc = kh4 + ks * 2 + chalf;
            uint32_t ah[2][4], al[2][4];
#pragma unroll
            for (int i = 0; i < 2; i++) {
                int rr = wm + i * 16 + rsel;
                uint32_t off = SWZ128(rr, cc);
                ldsm4(ah[i], sAHI + off);
                ldsm4(al[i], sALO + off);
            }
#pragma unroll
            for (int jj = 0; jj < 4; jj++) {
                uint32_t bh[4], bl[4];
                int rr = wn + jj * 16 + rsel;
                uint32_t off = SWZ128(rr, cc);
                ldsm4(bh, sBHI + off);
                ldsm4(bl, sBLO + off);
                mma16816(acc[0][jj * 2 + 0], ah[0], bh[0], bh[2]);
                mma16816(acc[0][jj * 2 + 1], ah[0], bh[1], bh[3]);
                mma16816(acc[1][jj * 2 + 0], ah[1], bh[0], bh[2]);
                mma16816(acc[1][jj * 2 + 1], ah[1], bh[1], bh[3]);
                mma16816(acc[0][jj * 2 + 0], ah[0], bl[0], bl[2]);
                mma16816(acc[0][jj * 2 + 1], ah[0], bl[1], bl[3]);
                mma16816(acc[1][jj * 2 + 0], ah[1], bl[0], bl[2]);
                mma16816(acc[1][jj * 2 + 1], ah[1], bl[1], bl[3]);
                mma16816(acc[0][jj * 2 + 0], al[0], bh[0], bh[2]);
                mma16816(acc[0][jj * 2 + 1], al[0], bh[1], bh[3]);
                mma16816(acc[1][jj * 2 + 0], al[1], bh[0], bh[2]);
                mma16816(acc[1][jj * 2 + 1], al[1], bh[1], bh[3]);
            }
        }
    };

    load_chunk(0);
    for (int kc = 0; kc < nch; kc++) {
        if (kc + 1 < nch) {
            load_chunk(kc + 1);
            asm volatile("cp.async.wait_group 1;");
        } else {
            asm volatile("cp.async.wait_group 0;");
        }
        __syncthreads();
        compute_chunk(kc);
        __syncthreads();
    }

    // ---- epilogue ----
    int r0 = lane >> 2, c0 = (lane & 3) * 2;
#pragma unroll
    for (int i = 0; i < 2; i++) {
        int mA = m0 + wm + i * 16 + r0;
        int mB = mA + 8;
        int sA = mA & (S_ - 1), bA = mA >> 9;
        int sB = mB & (S_ - 1), bB = mB >> 9;
        float mvA = 1.f, mvB = 1.f;
        if (flags & FLAG_MASK) {
            mvA = (sA >= lengths[bA]) ? 1.f : 0.f;   // reference's inverted mask
            mvB = (sB >= lengths[bB]) ? 1.f : 0.f;
        }
#pragma unroll
        for (int j = 0; j < 8; j++) {
            int nb = n0 + wn + j * 8 + c0;
            if (nb >= N) continue;
            float b0 = __ldg(bias + nb);
            float b1 = (nb + 1 < N) ? __ldg(bias + nb + 1) : 0.f;
            float v00 = acc[i][j][0] + b0, v01 = acc[i][j][1] + b1;
            float v10 = acc[i][j][2] + b0, v11 = acc[i][j][3] + b1;
            if (flags & FLAG_RELU) {
                v00 = fmaxf(v00, 0.f); v01 = fmaxf(v01, 0.f);
                v10 = fmaxf(v10, 0.f); v11 = fmaxf(v11, 0.f);
            }
            v00 *= mvA; v01 *= mvA; v10 *= mvB; v11 *= mvB;
            if (flags & FLAG_TRANS) {
                Cf[((size_t)bA * N + nb) * S_ + sA] = v00;
                Cf[((size_t)bB * N + nb) * S_ + sB] = v10;
                if (nb + 1 < N) {
                    Cf[((size_t)bA * N + nb + 1) * S_ + sA] = v01;
                    Cf[((size_t)bB * N + nb + 1) * S_ + sB] = v11;
                }
            } else {
                if (Cf) {
                    *(float2*)(Cf + (size_t)mA * N + nb) = make_float2(v00, v01);
                    *(float2*)(Cf + (size_t)mB * N + nb) = make_float2(v10, v11);
                }
                if (Chi) {
                    bf16 h0, l0, h1, l1;
                    split_hl(v00, h0, l0); split_hl(v01, h1, l1);
                    *(bf162*)(Chi + (size_t)mA * N + nb) = bf162(h0, h1);
                    *(bf162*)(Clo + (size_t)mA * N + nb) = bf162(l0, l1);
                    split_hl(v10, h0, l0); split_hl(v11, h1, l1);
                    *(bf162*)(Chi + (size_t)mB * N + nb) = bf162(h0, h1);
                    *(bf162*)(Clo + (size_t)mB * N + nb) = bf162(l0, l1);
                }
            }
        }
    }
}

// ---------------- HMMA flash attention (split-bf16, rope table, tile skipping) ----
__global__ __launch_bounds__(128) void attn_kernel(
    const float* __restrict__ qkv, const float2* __restrict__ rt,
    bf16* __restrict__ ohi, bf16* __restrict__ olo,
    const int* __restrict__ lengths)
{
    extern __shared__ __align__(16) char sm[];
    const uint32_t sb = smem_u32(sm);
    const uint32_t QH = 0, QL = 8192, KH = 16384, KL = 24576, VH = 32768, VL = 40960;

    int t = threadIdx.x, wid = t >> 5, lane = t & 31;
    int qt = blockIdx.x, hh = blockIdx.y, b = blockIdx.z;
    int len = lengths[b];

    // ---- Q load + rope + split ----
#pragma unroll
    for (int it = 0; it < 4; it++) {
        int idx = t + it * 128;
        int r = idx >> 3, c = idx & 7;
        int s = qt * 64 + r;
        const float* base = qkv + ((size_t)b * S_ + s) * (3 * H_) + hh * HD_;
        int d0 = c * 8;
        float4 xa = *(const float4*)(base + d0);
        float4 xb = *(const float4*)(base + d0 + 4);
        float4 pa = *(const float4*)(base + (d0 ^ 32));
        float4 pb = *(const float4*)(base + (d0 ^ 32) + 4);
        float xs[8] = {xa.x, xa.y, xa.z, xa.w, xb.x, xb.y, xb.z, xb.w};
        float ps[8] = {pa.x, pa.y, pa.z, pa.w, pb.x, pb.y, pb.z, pb.w};
        float sgn = (d0 < 32) ? -1.f : 1.f;
        const float2* rte = rt + s * 32 + (d0 & 31);
        uint32_t wh[4], wl[4];
#pragma unroll
        for (int e = 0; e < 8; e += 2) {
            float2 cs0 = rte[e], cs1 = rte[e + 1];
            float v0 = xs[e] * cs0.x + sgn * ps[e] * cs0.y;
            float v1 = xs[e + 1] * cs1.x + sgn * ps[e + 1] * cs1.y;
            bf16 h0, l0, h1, l1;
            split_hl(v0, h0, l0); split_hl(v1, h1, l1);
            wh[e >> 1] = packb(h0, h1); wl[e >> 1] = packb(l0, l1);
        }
        uint32_t off = SWZ128(r, c);
        *(uint4*)(sm + QH + off) = make_uint4(wh[0], wh[1], wh[2], wh[3]);
        *(uint4*)(sm + QL + off) = make_uint4(wl[0], wl[1], wl[2], wl[3]);
    }
    __syncthreads();

    int rsel = lane & 15, chalf = lane >> 4;
    uint32_t qh[4][4], ql[4][4];
#pragma unroll
    for (int ks = 0; ks < 4; ks++) {
        int rr = wid * 16 + rsel;
        uint32_t off = SWZ128(rr, ks * 2 + chalf);
        ldsm4(qh[ks], sb + QH + off);
        ldsm4(ql[ks], sb + QL + off);
    }

    float oc[8][4];
#pragma unroll
    for (int dt = 0; dt < 8; dt++)
#pragma unroll
        for (int e = 0; e < 4; e++) oc[dt][e] = 0.f;
    float m0 = -INFINITY, m1 = -INFINITY, ls0 = 0.f, ls1 = 0.f;

    int kt0 = len >> 6;
    if (kt0 > 7) kt0 = 7;

    for (int kt = kt0; kt < 8; kt++) {
        __syncthreads();
#pragma unroll
        for (int it = 0; it < 4; it++) {
            int idx = t + it * 128;
            int r = idx >> 3, c = idx & 7;
            int s = kt * 64 + r;
            const float* base = qkv + ((size_t)b * S_ + s) * (3 * H_) + H_ + hh * HD_;
            int d0 = c * 8;
            float4 xa = *(const float4*)(base + d0);
            float4 xb = *(const float4*)(base + d0 + 4);
            float4 pa = *(const float4*)(base + (d0 ^ 32));
            float4 pb = *(const float4*)(base + (d0 ^ 32) + 4);
            float xs[8] = {xa.x, xa.y, xa.z, xa.w, xb.x, xb.y, xb.z, xb.w};
            float ps[8] = {pa.x, pa.y, pa.z, pa.w, pb.x, pb.y, pb.z, pb.w};
            float sgn = (d0 < 32) ? -1.f : 1.f;
            const float2* rte = rt + s * 32 + (d0 & 31);
            uint32_t wh[4], wl[4];
#pragma unroll
            for (int e = 0; e < 8; e += 2) {
                float2 cs0 = rte[e], cs1 = rte[e + 1];
                float v0 = xs[e] * cs0.x + sgn * ps[e] * cs0.y;
                float v1 = xs[e + 1] * cs1.x + sgn * ps[e + 1] * cs1.y;
                bf16 h0, l0, h1, l1;
                split_hl(v0, h0, l0); split_hl(v1, h1, l1);
                wh[e >> 1] = packb(h0, h1); wl[e >> 1] = packb(l0, l1);
            }
            uint32_t off = SWZ128(r, c);
            *(uint4*)(sm + KH + off) = make_uint4(wh[0], wh[1], wh[2], wh[3]);
            *(uint4*)(sm + KL + off) = make_uint4(wl[0], wl[1], wl[2], wl[3]);
            const float* vbase = base + H_;
            float4 va = *(const float4*)(vbase + d0);
            float4 vb2 = *(const float4*)(vbase + d0 + 4);
            float vs[8] = {va.x, va.y, va.z, va.w, vb2.x, vb2.y, vb2.z, vb2.w};
#pragma unroll
            for (int e = 0; e < 8; e += 2) {
                bf16 h0, l0, h1, l1;
                split_hl(vs[e], h0, l0); split_hl(vs[e + 1], h1, l1);
                wh[e >> 1] = packb(h0, h1); wl[e >> 1] = packb(l0, l1);
            }
            *(uint4*)(sm + VH + off) = make_uint4(wh[0], wh[1], wh[2], wh[3]);
            *(uint4*)(sm + VL + off) = make_uint4(wl[0], wl[1], wl[2], wl[3]);
        }
        __syncthreads();

        // ---- S = Q K^T ----
        float sv[8][4];
#pragma unroll
        for (int jt = 0; jt < 8; jt++)
#pragma unroll
            for (int e = 0; e < 4; e++) sv[jt][e] = 0.f;
#pragma unroll
        for (int ks = 0; ks < 4; ks++) {
#pragma unroll
            for (int jj = 0; jj < 4; jj++) {
                uint32_t bh[4], bl[4];
                int rr = jj * 16 + rsel;
                uint32_t off = SWZ128(rr, ks * 2 + chalf);
                ldsm4(bh, sb + KH + off);
                ldsm4(bl, sb + KL + off);
                mma16816(sv[jj * 2 + 0], qh[ks], bh[0], bh[2]);
                mma16816(sv[jj * 2 + 1], qh[ks], bh[1], bh[3]);
                mma16816(sv[jj * 2 + 0], qh[ks], bl[0], bl[2]);
                mma16816(sv[jj * 2 + 1], qh[ks], bl[1], bl[3]);
                mma16816(sv[jj * 2 + 0], ql[ks], bh[0], bh[2]);
                mma16816(sv[jj * 2 + 1], ql[ks], bh[1], bh[3]);
            }
        }

        // ---- scale + inverted mask + online softmax ----
        int colb = kt * 64 + (lane & 3) * 2;
        float rm0 = -INFINITY, rm1 = -INFINITY;
#pragma unroll
        for (int jt = 0; jt < 8; jt++) {
#pragma unroll
            for (int e = 0; e < 2; e++) {
                int kp = colb + jt * 8 + e;
                bool keep = (kp >= len);
                float v0 = sv[jt][e] * 0.125f;
                float v1 = sv[jt][2 + e] * 0.125f;
                sv[jt][e]     = keep ? v0 : -1e9f;
                sv[jt][2 + e] = keep ? v1 : -1e9f;
                rm0 = fmaxf(rm0, sv[jt][e]);
                rm1 = fmaxf(rm1, sv[jt][2 + e]);
            }
        }
        rm0 = fmaxf(rm0, __shfl_xor_sync(0xffffffffu, rm0, 1));
        rm0 = fmaxf(rm0, __shfl_xor_sync(0xffffffffu, rm0, 2));
        rm1 = fmaxf(rm1, __shfl_xor_sync(0xffffffffu, rm1, 1));
        rm1 = fmaxf(rm1, __shfl_xor_sync(0xffffffffu, rm1, 2));
        float mn0 = fmaxf(m0, rm0), mn1 = fmaxf(m1, rm1);
        float a0 = __expf(m0 - mn0), a1 = __expf(m1 - mn1);
        m0 = mn0; m1 = mn1;
        float s0 = 0.f, s1 = 0.f;
#pragma unroll
        for (int jt = 0; jt < 8; jt++) {
            sv[jt][0] = __expf(sv[jt][0] - mn0);
            sv[jt][1] = __expf(sv[jt][1] - mn0);
            sv[jt][2] = __expf(sv[jt][2] - mn1);
            sv[jt][3] = __expf(sv[jt][3] - mn1);
            s0 += sv[jt][0] + sv[jt][1];
            s1 += sv[jt][2] + sv[jt][3];
        }
        s0 += __shfl_xor_sync(0xffffffffu, s0, 1);
        s0 += __shfl_xor_sync(0xffffffffu, s0, 2);
        s1 += __shfl_xor_sync(0xffffffffu, s1, 1);
        s1 += __shfl_xor_sync(0xffffffffu, s1, 2);
        ls0 = ls0 * a0 + s0;
        ls1 = ls1 * a1 + s1;
#pragma unroll
        for (int dt = 0; dt < 8; dt++) {
            oc[dt][0] *= a0; oc[dt][1] *= a0;
            oc[dt][2] *= a1; oc[dt][3] *= a1;
        }

        // ---- O += P V ----
#pragma unroll
        for (int jp = 0; jp < 4; jp++) {
            uint32_t pah[4], pal[4];
#pragma unroll
            for (int half = 0; half < 2; half++) {
                bf16 h0, lo0, h1, lo1, h2, lo2, h3, lo3;
                split_hl(sv[2 * jp + half][0], h0, lo0);
                split_hl(sv[2 * jp + half][1], h1, lo1);
                split_hl(sv[2 * jp + half][2], h2, lo2);
                split_hl(sv[2 * jp + half][3], h3, lo3);
                pah[2 * half + 0] = packb(h0, h1);  pal[2 * half + 0] = packb(lo0, lo1);
                pah[2 * half + 1] = packb(h2, h3);  pal[2 * half + 1] = packb(lo2, lo3);
            }
            int vrow = jp * 16 + ((lane >> 3) & 1) * 8 + (lane & 7);
#pragma unroll
            for (int g = 0; g < 4; g++) {
                int cch = 2 * g + (lane >> 4);
                uint32_t off = SWZ128(vrow, cch);
                uint32_t vh[4], vl[4];
                ldsm4t(vh, sb + VH + off);
                ldsm4t(vl, sb + VL + off);
                mma16816(oc[2 * g],     pah, vh[0], vh[1]);
                mma16816(oc[2 * g + 1], pah, vh[2], vh[3]);
                mma16816(oc[2 * g],     pah, vl[0], vl[1]);
                mma16816(oc[2 * g + 1], pah, vl[2], vl[3]);
                mma16816(oc[2 * g],     pal, vh[0], vh[1]);
                mma16816(oc[2 * g + 1], pal, vh[2], vh[3]);
            }
        }
    }

    // ---- epilogue ----
    float i0 = 1.f / ls0, i1 = 1.f / ls1;
    int r0 = qt * 64 + wid * 16 + (lane >> 2);
#pragma unroll
    for (int dt = 0; dt < 8; dt++) {
        int d = hh * HD_ + dt * 8 + (lane & 3) * 2;
        size_t o0 = ((size_t)b * S_ + r0) * H_ + d;
        size_t o1 = o0 + (size_t)8 * H_;
        bf16 h0, lo0, h1, lo1;
        split_hl(oc[dt][0] * i0, h0, lo0);
        split_hl(oc[dt][1] * i0, h1, lo1);
        *(bf162*)(ohi + o0) = bf162(h0, h1);
        *(bf162*)(olo + o0) = bf162(lo0, lo1);
        split_hl(oc[dt][2] * i1, h0, lo0);
        split_hl(oc[dt][3] * i1, h1, lo1);
        *(bf162*)(ohi + o1) = bf162(h0, h1);
        *(bf162*)(olo + o1) = bf162(lo0, lo1);
    }
}

// ---------------- LayerNorm (residual add + optional split outputs) ----------------
__global__ __launch_bounds__(128) void ln_kernel(
    const float* __restrict__ x, const float* __restrict__ res,
    const float* __restrict__ g, const float* __restrict__ be,
    float* __restrict__ out, bf16* __restrict__ ohi, bf16* __restrict__ olo, int C)
{
    int m = blockIdx.x, t = threadIdx.x;
    int nv = C >> 2;
    float4 v = make_float4(0.f, 0.f, 0.f, 0.f);
    if (t < nv) {
        v = ((const float4*)(x + (size_t)m * C))[t];
        if (res) {
            float4 w = ((const float4*)(res + (size_t)m * C))[t];
            v.x += w.x; v.y += w.y; v.z += w.z; v.w += w.w;
        }
    }
    float sum = v.x + v.y + v.z + v.w;
    float sq  = v.x * v.x + v.y * v.y + v.z * v.z + v.w * v.w;
#pragma unroll
    for (int off = 16; off; off >>= 1) {
        sum += __shfl_xor_sync(0xffffffffu, sum, off);
        sq  += __shfl_xor_sync(0xffffffffu, sq,  off);
    }
    __shared__ float s1[4], s2[4];
    if ((t & 31) == 0) { s1[t >> 5] = sum; s2[t >> 5] = sq; }
    __syncthreads();
    sum = s1[0] + s1[1] + s1[2] + s1[3];
    sq  = s2[0] + s2[1] + s2[2] + s2[3];
    float mean = sum / C;
    float var  = sq / C - mean * mean;
    float inv  = rsqrtf(var + 1e-5f);
    if (t < nv) {
        float4 gv = ((const float4*)g)[t];
        float4 bv = ((const float4*)be)[t];
        float4 o4;
        o4.x = (v.x - mean) * inv * gv.x + bv.x;
        o4.y = (v.y - mean) * inv * gv.y + bv.y;
        o4.z = (v.z - mean) * inv * gv.z + bv.z;
        o4.w = (v.w - mean) * inv * gv.w + bv.w;
        if (out) ((float4*)(out + (size_t)m * C))[t] = o4;
        if (ohi) {
            bf16 h0, l0, h1, l1, h2, l2, h3, l3;
            split_hl(o4.x, h0, l0); split_hl(o4.y, h1, l1);
            split_hl(o4.z, h2, l2); split_hl(o4.w, h3, l3);
            *(bf162*)(ohi + (size_t)m * C + t * 4)     = bf162(h0, h1);
            *(bf162*)(ohi + (size_t)m * C + t * 4 + 2) = bf162(h2, h3);
            *(bf162*)(olo + (size_t)m * C + t * 4)     = bf162(l0, l1);
            *(bf162*)(olo + (size_t)m * C + t * 4 + 2) = bf162(l2, l3);
        }
    }
}

// ---------------- small kernels ----------------
__global__ __launch_bounds__(256) void embed_kernel(
    const int* __restrict__ x, const float* __restrict__ emb,
    float* __restrict__ h, bf16* __restrict__ hh, bf16* __restrict__ hl)
{
    int idx = blockIdx.x * blockDim.x + threadIdx.x;
    if (idx >= M_ * (H_ / 4)) return;
    int m = idx >> 7, c4 = idx & 127;
    int tok = x[m];
    float4 e = ((const float4*)(emb + (size_t)tok * H_))[c4];
    const float sc = 22.62741699796952f;  // sqrt(512)
    e.x *= sc; e.y *= sc; e.z *= sc; e.w *= sc;
    ((float4*)(h + (size_t)m * H_))[c4] = e;
    bf16 h0, l0, h1, l1, h2, l2, h3, l3;
    split_hl(e.x, h0, l0); split_hl(e.y, h1, l1);
    split_hl(e.z, h2, l2); split_hl(e.w, h3, l3);
    *(bf162*)(hh + (size_t)m * H_ + c4 * 4)     = bf162(h0, h1);
    *(bf162*)(hh + (size_t)m * H_ + c4 * 4 + 2) = bf162(h2, h3);
    *(bf162*)(hl + (size_t)m * H_ + c4 * 4)     = bf162(l0, l1);
    *(bf162*)(hl + (size_t)m * H_ + c4 * 4 + 2) = bf162(l2, l3);
}

__global__ __launch_bounds__(256) void maskmul_kernel(
    const float* __restrict__ in, bf16* __restrict__ ohi, bf16* __restrict__ olo,
    const int* __restrict__ lengths)
{
    int idx = blockIdx.x * blockDim.x + threadIdx.x;
    if (idx >= M_ * H_) return;
    int m = idx >> 9;
    int s = m & (S_ - 1), b = m >> 9;
    float v = in[idx] * ((s >= lengths[b]) ? 1.f : 0.f);  // inverted mask
    bf16 h, l;
    split_hl(v, h, l);
    ohi[idx] = h; olo[idx] = l;
}

#define NW1 (L_*F_*H_*3)
#define NW2 (L_*H_*F_*3)
#define ND1 (FD_*H_*3)
#define ND2 (FD_*FD_*3)
__global__ __launch_bounds__(256) void prep_conv_kernel(
    const float* __restrict__ c1w, const float* __restrict__ c2w,
    const float* __restrict__ d1w, const float* __restrict__ d2w)
{
    int idx = blockIdx.x * blockDim.x + threadIdx.x;
    const float* src; bf16 *dh, *dl; int CI; int base;
    if (idx < NW1)                        { src = c1w; dh = g_w1h; dl = g_w1l; CI = H_;  base = idx; }
    else if (idx < NW1 + NW2)             { src = c2w; dh = g_w2h; dl = g_w2l; CI = F_;  base = idx - NW1; }
    else if (idx < NW1 + NW2 + ND1)       { src = d1w; dh = g_d1h; dl = g_d1l; CI = H_;  base = idx - NW1 - NW2; }
    else if (idx < NW1 + NW2 + ND1 + ND2) { src = d2w; dh = g_d2h; dl = g_d2l; CI = FD_; base = idx - NW1 - NW2 - ND1; }
    else return;
    int kk = base % 3;
    int rest = base / 3;
    int ci = rest % CI;
    int co = rest / CI;
    float v = src[base];
    bf16 h, l; split_hl(v, h, l);
    size_t o = (size_t)co * (3 * CI) + kk * CI + ci;
    dh[o] = h; dl[o] = l;
}

#define NQKV (L_*3*H_*H_)
#define NWO  (L_*H_*H_)
#define NPJ  (OUT_*H_)
#define NBQ  (L_*3*H_)
#define NRT  (S_*32)
__global__ __launch_bounds__(256) void prep_lin_kernel(
    const float* __restrict__ Wq, const float* __restrict__ Wk,
    const float* __restrict__ Wv, const float* __restrict__ Wo,
    const float* __restrict__ pj,
    const float* __restrict__ bq, const float* __restrict__ bk,
    const float* __restrict__ bv)
{
    int idx = blockIdx.x * blockDim.x + threadIdx.x;
    if (idx < NQKV) {
        int e = idx % H_;
        int n = (idx / H_) % (3 * H_);
        int l = idx / (3 * H_ * H_);
        const float* W = (n < H_) ? Wq : (n < 2 * H_) ? Wk : Wv;
        int nn = n & (H_ - 1);
        float v = W[(size_t)l * H_ * H_ + (size_t)nn * H_ + e];
        bf16 h, lo; split_hl(v, h, lo);
        g_wqkvh[idx] = h; g_wqkvl[idx] = lo;
        return;
    }
    int i2 = idx - NQKV;
    if (i2 < NWO) {
        float v = Wo[i2];
        bf16 h, lo; split_hl(v, h, lo);
        g_woh[i2] = h; g_wol[i2] = lo;
        return;
    }
    int i3 = i2 - NWO;
    if (i3 < NPJ) {
        float v = pj[i3];
        bf16 h, lo; split_hl(v, h, lo);
        g_pjh[i3] = h; g_pjl[i3] = lo;
        return;
    }
    int i4 = i3 - NPJ;
    if (i4 < NBQ) {
        int n = i4 % (3 * H_);
        int l = i4 / (3 * H_);
        const float* bb = (n < H_) ? bq : (n < 2 * H_) ? bk : bv;
        g_bqkv[i4] = bb[l * H_ + (n & (H_ - 1))];
        return;
    }
    int i5 = i4 - NBQ;
    if (i5 < NRT) {
        int s = i5 >> 5, j = i5 & 31;
        float th = expf(-(float)j * 0.28782313662425574f);
        float sn, cs;
        sincosf((float)s * th, &sn, &cs);
        g_rope[i5] = make_float2(cs, sn);
    }
}

__global__ __launch_bounds__(256) void dp_final_kernel(
    const float* __restrict__ x, const float* __restrict__ w,
    const float* __restrict__ pb, const int* __restrict__ lengths,
    float* __restrict__ out)
{
    int warp = threadIdx.x >> 5, lane = threadIdx.x & 31;
    int m = blockIdx.x * 8 + warp;
    if (m >= M_) return;
    const float* xr = x + (size_t)m * FD_;
    float s = 0.f;
    for (int c = lane; c < FD_; c += 32) s += xr[c] * w[c];
#pragma unroll
    for (int off = 16; off; off >>= 1) s += __shfl_xor_sync(0xffffffffu, s, off);
    if (lane == 0) {
        int b = m >> 9, sp = m & (S_ - 1);
        float mv = (sp >= lengths[b]) ? 1.f : 0.f;
        float val = (s + pb[0]) * mv;
        out[(size_t)b * S_ + sp] = ceilf(expf(val));
    }
}

// ---------------- orchestration ----------------
extern "C" void kernel_launch(void* const* d_in, const int* in_sizes, int n_in,
                              void* d_out, int out_size)
{
    const int*   x      = (const int*)  d_in[0];
    const int*   xlen   = (const int*)  d_in[1];
    const float* emb    = (const float*)d_in[2];
    const float* Wq     = (const float*)d_in[3];
    const float* bq     = (const float*)d_in[4];
    const float* Wk     = (const float*)d_in[5];
    const float* bk     = (const float*)d_in[6];
    const float* Wv     = (const float*)d_in[7];
    const float* bv     = (const float*)d_in[8];
    const float* Wo     = (const float*)d_in[9];
    const float* bo     = (const float*)d_in[10];
    const float* c1w    = (const float*)d_in[11];
    const float* c1b    = (const float*)d_in[12];
    const float* c2w    = (const float*)d_in[13];
    const float* c2b    = (const float*)d_in[14];
    const float* ln1g   = (const float*)d_in[15];
    const float* ln1b   = (const float*)d_in[16];
    const float* ln2g   = (const float*)d_in[17];
    const float* ln2b   = (const float*)d_in[18];
    const float* projw  = (const float*)d_in[19];
    const float* projb  = (const float*)d_in[20];
    const float* dpc1w  = (const float*)d_in[21];
    const float* dpc1b  = (const float*)d_in[22];
    const float* dpln1g = (const float*)d_in[23];
    const float* dpln1b = (const float*)d_in[24];
    const float* dpc2w  = (const float*)d_in[25];
    const float* dpc2b  = (const float*)d_in[26];
    const float* dpln2g = (const float*)d_in[27];
    const float* dpln2b = (const float*)d_in[28];
    const float* dppw   = (const float*)d_in[29];
    const float* dppb   = (const float*)d_in[30];
    float* out = (float*)d_out;

    float *h, *x1, *op, *cv2, *qkv, *bqkv;
    float2* rtab;
    bf16 *hh, *hl, *x1h, *x1l, *ah, *al, *midh, *midl, *mkh, *mkl, *dpxh, *dpxl;
    bf16 *wqh, *wql, *woh, *wol, *w1h, *w1l, *w2h, *w2l, *pjh, *pjl, *d1h, *d1l, *d2h, *d2l;
    cudaGetSymbolAddress((void**)&h,    g_h);
    cudaGetSymbolAddress((void**)&x1,   g_x1);
    cudaGetSymbolAddress((void**)&op,   g_op);
    cudaGetSymbolAddress((void**)&cv2,  g_cv2);
    cudaGetSymbolAddress((void**)&qkv,  g_qkv);
    cudaGetSymbolAddress((void**)&rtab, g_rope);
    cudaGetSymbolAddress((void**)&hh,   g_hh);
    cudaGetSymbolAddress((void**)&hl,   g_hl);
    cudaGetSymbolAddress((void**)&x1h,  g_x1h);
    cudaGetSymbolAddress((void**)&x1l,  g_x1l);
    cudaGetSymbolAddress((void**)&ah,   g_ah);
    cudaGetSymbolAddress((void**)&al,   g_al);
    cudaGetSymbolAddress((void**)&midh, g_midh);
    cudaGetSymbolAddress((void**)&midl, g_midl);
    cudaGetSymbolAddress((void**)&mkh,  g_mkh);
    cudaGetSymbolAddress((void**)&mkl,  g_mkl);
    cudaGetSymbolAddress((void**)&dpxh, g_dpxh);
    cudaGetSymbolAddress((void**)&dpxl, g_dpxl);
    cudaGetSymbolAddress((void**)&wqh,  g_wqkvh);
    cudaGetSymbolAddress((void**)&wql,  g_wqkvl);
    cudaGetSymbolAddress((void**)&woh,  g_woh);
    cudaGetSymbolAddress((void**)&wol,  g_wol);
    cudaGetSymbolAddress((void**)&w1h,  g_w1h);
    cudaGetSymbolAddress((void**)&w1l,  g_w1l);
    cudaGetSymbolAddress((void**)&w2h,  g_w2h);
    cudaGetSymbolAddress((void**)&w2l,  g_w2l);
    cudaGetSymbolAddress((void**)&pjh,  g_pjh);
    cudaGetSymbolAddress((void**)&pjl,  g_pjl);
    cudaGetSymbolAddress((void**)&d1h,  g_d1h);
    cudaGetSymbolAddress((void**)&d1l,  g_d1l);
    cudaGetSymbolAddress((void**)&d2h,  g_d2h);
    cudaGetSymbolAddress((void**)&d2l,  g_d2l);
    cudaGetSymbolAddress((void**)&bqkv, g_bqkv);

    cudaFuncSetAttribute((const void*)attn_kernel,
                         cudaFuncAttributeMaxDynamicSharedMemorySize, 49152);
    cudaFuncSetAttribute((const void*)hgemm_kernel,
                         cudaFuncAttributeMaxDynamicSharedMemorySize, 49152);

    {
        int tot = NW1 + NW2 + ND1 + ND2;
        prep_conv_kernel<<<(tot + 255) / 256, 256>>>(c1w, c2w, dpc1w, dpc2w);
        tot = NQKV + NWO + NPJ + NBQ + NRT;
        prep_lin_kernel<<<(tot + 255) / 256, 256>>>(Wq, Wk, Wv, Wo, projw, bq, bk, bv);
    }
    embed_kernel<<<M_ * (H_ / 4) / 256, 256>>>(x, emb, h, hh, hl);

    const int SM_G = 49152;
    dim3 gQKV(3 * H_ / 128, M_ / 64);   // (12,256)
    dim3 gH(H_ / 128, M_ / 64);         // (4,256)
    dim3 gF(F_ / 128, M_ / 64);         // (16,256)
    dim3 gMu(1, M_ / 64);
    dim3 gDp(FD_ / 128, M_ / 64);       // (2,256)
    dim3 ga(S_ / 64, NH_, B_);

    for (int l = 0; l < L_; l++) {
        size_t wOff = (size_t)l * H_ * H_;
        size_t wqOff = (size_t)l * 3 * H_ * H_;
        hgemm_kernel<<<gQKV, 128, SM_G>>>(hh, hl, wqh + wqOff, wql + wqOff,
                                          bqkv + l * 3 * H_, qkv, nullptr, nullptr,
                                          3 * H_, 9, 1, 0, 0, xlen);
        attn_kernel<<<ga, 128, SM_G>>>(qkv, rtab, ah, al, xlen);
        hgemm_kernel<<<gH, 128, SM_G>>>(ah, al, woh + wOff, wol + wOff,
                                        bo + l * H_, op, nullptr, nullptr,
                                        H_, 9, 1, 0, 0, xlen);
        ln_kernel<<<M_, 128>>>(op, h, ln1g + l * H_, ln1b + l * H_, x1, x1h, x1l, H_);
        hgemm_kernel<<<gF, 128, SM_G>>>(x1h, x1l,
                                        w1h + (size_t)l * F_ * 3 * H_, w1l + (size_t)l * F_ * 3 * H_,
                                        c1b + l * F_, nullptr, midh, midl,
                                        F_, 9, 3, 1, FLAG_RELU, xlen);
        hgemm_kernel<<<gH, 128, SM_G>>>(midh, midl,
                                        w2h + (size_t)l * H_ * 3 * F_, w2l + (size_t)l * H_ * 3 * F_,
                                        c2b + l * H_, cv2, nullptr, nullptr,
                                        H_, 11, 3, 1, 0, xlen);
        ln_kernel<<<M_, 128>>>(cv2, x1, ln2g + l * H_, ln2b + l * H_, h, hh, hl, H_);
    }

    hgemm_kernel<<<gMu, 128, SM_G>>>(hh, hl, pjh, pjl, projb, out, nullptr, nullptr,
                                     OUT_, 9, 1, 0, FLAG_TRANS, xlen);

    maskmul_kernel<<<M_ * H_ / 256, 256>>>(h, mkh, mkl, xlen);
    hgemm_kernel<<<gDp, 128, SM_G>>>(mkh, mkl, d1h, d1l, dpc1b, op, nullptr, nullptr,
                                     FD_, 9, 3, 1, FLAG_RELU | FLAG_MASK, xlen);
    ln_kernel<<<M_, 128>>>(op, nullptr, dpln1g, dpln1b, cv2, dpxh, dpxl, FD_);
    hgemm_kernel<<<gDp, 128, SM_G>>>(dpxh, dpxl, d2h, d2l, dpc2b, op, nullptr, nullptr,
                                     FD_, 8, 3, 1, FLAG_RELU | FLAG_MASK, xlen);
    ln_kernel<<<M_, 128>>>(op, nullptr, dpln2g, dpln2b, x1, nullptr, nullptr, FD_);
    dp_final_kernel<<<M_ / 8, 256>>>(x1, dppw, dppb, xlen,
                                     out + ((size_t)out_size - (size_t)B_ * S_));
}